// round 10
// baseline (speedup 1.0000x reference)
#include <cuda_runtime.h>
#include <cuda_bf16.h>
#include <math.h>
#include <stdint.h>

#define NN 100000
#define NE 400000
#define NG 4000
#define NF 39
#define K1PAD 40
#define DMAX 1024
#define BN_EPS 1e-5f
// W1(40x1024)+W2(1024x512)+W3(512x256)+W4(256x512)+W5(512x1024)+fc2(1024x128)
#define WTOT 1482752

// ---------------- static device scratch ----------------
__device__ float g_dis[NN];
__device__ float g_norm[NE];
__device__ int   g_counts[NN];
__device__ int   g_off[NN + 1];
__device__ int   g_cursor[NN];
__device__ int   g_src[NE];
__device__ float g_w[NE];
__device__ float g_bufA[(size_t)NN * DMAX];
__device__ float g_bufB[(size_t)NN * DMAX];
__device__ float g_bufC[(size_t)NN * DMAX];
__device__ __align__(16) __nv_bfloat16 g_ah[(size_t)NN * DMAX];
__device__ __align__(16) __nv_bfloat16 g_al[(size_t)NN * DMAX];
__device__ __align__(16) __nv_bfloat16 g_wh[WTOT];
__device__ __align__(16) __nv_bfloat16 g_wl[WTOT];
__device__ float g_colsum[DMAX];
__device__ float g_colsq[DMAX];
__device__ float g_scale[DMAX];
__device__ float g_shift[DMAX];
__device__ float g_gw2[DMAX];
__device__ float g_gconst[1];
__device__ int   g_gs[NG];
__device__ int   g_ge[NG];
__device__ float g_pooled[(size_t)NG * DMAX];
__device__ float g_h2[NG * 128];
__device__ float g_h3[NG * 16];

// ---------------- utility ----------------
__global__ void k_filli(int* p, int v, int n) {
    for (int i = blockIdx.x * blockDim.x + threadIdx.x; i < n; i += gridDim.x * blockDim.x)
        p[i] = v;
}
__global__ void k_copyi(const int* __restrict__ a, int* __restrict__ b, int n) {
    for (int i = blockIdx.x * blockDim.x + threadIdx.x; i < n; i += gridDim.x * blockDim.x)
        b[i] = a[i];
}

__device__ __forceinline__ void splitf(float v, __nv_bfloat16& h, __nv_bfloat16& l) {
    h = __float2bfloat16(v);
    l = __float2bfloat16(v - __bfloat162float(h));
}

// ---------------- CSR build ----------------
__global__ void k_histc(const int* __restrict__ col, int* counts) {
    int e = blockIdx.x * blockDim.x + threadIdx.x;
    if (e < NE) atomicAdd(&counts[col[e]], 1);
}
__global__ void k_disk(const int* __restrict__ counts, float* dis) {
    int i = blockIdx.x * blockDim.x + threadIdx.x;
    if (i < NN) dis[i] = rsqrtf((float)counts[i] + 1.0f);
}
__global__ void k_edge_norm(const int* __restrict__ row, const int* __restrict__ col,
                            const float* __restrict__ dis, float* __restrict__ norm) {
    int e = blockIdx.x * blockDim.x + threadIdx.x;
    if (e < NE) norm[e] = dis[row[e]] * dis[col[e]];
}
__global__ void k_scan(const int* __restrict__ counts, int* __restrict__ off) {
    __shared__ int sh[1024];
    __shared__ int carry_s;
    int t = threadIdx.x;
    if (t == 0) { carry_s = 0; off[0] = 0; }
    __syncthreads();
    for (int base = 0; base < NN; base += 1024) {
        int i = base + t;
        int v = (i < NN) ? counts[i] : 0;
        sh[t] = v;
        __syncthreads();
        for (int o = 1; o < 1024; o <<= 1) {
            int add = (t >= o) ? sh[t - o] : 0;
            __syncthreads();
            sh[t] += add;
            __syncthreads();
        }
        int carry = carry_s;
        if (i < NN) off[i + 1] = carry + sh[t];
        __syncthreads();
        if (t == 1023) carry_s = carry + sh[1023];
        __syncthreads();
    }
}
__global__ void k_scatter(const int* __restrict__ row, const int* __restrict__ col,
                          const float* __restrict__ norm, int* cursor,
                          int* __restrict__ csr_src, float* __restrict__ csr_w) {
    int e = blockIdx.x * blockDim.x + threadIdx.x;
    if (e >= NE) return;
    int c = col[e];
    int p = atomicAdd(&cursor[c], 1);
    csr_src[p] = row[e];
    csr_w[p] = norm[e];
}

// ---------------- split passes ----------------
__global__ void k_split_mat(const float* __restrict__ src, __nv_bfloat16* __restrict__ oh,
                            __nv_bfloat16* __restrict__ ol, int k, int kpad, int n) {
    int idx = blockIdx.x * blockDim.x + threadIdx.x;
    if (idx >= kpad * n) return;
    int r = idx / n, c = idx - r * n;
    float v = (r < k) ? src[(size_t)r * n + c] : 0.f;
    __nv_bfloat16 h, l;
    splitf(v, h, l);
    oh[idx] = h;
    ol[idx] = l;
}
__global__ void k_bnsplit(const float4* __restrict__ y, const float* __restrict__ scale,
                          const float* __restrict__ shift,
                          __nv_bfloat16* __restrict__ oh, __nv_bfloat16* __restrict__ ol,
                          int dimv, int total4) {
    int idx = blockIdx.x * blockDim.x + threadIdx.x;
    if (idx >= total4) return;
    int c = (idx % dimv) * 4;
    float4 v = y[idx];
    v.x = v.x * scale[c + 0] + shift[c + 0];
    v.y = v.y * scale[c + 1] + shift[c + 1];
    v.z = v.z * scale[c + 2] + shift[c + 2];
    v.w = v.w * scale[c + 3] + shift[c + 3];
    __nv_bfloat16 h0, l0, h1, l1, h2, l2, h3, l3;
    splitf(v.x, h0, l0); splitf(v.y, h1, l1); splitf(v.z, h2, l2); splitf(v.w, h3, l3);
    uint2 hv, lv;
    hv.x = ((uint32_t)__bfloat16_as_ushort(h1) << 16) | __bfloat16_as_ushort(h0);
    hv.y = ((uint32_t)__bfloat16_as_ushort(h3) << 16) | __bfloat16_as_ushort(h2);
    lv.x = ((uint32_t)__bfloat16_as_ushort(l1) << 16) | __bfloat16_as_ushort(l0);
    lv.y = ((uint32_t)__bfloat16_as_ushort(l3) << 16) | __bfloat16_as_ushort(l2);
    *(uint2*)&oh[(size_t)idx * 4] = hv;
    *(uint2*)&ol[(size_t)idx * 4] = lv;
}

// ---------------- CSR gather propagate (edge loop unrolled x2) ----------------
template <int DIMV, int NPB, int MODE>
__global__ void k_prop4(const float4* __restrict__ in, float4* __restrict__ out,
                        __nv_bfloat16* __restrict__ outh, __nv_bfloat16* __restrict__ outl,
                        const float* __restrict__ dis,
                        const int* __restrict__ off, const int* __restrict__ src,
                        const float* __restrict__ w,
                        const float* __restrict__ bias,
                        const float* __restrict__ insc, const float* __restrict__ insh,
                        float* __restrict__ colsum, float* __restrict__ colsq) {
    const int DIM = DIMV * 4;
    int x = threadIdx.x;
    int yy = threadIdx.y;
    float4 bb = make_float4(0.f, 0.f, 0.f, 0.f);
    float4 sc4 = make_float4(0.f, 0.f, 0.f, 0.f), sh4 = sc4;
    float4 s1 = make_float4(0.f, 0.f, 0.f, 0.f);
    float4 s2 = make_float4(0.f, 0.f, 0.f, 0.f);
    if (MODE == 1) bb = *(const float4*)&bias[x * 4];
    if (MODE == 2) {
        sc4 = *(const float4*)&insc[x * 4];
        sh4 = *(const float4*)&insh[x * 4];
    }
    for (int n = blockIdx.x * NPB + yy; n < NN; n += gridDim.x * NPB) {
        float d = dis[n];
        float sw = d * d;
        float4 v = in[(size_t)n * DIMV + x];
        float4 acc = make_float4(sw * v.x, sw * v.y, sw * v.z, sw * v.w);
        float4 acc2 = make_float4(0.f, 0.f, 0.f, 0.f);
        float wsum = sw, wsum2 = 0.f;
        int e = __ldg(&off[n]);
        int e1 = __ldg(&off[n + 1]);
        for (; e + 1 < e1; e += 2) {
            int sr0 = __ldg(&src[e]);
            int sr1 = __ldg(&src[e + 1]);
            float w0 = __ldg(&w[e]);
            float w1 = __ldg(&w[e + 1]);
            float4 u0 = in[(size_t)sr0 * DIMV + x];
            float4 u1 = in[(size_t)sr1 * DIMV + x];
            wsum += w0; wsum2 += w1;
            acc.x = fmaf(w0, u0.x, acc.x);   acc2.x = fmaf(w1, u1.x, acc2.x);
            acc.y = fmaf(w0, u0.y, acc.y);   acc2.y = fmaf(w1, u1.y, acc2.y);
            acc.z = fmaf(w0, u0.z, acc.z);   acc2.z = fmaf(w1, u1.z, acc2.z);
            acc.w = fmaf(w0, u0.w, acc.w);   acc2.w = fmaf(w1, u1.w, acc2.w);
        }
        if (e < e1) {
            int sr = __ldg(&src[e]);
            float ww = __ldg(&w[e]);
            float4 u = in[(size_t)sr * DIMV + x];
            wsum += ww;
            acc.x = fmaf(ww, u.x, acc.x);
            acc.y = fmaf(ww, u.y, acc.y);
            acc.z = fmaf(ww, u.z, acc.z);
            acc.w = fmaf(ww, u.w, acc.w);
        }
        acc.x += acc2.x; acc.y += acc2.y; acc.z += acc2.z; acc.w += acc2.w;
        wsum += wsum2;
        if (MODE == 1) {
            acc.x = fmaxf(acc.x + bb.x, 0.f);
            acc.y = fmaxf(acc.y + bb.y, 0.f);
            acc.z = fmaxf(acc.z + bb.z, 0.f);
            acc.w = fmaxf(acc.w + bb.w, 0.f);
            out[(size_t)n * DIMV + x] = acc;
            s1.x += acc.x; s1.y += acc.y; s1.z += acc.z; s1.w += acc.w;
            s2.x += acc.x * acc.x; s2.y += acc.y * acc.y;
            s2.z += acc.z * acc.z; s2.w += acc.w * acc.w;
        } else {
            acc.x = sc4.x * acc.x + sh4.x * wsum;
            acc.y = sc4.y * acc.y + sh4.y * wsum;
            acc.z = sc4.z * acc.z + sh4.z * wsum;
            acc.w = sc4.w * acc.w + sh4.w * wsum;
            __nv_bfloat16 h0, l0, h1, l1, h2, l2, h3, l3;
            splitf(acc.x, h0, l0); splitf(acc.y, h1, l1);
            splitf(acc.z, h2, l2); splitf(acc.w, h3, l3);
            uint2 hv, lv;
            hv.x = ((uint32_t)__bfloat16_as_ushort(h1) << 16) | __bfloat16_as_ushort(h0);
            hv.y = ((uint32_t)__bfloat16_as_ushort(h3) << 16) | __bfloat16_as_ushort(h2);
            lv.x = ((uint32_t)__bfloat16_as_ushort(l1) << 16) | __bfloat16_as_ushort(l0);
            lv.y = ((uint32_t)__bfloat16_as_ushort(l3) << 16) | __bfloat16_as_ushort(l2);
            *(uint2*)&outh[(size_t)n * DIM + x * 4] = hv;
            *(uint2*)&outl[(size_t)n * DIM + x * 4] = lv;
        }
    }
    if (MODE == 1) {
        int c = x * 4;
        atomicAdd(&colsum[c + 0], s1.x);
        atomicAdd(&colsum[c + 1], s1.y);
        atomicAdd(&colsum[c + 2], s1.z);
        atomicAdd(&colsum[c + 3], s1.w);
        atomicAdd(&colsq[c + 0], s2.x);
        atomicAdd(&colsq[c + 1], s2.y);
        atomicAdd(&colsq[c + 2], s2.z);
        atomicAdd(&colsq[c + 3], s2.w);
    }
}

__global__ void k_prop39(const float* __restrict__ in,
                         __nv_bfloat16* __restrict__ oh, __nv_bfloat16* __restrict__ ol,
                         const float* __restrict__ dis,
                         const int* __restrict__ off, const int* __restrict__ src,
                         const float* __restrict__ w) {
    int x = threadIdx.x;
    if (x >= K1PAD) return;
    int yy = threadIdx.y;
    __nv_bfloat16 z = __float2bfloat16(0.f);
    for (int n = blockIdx.x * 4 + yy; n < NN; n += gridDim.x * 4) {
        if (x >= NF) {
            oh[(size_t)n * K1PAD + x] = z;
            ol[(size_t)n * K1PAD + x] = z;
            continue;
        }
        float d = dis[n];
        float acc = d * d * in[(size_t)n * NF + x];
        int e1 = __ldg(&off[n + 1]);
        for (int e = __ldg(&off[n]); e < e1; e++)
            acc = fmaf(__ldg(&w[e]), in[(size_t)__ldg(&src[e]) * NF + x], acc);
        __nv_bfloat16 h, l;
        splitf(acc, h, l);
        oh[(size_t)n * K1PAD + x] = h;
        ol[(size_t)n * K1PAD + x] = l;
    }
}

// ================= bf16 3-product tensor-core GEMM (3-stage cp.async) ==========
__device__ __forceinline__ void ldsm4(uint32_t* r, const void* p) {
    uint32_t a = (uint32_t)__cvta_generic_to_shared(p);
    asm volatile("ldmatrix.sync.aligned.m8n8.x4.shared.b16 {%0,%1,%2,%3}, [%4];"
                 : "=r"(r[0]), "=r"(r[1]), "=r"(r[2]), "=r"(r[3]) : "r"(a));
}
__device__ __forceinline__ void ldsm4t(uint32_t* r, const void* p) {
    uint32_t a = (uint32_t)__cvta_generic_to_shared(p);
    asm volatile("ldmatrix.sync.aligned.m8n8.x4.trans.shared.b16 {%0,%1,%2,%3}, [%4];"
                 : "=r"(r[0]), "=r"(r[1]), "=r"(r[2]), "=r"(r[3]) : "r"(a));
}
__device__ __forceinline__ void mma16816(float* d, const uint32_t* a, const uint32_t* b) {
    asm volatile("mma.sync.aligned.m16n8k16.row.col.f32.bf16.bf16.f32 "
                 "{%0,%1,%2,%3}, {%4,%5,%6,%7}, {%8,%9}, {%0,%1,%2,%3};"
                 : "+f"(d[0]), "+f"(d[1]), "+f"(d[2]), "+f"(d[3])
                 : "r"(a[0]), "r"(a[1]), "r"(a[2]), "r"(a[3]),
                   "r"(b[0]), "r"(b[1]));
}
__device__ __forceinline__ void cpa16(uint32_t saddr, const void* g, int sz) {
    asm volatile("cp.async.cg.shared.global [%0], [%1], 16, %2;"
                 :: "r"(saddr), "l"(g), "r"(sz));
}
__device__ __forceinline__ void cpa_commit() {
    asm volatile("cp.async.commit_group;");
}
template <int N>
__device__ __forceinline__ void cpa_wait() {
    asm volatile("cp.async.wait_group %0;" :: "n"(N));
}

#define APAD 40   // A smem row stride: 80B/row (odd 16B multiple)
#define BPAD 136  // B smem row stride: 272B/row
#define ABUF (128 * APAD)
#define BBUF (32 * BPAD)
#define NSTAGE 3
// dynamic smem: Ah[3], Al[3], Bh[3], Bl[3] planes + s_sum/s_sq
#define GEMM_SMEM (NSTAGE * (2 * ABUF + 2 * BBUF) * 2 + 256 * 4)

// mode: 0 = raw, 1 = +bias, 2 = +bias+relu, 3 = +bias+relu+stats
__global__ void __launch_bounds__(256)
k_mma_gemm(const __nv_bfloat16* __restrict__ Ah, const __nv_bfloat16* __restrict__ Al,
           const __nv_bfloat16* __restrict__ Bh, const __nv_bfloat16* __restrict__ Bl,
           const float* __restrict__ bias, float* __restrict__ C,
           int M, int N, int K, int mode,
           float* __restrict__ colsum, float* __restrict__ colsq) {
    extern __shared__ __align__(16) char dsm[];
    __nv_bfloat16* Ahs = (__nv_bfloat16*)dsm;
    __nv_bfloat16* Als = Ahs + NSTAGE * ABUF;
    __nv_bfloat16* Bhs = Als + NSTAGE * ABUF;
    __nv_bfloat16* Bls = Bhs + NSTAGE * BBUF;
    float* s_sum = (float*)(Bls + NSTAGE * BBUF);
    float* s_sq = s_sum + 128;

    const int tid = threadIdx.x;
    const int lane = tid & 31;
    const int warp = tid >> 5;
    const int wm = warp & 3;
    const int wn = warp >> 2;
    const int bm = blockIdx.y * 128;
    const int bn = blockIdx.x * 128;

    float acc[2][8][4];
#pragma unroll
    for (int i = 0; i < 2; i++)
#pragma unroll
        for (int j = 0; j < 8; j++)
#pragma unroll
            for (int c = 0; c < 4; c++) acc[i][j][c] = 0.f;

    const uint32_t sAh = (uint32_t)__cvta_generic_to_shared(Ahs);
    const uint32_t sAl = (uint32_t)__cvta_generic_to_shared(Als);
    const uint32_t sBh = (uint32_t)__cvta_generic_to_shared(Bhs);
    const uint32_t sBl = (uint32_t)__cvta_generic_to_shared(Bls);

    auto prefetch = [&](int k0, int buf) {
        uint32_t aOff = buf * ABUF * 2;
        uint32_t bOff = buf * BBUF * 2;
#pragma unroll
        for (int it = 0; it < 2; it++) {
            int idx = tid + it * 256;
            int r = idx >> 2, q = idx & 3;
            int gm = bm + r, gk = k0 + q * 8;
            int sz = (gm < M && gk < K) ? 16 : 0;
            int gmc = (gm < M) ? gm : 0;
            int gkc = (gk < K) ? gk : 0;
            uint32_t d = (uint32_t)(r * APAD + q * 8) * 2;
            cpa16(sAh + aOff + d, &Ah[(size_t)gmc * K + gkc], sz);
            cpa16(sAl + aOff + d, &Al[(size_t)gmc * K + gkc], sz);
        }
#pragma unroll
        for (int it = 0; it < 2; it++) {
            int idx = tid + it * 256;
            int r = idx >> 4, q = idx & 15;
            int gk = k0 + r, gn = bn + q * 8;
            int sz = (gk < K) ? 16 : 0;
            int gkc = (gk < K) ? gk : 0;
            uint32_t d = (uint32_t)(r * BPAD + q * 8) * 2;
            cpa16(sBh + bOff + d, &Bh[(size_t)gkc * N + gn], sz);
            cpa16(sBl + bOff + d, &Bl[(size_t)gkc * N + gn], sz);
        }
    };

    const int nk = (K + 31) >> 5;
    prefetch(0, 0);
    cpa_commit();
    if (nk > 1) { prefetch(32, 1); }
    cpa_commit();   // always commit (possibly empty group) to keep counts aligned

    for (int kt = 0; kt < nk; kt++) {
        const int cur = kt % NSTAGE;
        cpa_wait<1>();          // group kt landed; kt+1 may be in flight
        __syncthreads();        // all threads see buffer cur; compute(kt-1) done

        if (kt + 2 < nk) { prefetch((kt + 2) << 5, (kt + 2) % NSTAGE); }
        cpa_commit();

        const __nv_bfloat16* cAh = Ahs + cur * ABUF;
        const __nv_bfloat16* cAl = Als + cur * ABUF;
        const __nv_bfloat16* cBh = Bhs + cur * BBUF;
        const __nv_bfloat16* cBl = Bls + cur * BBUF;

        // fragment double-buffer across the two ks halves
        uint32_t ah[2][2][4], al[2][2][4], bh[2][4][4], bl[2][4][4];
        auto loadfrag = [&](int ks, int p) {
#pragma unroll
            for (int i = 0; i < 2; i++) {
                int rowa = wm * 32 + i * 16 + (lane & 15);
                int kc = ks + ((lane >> 4) << 3);
                ldsm4(ah[p][i], &cAh[rowa * APAD + kc]);
                ldsm4(al[p][i], &cAl[rowa * APAD + kc]);
            }
#pragma unroll
            for (int j2 = 0; j2 < 4; j2++) {
                int rowb = ks + (lane & 15);
                int nc = wn * 64 + j2 * 16 + ((lane >> 4) << 3);
                ldsm4t(bh[p][j2], &cBh[rowb * BPAD + nc]);
                ldsm4t(bl[p][j2], &cBl[rowb * BPAD + nc]);
            }
        };
        loadfrag(0, 0);
        loadfrag(16, 1);
#pragma unroll
        for (int p = 0; p < 2; p++) {
#pragma unroll
            for (int i = 0; i < 2; i++)
#pragma unroll
                for (int j = 0; j < 8; j++)
                    mma16816(acc[i][j], ah[p][i], &bh[p][j >> 1][(j & 1) * 2]);
#pragma unroll
            for (int i = 0; i < 2; i++)
#pragma unroll
                for (int j = 0; j < 8; j++)
                    mma16816(acc[i][j], ah[p][i], &bl[p][j >> 1][(j & 1) * 2]);
#pragma unroll
            for (int i = 0; i < 2; i++)
#pragma unroll
                for (int j = 0; j < 8; j++)
                    mma16816(acc[i][j], al[p][i], &bh[p][j >> 1][(j & 1) * 2]);
        }
    }

    // ---- epilogue ----
    __syncthreads();
    if (mode == 3) {
        if (tid < 128) { s_sum[tid] = 0.f; s_sq[tid] = 0.f; }
        __syncthreads();
    }
    float csum[8][2], csq[8][2];
#pragma unroll
    for (int j = 0; j < 8; j++) { csum[j][0] = csum[j][1] = 0.f; csq[j][0] = csq[j][1] = 0.f; }

#pragma unroll
    for (int i = 0; i < 2; i++) {
        int r0 = bm + wm * 32 + i * 16 + (lane >> 2);
#pragma unroll
        for (int j = 0; j < 8; j++) {
            int cc = bn + wn * 64 + j * 8 + (lane & 3) * 2;
            float b0 = 0.f, b1 = 0.f;
            if (mode >= 1) { b0 = bias[cc]; b1 = bias[cc + 1]; }
            float v0 = acc[i][j][0] + b0, v1 = acc[i][j][1] + b1;
            float v2 = acc[i][j][2] + b0, v3 = acc[i][j][3] + b1;
            if (mode >= 2) {
                v0 = fmaxf(v0, 0.f); v1 = fmaxf(v1, 0.f);
                v2 = fmaxf(v2, 0.f); v3 = fmaxf(v3, 0.f);
            }
            if (r0 < M) {
                *(float2*)&C[(size_t)r0 * N + cc] = make_float2(v0, v1);
                if (mode == 3) { csum[j][0] += v0; csum[j][1] += v1; csq[j][0] += v0 * v0; csq[j][1] += v1 * v1; }
            }
            if (r0 + 8 < M) {
                *(float2*)&C[(size_t)(r0 + 8) * N + cc] = make_float2(v2, v3);
                if (mode == 3) { csum[j][0] += v2; csum[j][1] += v3; csq[j][0] += v2 * v2; csq[j][1] += v3 * v3; }
            }
        }
    }
    if (mode == 3) {
#pragma unroll
        for (int j = 0; j < 8; j++) {
            int nl = wn * 64 + j * 8 + (lane & 3) * 2;
            atomicAdd(&s_sum[nl], csum[j][0]);
            atomicAdd(&s_sum[nl + 1], csum[j][1]);
            atomicAdd(&s_sq[nl], csq[j][0]);
            atomicAdd(&s_sq[nl + 1], csq[j][1]);
        }
        __syncthreads();
        if (tid < 128) {
            atomicAdd(&colsum[bn + tid], s_sum[tid]);
            atomicAdd(&colsq[bn + tid], s_sq[tid]);
        }
    }
}

// ---------------- fp32 SGEMM (small head GEMMs) --------------------
__global__ void __launch_bounds__(256, 2)
k_sgemm128(const float* __restrict__ A, const float* __restrict__ B,
           const float* __restrict__ bias, float* __restrict__ C,
           int M, int N, int K, int mode) {
    __shared__ float As[8][132];
    __shared__ float Bs[8][132];
    const int bm = blockIdx.y * 128;
    const int bn = blockIdx.x * 128;
    const int tid = threadIdx.x;
    const int tx = tid & 15, ty = tid >> 4;
    const bool vecK = (K & 3) == 0;
    const bool vecN = (N & 3) == 0;

    float acc[8][8];
#pragma unroll
    for (int i = 0; i < 8; i++)
#pragma unroll
        for (int j = 0; j < 8; j++) acc[i][j] = 0.f;

    const int arow = tid >> 1, ah = tid & 1;
    const int bk = tid >> 5, bn4 = (tid & 31) * 4;

    for (int k0 = 0; k0 < K; k0 += 8) {
        {
            int gm = bm + arow;
            float av[4];
            if (vecK && gm < M && k0 + ah * 4 + 3 < K) {
                float4 v = *(const float4*)&A[(size_t)gm * K + k0 + ah * 4];
                av[0] = v.x; av[1] = v.y; av[2] = v.z; av[3] = v.w;
            } else {
#pragma unroll
                for (int j = 0; j < 4; j++)
                    av[j] = (gm < M && k0 + ah * 4 + j < K)
                                ? A[(size_t)gm * K + k0 + ah * 4 + j] : 0.f;
            }
#pragma unroll
            for (int j = 0; j < 4; j++) As[ah * 4 + j][arow] = av[j];
        }
        {
            float4 v;
            if (vecN && k0 + bk < K && bn + bn4 + 3 < N) {
                v = *(const float4*)&B[(size_t)(k0 + bk) * N + bn + bn4];
            } else {
                float bv[4];
#pragma unroll
                for (int j = 0; j < 4; j++)
                    bv[j] = (k0 + bk < K && bn + bn4 + j < N)
                                ? B[(size_t)(k0 + bk) * N + bn + bn4 + j] : 0.f;
                v = make_float4(bv[0], bv[1], bv[2], bv[3]);
            }
            *(float4*)&Bs[bk][bn4] = v;
        }
        __syncthreads();
#pragma unroll
        for (int k = 0; k < 8; k++) {
            float4 a0 = *(const float4*)&As[k][ty * 4];
            float4 a1 = *(const float4*)&As[k][64 + ty * 4];
            float4 b0 = *(const float4*)&Bs[k][tx * 4];
            float4 b1 = *(const float4*)&Bs[k][64 + tx * 4];
            float a[8] = {a0.x, a0.y, a0.z, a0.w, a1.x, a1.y, a1.z, a1.w};
            float b[8] = {b0.x, b0.y, b0.z, b0.w, b1.x, b1.y, b1.z, b1.w};
#pragma unroll
            for (int i = 0; i < 8; i++)
#pragma unroll
                for (int j = 0; j < 8; j++) acc[i][j] = fmaf(a[i], b[j], acc[i][j]);
        }
        __syncthreads();
    }
#pragma unroll
    for (int i = 0; i < 8; i++) {
        int mr = (i < 4) ? (ty * 4 + i) : (64 + ty * 4 + i - 4);
        int m = bm + mr;
        if (m >= M) continue;
#pragma unroll
        for (int j = 0; j < 8; j++) {
            int nc = (j < 4) ? (tx * 4 + j) : (64 + tx * 4 + j - 4);
            int n = bn + nc;
            if (n >= N) continue;
            float v = acc[i][j];
            if (mode >= 1) v += bias[n];
            if (mode == 2) v = fmaxf(v, 0.f);
            C[(size_t)m * N + n] = v;
        }
    }
}

// ---------------- BN finalize (self-zeroing stats) ----------------
__global__ void k_mkscale(float* __restrict__ colsum, float* __restrict__ colsq,
                          const float* __restrict__ g, const float* __restrict__ be,
                          float* __restrict__ scale, float* __restrict__ shift,
                          float invn, int ncols) {
    int c = blockIdx.x * blockDim.x + threadIdx.x;
    if (c >= ncols) return;
    float mean = colsum[c] * invn;
    float var = colsq[c] * invn - mean * mean;
    float sc = g[c] * rsqrtf(var + BN_EPS);
    scale[c] = sc;
    shift[c] = be[c] - mean * sc;
    colsum[c] = 0.f;
    colsq[c] = 0.f;
}

// ---------------- fused pooling ----------------
__global__ void k_gateprep(const float* __restrict__ scale, const float* __restrict__ shift,
                           const float* __restrict__ gw, const float* __restrict__ gb,
                           float* __restrict__ gw2, float* __restrict__ gconst) {
    __shared__ float red[256];
    int tid = threadIdx.x;
    float part = 0.f;
    for (int c = tid; c < 1024; c += 256) {
        gw2[c] = scale[c] * gw[c];
        part += shift[c] * gw[c];
    }
    red[tid] = part;
    __syncthreads();
    for (int o = 128; o > 0; o >>= 1) {
        if (tid < o) red[tid] += red[tid + o];
        __syncthreads();
    }
    if (tid == 0) gconst[0] = red[0] + gb[0];
}
__global__ void k_bounds(const int* __restrict__ batch, int* gs, int* ge) {
    int i = blockIdx.x * blockDim.x + threadIdx.x;
    if (i >= NN) return;
    int b = batch[i];
    atomicMin(&gs[b], i);
    atomicMax(&ge[b], i + 1);
}

#define SGMAX 1024
__global__ void k_pool_gated(const float* __restrict__ x, const float* __restrict__ gw2,
                             const float* __restrict__ gconstp,
                             const float* __restrict__ scale, const float* __restrict__ shift,
                             const int* __restrict__ gs, const int* __restrict__ ge,
                             float* __restrict__ pooled) {
    int g = blockIdx.x;
    int s = gs[g], e = ge[g];
    int tid = threadIdx.x, lane = tid & 31, warp = tid >> 5;
    __shared__ float sgate[SGMAX];
    __shared__ float red[256];
    float gconst = gconstp[0];

    for (int i = s + warp; i < e; i += 8) {
        const float4* xr = (const float4*)(x + (size_t)i * 1024);
        const float4* w4 = (const float4*)gw2;
        float acc = 0.f;
#pragma unroll
        for (int k = 0; k < 8; k++) {
            float4 a = xr[lane + k * 32];
            float4 b = w4[lane + k * 32];
            acc += a.x * b.x + a.y * b.y + a.z * b.z + a.w * b.w;
        }
#pragma unroll
        for (int o = 16; o > 0; o >>= 1) acc += __shfl_down_sync(0xffffffffu, acc, o);
        if (lane == 0 && (i - s) < SGMAX) sgate[i - s] = acc + gconst;
    }
    __syncthreads();

    auto getg = [&](int i) -> float {
        if (i - s < SGMAX) return sgate[i - s];
        float acc = 0.f;
        const float* xr = x + (size_t)i * 1024;
        for (int c = 0; c < 1024; c++) acc += xr[c] * gw2[c];
        return acc + gconst;
    };

    float m = -INFINITY;
    for (int i = s + tid; i < e; i += 256) m = fmaxf(m, getg(i));
    red[tid] = m;
    __syncthreads();
    for (int o = 128; o > 0; o >>= 1) {
        if (tid < o) red[tid] = fmaxf(red[tid], red[tid + o]);
        __syncthreads();
    }
    float gm = red[0];
    __syncthreads();
    float ss = 0.f;
    for (int i = s + tid; i < e; i += 256) ss += expf(getg(i) - gm);
    red[tid] = ss;
    __syncthreads();
    for (int o = 128; o > 0; o >>= 1) {
        if (tid < o) red[tid] += red[tid + o];
        __syncthreads();
    }
    float inv = (e > s) ? 1.0f / red[0] : 0.f;

    int d = tid * 4;
    float4 acc = make_float4(0.f, 0.f, 0.f, 0.f);
    float ws = 0.f;
    for (int i = s; i < e; i++) {
        float w = expf(getg(i) - gm) * inv;
        ws += w;
        float4 v = *(const float4*)&x[(size_t)i * 1024 + d];
        acc.x += w * v.x; acc.y += w * v.y; acc.z += w * v.z; acc.w += w * v.w;
    }
    float4 o;
    o.x = scale[d + 0] * acc.x + shift[d + 0] * ws;
    o.y = scale[d + 1] * acc.y + shift[d + 1] * ws;
    o.z = scale[d + 2] * acc.z + shift[d + 2] * ws;
    o.w = scale[d + 3] * acc.w + shift[d + 3] * ws;
    *(float4*)&pooled[(size_t)g * 1024 + d] = o;
}

// ---------------- host orchestration ----------------
static inline int cdiv(long a, long b) { return (int)((a + b - 1) / b); }

static void gemm_tc(const __nv_bfloat16* Ah, const __nv_bfloat16* Al,
                    const __nv_bfloat16* Bh, const __nv_bfloat16* Bl,
                    const float* bias, float* C,
                    int M, int N, int K, int mode, float* colsum, float* colsq) {
    dim3 grid(N / 128, cdiv(M, 128));
    k_mma_gemm<<<grid, 256, GEMM_SMEM>>>(Ah, Al, Bh, Bl, bias, C, M, N, K, mode, colsum, colsq);
}
static void gemm32(const float* A, const float* B, const float* bias, float* C,
                   int M, int N, int K, int mode) {
    dim3 grid(cdiv(N, 128), cdiv(M, 128));
    k_sgemm128<<<grid, 256>>>(A, B, bias, C, M, N, K, mode);
}

extern "C" void kernel_launch(void* const* d_in, const int* in_sizes, int n_in,
                              void* d_out, int out_size) {
    (void)in_sizes; (void)n_in; (void)out_size;
    const float* x_in  = (const float*)d_in[0];
    const int*   ei    = (const int*)d_in[1];
    const int*   batch = (const int*)d_in[2];
    const float *W[5], *bb[5], *gg[5], *be[5];
    for (int l = 0; l < 5; l++) {
        W[l]  = (const float*)d_in[3 + 4 * l];
        bb[l] = (const float*)d_in[4 + 4 * l];
        gg[l] = (const float*)d_in[5 + 4 * l];
        be[l] = (const float*)d_in[6 + 4 * l];
    }
    const float* gate_W = (const float*)d_in[23];
    const float* gate_b = (const float*)d_in[24];
    const float* fc2_W  = (const float*)d_in[25];
    const float* fc2_b  = (const float*)d_in[26];
    const float* fc3_W  = (const float*)d_in[27];
    const float* fc3_b  = (const float*)d_in[28];
    const float* fc4_W  = (const float*)d_in[29];
    const float* fc4_b  = (const float*)d_in[30];
    float* out = (float*)d_out;

    float *dis, *norm, *bufA, *bufB, *bufC, *colsum, *colsq, *scale, *shift;
    float *pooled, *h2, *h3, *csr_w, *gw2, *gconst;
    __nv_bfloat16 *ah, *al, *wh, *wl;
    int *gs, *ge, *counts, *off, *cursor, *csr_src;
    cudaGetSymbolAddress((void**)&dis,     g_dis);
    cudaGetSymbolAddress((void**)&norm,    g_norm);
    cudaGetSymbolAddress((void**)&counts,  g_counts);
    cudaGetSymbolAddress((void**)&off,     g_off);
    cudaGetSymbolAddress((void**)&cursor,  g_cursor);
    cudaGetSymbolAddress((void**)&csr_src, g_src);
    cudaGetSymbolAddress((void**)&csr_w,   g_w);
    cudaGetSymbolAddress((void**)&bufA,    g_bufA);
    cudaGetSymbolAddress((void**)&bufB,    g_bufB);
    cudaGetSymbolAddress((void**)&bufC,    g_bufC);
    cudaGetSymbolAddress((void**)&ah,      g_ah);
    cudaGetSymbolAddress((void**)&al,      g_al);
    cudaGetSymbolAddress((void**)&wh,      g_wh);
    cudaGetSymbolAddress((void**)&wl,      g_wl);
    cudaGetSymbolAddress((void**)&colsum,  g_colsum);
    cudaGetSymbolAddress((void**)&colsq,   g_colsq);
    cudaGetSymbolAddress((void**)&scale,   g_scale);
    cudaGetSymbolAddress((void**)&shift,   g_shift);
    cudaGetSymbolAddress((void**)&gw2,     g_gw2);
    cudaGetSymbolAddress((void**)&gconst,  g_gconst);
    cudaGetSymbolAddress((void**)&gs,      g_gs);
    cudaGetSymbolAddress((void**)&ge,      g_ge);
    cudaGetSymbolAddress((void**)&pooled,  g_pooled);
    cudaGetSymbolAddress((void**)&h2,      g_h2);
    cudaGetSymbolAddress((void**)&h3,      g_h3);

    cudaFuncSetAttribute(k_mma_gemm, cudaFuncAttributeMaxDynamicSharedMemorySize, GEMM_SMEM);

    const int* row = ei;
    const int* col = ei + NE;

    const size_t wo1 = 0;
    const size_t wo2 = wo1 + (size_t)K1PAD * 1024;
    const size_t wo3 = wo2 + (size_t)1024 * 512;
    const size_t wo4 = wo3 + (size_t)512 * 256;
    const size_t wo5 = wo4 + (size_t)256 * 512;
    const size_t wo6 = wo5 + (size_t)512 * 1024;

    // ---- GCN norm + CSR build ----
    k_filli<<<256, 256>>>(counts, 0, NN);
    k_histc<<<cdiv(NE, 256), 256>>>(col, counts);
    k_disk<<<cdiv(NN, 256), 256>>>(counts, dis);
    k_edge_norm<<<cdiv(NE, 256), 256>>>(row, col, dis, norm);
    k_scan<<<1, 1024>>>(counts, off);
    k_copyi<<<cdiv(NN, 256), 256>>>(off, cursor, NN);
    k_scatter<<<cdiv(NE, 256), 256>>>(row, col, norm, cursor, csr_src, csr_w);

    // ---- weight pre-split ----
    k_split_mat<<<cdiv((long)K1PAD * 1024, 256), 256>>>(W[0], wh + wo1, wl + wo1, NF, K1PAD, 1024);
    k_split_mat<<<cdiv((long)1024 * 512, 256), 256>>>(W[1], wh + wo2, wl + wo2, 1024, 1024, 512);
    k_split_mat<<<cdiv((long)512 * 256, 256), 256>>>(W[2], wh + wo3, wl + wo3, 512, 512, 256);
    k_split_mat<<<cdiv((long)256 * 512, 256), 256>>>(W[3], wh + wo4, wl + wo4, 256, 256, 512);
    k_split_mat<<<cdiv((long)512 * 1024, 256), 256>>>(W[4], wh + wo5, wl + wo5, 512, 512, 1024);
    k_split_mat<<<cdiv((long)1024 * 128, 256), 256>>>(fc2_W, wh + wo6, wl + wo6, 1024, 1024, 128);

    const float invn = 1.0f / NN;

    // ---- Layer 1 ----
    k_prop39<<<2048, dim3(64, 4)>>>(x_in, ah, al, dis, off, csr_src, csr_w);
    gemm_tc(ah, al, wh + wo1, wl + wo1, bb[0], bufB, NN, 1024, K1PAD, 3, colsum, colsq);
    k_mkscale<<<4, 256>>>(colsum, colsq, gg[0], be[0], scale, shift, invn, 1024);
    k_bnsplit<<<cdiv((long)NN * 256, 256), 256>>>((const float4*)bufB, scale, shift, ah, al, 256, NN * 256);

    // ---- Layer 2 ----
    gemm_tc(ah, al, wh + wo2, wl + wo2, nullptr, bufA, NN, 512, 1024, 0, nullptr, nullptr);
    k_prop4<128, 2, 1><<<2048, dim3(128, 2)>>>((const float4*)bufA, (float4*)bufC, nullptr, nullptr,
                                               dis, off, csr_src, csr_w, bb[1], nullptr, nullptr,
                                               colsum, colsq);
    k_mkscale<<<2, 256>>>(colsum, colsq, gg[1], be[1], scale, shift, invn, 512);
    k_bnsplit<<<cdiv((long)NN * 128, 256), 256>>>((const float4*)bufC, scale, shift, ah, al, 128, NN * 128);

    // ---- Layer 3 ----
    gemm_tc(ah, al, wh + wo3, wl + wo3, nullptr, bufA, NN, 256, 512, 0, nullptr, nullptr);
    k_prop4<64, 4, 1><<<2048, dim3(64, 4)>>>((const float4*)bufA, (float4*)bufB, nullptr, nullptr,
                                             dis, off, csr_src, csr_w, bb[2], nullptr, nullptr,
                                             colsum, colsq);
    k_mkscale<<<1, 256>>>(colsum, colsq, gg[2], be[2], scale, shift, invn, 256);

    // ---- Layer 4 ----
    k_prop4<64, 4, 2><<<2048, dim3(64, 4)>>>((const float4*)bufB, nullptr, ah, al,
                                             dis, off, csr_src, csr_w, nullptr, scale, shift,
                                             nullptr, nullptr);
    gemm_tc(ah, al, wh + wo4, wl + wo4, bb[3], bufC, NN, 512, 256, 3, colsum, colsq);
    k_mkscale<<<2, 256>>>(colsum, colsq, gg[3], be[3], scale, shift, invn, 512);

    // ---- Layer 5 ----
    k_prop4<128, 2, 2><<<2048, dim3(128, 2)>>>((const float4*)bufC, nullptr, ah, al,
                                               dis, off, csr_src, csr_w, nullptr, scale, shift,
                                               nullptr, nullptr);
    gemm_tc(ah, al, wh + wo5, wl + wo5, bb[4], bufB, NN, 1024, 512, 3, colsum, colsq);
    k_mkscale<<<4, 256>>>(colsum, colsq, gg[4], be[4], scale, shift, invn, 1024);

    // ---- attentional pooling (BN5 folded in) ----
    k_gateprep<<<1, 256>>>(scale, shift, gate_W, gate_b, gw2, gconst);
    k_filli<<<32, 256>>>(gs, NN, NG);
    k_filli<<<32, 256>>>(ge, 0, NG);
    k_bounds<<<cdiv(NN, 256), 256>>>(batch, gs, ge);
    k_pool_gated<<<NG, 256>>>(bufB, gw2, gconst, scale, shift, gs, ge, pooled);

    // ---- MLP head ----
    k_split_mat<<<cdiv((long)NG * 1024, 256), 256>>>(pooled, ah, al, NG, NG, 1024);
    gemm_tc(ah, al, wh + wo6, wl + wo6, fc2_b, h2, NG, 128, 1024, 2, nullptr, nullptr);
    gemm32(h2, fc3_W, fc3_b, h3, NG, 16, 128, 2);
    gemm32(h3, fc4_W, fc4_b, out, NG, 1, 16, 1);
}

// round 11
// speedup vs baseline: 1.2698x; 1.2698x over previous
#include <cuda_runtime.h>
#include <cuda_bf16.h>
#include <math.h>
#include <stdint.h>

#define NN 100000
#define NE 400000
#define NG 4000
#define NF 39
#define K1PAD 40
#define DMAX 1024
#define BN_EPS 1e-5f
// W1(40x1024)+W2(1024x512)+W3(512x256)+W4(256x512)+W5(512x1024)+fc2(1024x128)
#define WTOT 1482752

// ---------------- static device scratch ----------------
__device__ float g_dis[NN];
__device__ float g_norm[NE];
__device__ int   g_counts[NN];
__device__ int   g_off[NN + 1];
__device__ int   g_cursor[NN];
__device__ int   g_src[NE];
__device__ float g_w[NE];
__device__ float g_bufA[(size_t)NN * DMAX];
__device__ float g_bufB[(size_t)NN * DMAX];
__device__ float g_bufC[(size_t)NN * DMAX];
__device__ __align__(16) __nv_bfloat16 g_ah[(size_t)NN * DMAX];
__device__ __align__(16) __nv_bfloat16 g_al[(size_t)NN * DMAX];
__device__ __align__(16) __nv_bfloat16 g_wh[WTOT];
__device__ __align__(16) __nv_bfloat16 g_wl[WTOT];
__device__ float g_colsum[DMAX];
__device__ float g_colsq[DMAX];
__device__ float g_scale[DMAX];
__device__ float g_shift[DMAX];
__device__ float g_gw2[DMAX];
__device__ float g_gconst[1];
__device__ int   g_gs[NG];
__device__ int   g_ge[NG];
__device__ float g_pooled[(size_t)NG * DMAX];
__device__ float g_h2[NG * 128];
__device__ float g_h3[NG * 16];

// ---------------- utility ----------------
__global__ void k_filli(int* p, int v, int n) {
    for (int i = blockIdx.x * blockDim.x + threadIdx.x; i < n; i += gridDim.x * blockDim.x)
        p[i] = v;
}
__global__ void k_copyi(const int* __restrict__ a, int* __restrict__ b, int n) {
    for (int i = blockIdx.x * blockDim.x + threadIdx.x; i < n; i += gridDim.x * blockDim.x)
        b[i] = a[i];
}

__device__ __forceinline__ void splitf(float v, __nv_bfloat16& h, __nv_bfloat16& l) {
    h = __float2bfloat16(v);
    l = __float2bfloat16(v - __bfloat162float(h));
}

// ---------------- CSR build ----------------
__global__ void k_histc(const int* __restrict__ col, int* counts) {
    int e = blockIdx.x * blockDim.x + threadIdx.x;
    if (e < NE) atomicAdd(&counts[col[e]], 1);
}
__global__ void k_disk(const int* __restrict__ counts, float* dis) {
    int i = blockIdx.x * blockDim.x + threadIdx.x;
    if (i < NN) dis[i] = rsqrtf((float)counts[i] + 1.0f);
}
__global__ void k_edge_norm(const int* __restrict__ row, const int* __restrict__ col,
                            const float* __restrict__ dis, float* __restrict__ norm) {
    int e = blockIdx.x * blockDim.x + threadIdx.x;
    if (e < NE) norm[e] = dis[row[e]] * dis[col[e]];
}
__global__ void k_scan(const int* __restrict__ counts, int* __restrict__ off) {
    __shared__ int sh[1024];
    __shared__ int carry_s;
    int t = threadIdx.x;
    if (t == 0) { carry_s = 0; off[0] = 0; }
    __syncthreads();
    for (int base = 0; base < NN; base += 1024) {
        int i = base + t;
        int v = (i < NN) ? counts[i] : 0;
        sh[t] = v;
        __syncthreads();
        for (int o = 1; o < 1024; o <<= 1) {
            int add = (t >= o) ? sh[t - o] : 0;
            __syncthreads();
            sh[t] += add;
            __syncthreads();
        }
        int carry = carry_s;
        if (i < NN) off[i + 1] = carry + sh[t];
        __syncthreads();
        if (t == 1023) carry_s = carry + sh[1023];
        __syncthreads();
    }
}
__global__ void k_scatter(const int* __restrict__ row, const int* __restrict__ col,
                          const float* __restrict__ norm, int* cursor,
                          int* __restrict__ csr_src, float* __restrict__ csr_w) {
    int e = blockIdx.x * blockDim.x + threadIdx.x;
    if (e >= NE) return;
    int c = col[e];
    int p = atomicAdd(&cursor[c], 1);
    csr_src[p] = row[e];
    csr_w[p] = norm[e];
}

// ---------------- split passes ----------------
__global__ void k_split_mat(const float* __restrict__ src, __nv_bfloat16* __restrict__ oh,
                            __nv_bfloat16* __restrict__ ol, int k, int kpad, int n) {
    int idx = blockIdx.x * blockDim.x + threadIdx.x;
    if (idx >= kpad * n) return;
    int r = idx / n, c = idx - r * n;
    float v = (r < k) ? src[(size_t)r * n + c] : 0.f;
    __nv_bfloat16 h, l;
    splitf(v, h, l);
    oh[idx] = h;
    ol[idx] = l;
}
__global__ void k_bnsplit(const float4* __restrict__ y, const float* __restrict__ scale,
                          const float* __restrict__ shift,
                          __nv_bfloat16* __restrict__ oh, __nv_bfloat16* __restrict__ ol,
                          int dimv, int total4) {
    int idx = blockIdx.x * blockDim.x + threadIdx.x;
    if (idx >= total4) return;
    int c = (idx % dimv) * 4;
    float4 v = y[idx];
    v.x = v.x * scale[c + 0] + shift[c + 0];
    v.y = v.y * scale[c + 1] + shift[c + 1];
    v.z = v.z * scale[c + 2] + shift[c + 2];
    v.w = v.w * scale[c + 3] + shift[c + 3];
    __nv_bfloat16 h0, l0, h1, l1, h2, l2, h3, l3;
    splitf(v.x, h0, l0); splitf(v.y, h1, l1); splitf(v.z, h2, l2); splitf(v.w, h3, l3);
    uint2 hv, lv;
    hv.x = ((uint32_t)__bfloat16_as_ushort(h1) << 16) | __bfloat16_as_ushort(h0);
    hv.y = ((uint32_t)__bfloat16_as_ushort(h3) << 16) | __bfloat16_as_ushort(h2);
    lv.x = ((uint32_t)__bfloat16_as_ushort(l1) << 16) | __bfloat16_as_ushort(l0);
    lv.y = ((uint32_t)__bfloat16_as_ushort(l3) << 16) | __bfloat16_as_ushort(l2);
    *(uint2*)&oh[(size_t)idx * 4] = hv;
    *(uint2*)&ol[(size_t)idx * 4] = lv;
}

// ---------------- CSR gather propagate (edge loop unrolled x2) ----------------
template <int DIMV, int NPB, int MODE>
__global__ void k_prop4(const float4* __restrict__ in, float4* __restrict__ out,
                        __nv_bfloat16* __restrict__ outh, __nv_bfloat16* __restrict__ outl,
                        const float* __restrict__ dis,
                        const int* __restrict__ off, const int* __restrict__ src,
                        const float* __restrict__ w,
                        const float* __restrict__ bias,
                        const float* __restrict__ insc, const float* __restrict__ insh,
                        float* __restrict__ colsum, float* __restrict__ colsq) {
    const int DIM = DIMV * 4;
    int x = threadIdx.x;
    int yy = threadIdx.y;
    float4 bb = make_float4(0.f, 0.f, 0.f, 0.f);
    float4 sc4 = make_float4(0.f, 0.f, 0.f, 0.f), sh4 = sc4;
    float4 s1 = make_float4(0.f, 0.f, 0.f, 0.f);
    float4 s2 = make_float4(0.f, 0.f, 0.f, 0.f);
    if (MODE == 1) bb = *(const float4*)&bias[x * 4];
    if (MODE == 2) {
        sc4 = *(const float4*)&insc[x * 4];
        sh4 = *(const float4*)&insh[x * 4];
    }
    for (int n = blockIdx.x * NPB + yy; n < NN; n += gridDim.x * NPB) {
        float d = dis[n];
        float sw = d * d;
        float4 v = in[(size_t)n * DIMV + x];
        float4 acc = make_float4(sw * v.x, sw * v.y, sw * v.z, sw * v.w);
        float4 acc2 = make_float4(0.f, 0.f, 0.f, 0.f);
        float wsum = sw, wsum2 = 0.f;
        int e = __ldg(&off[n]);
        int e1 = __ldg(&off[n + 1]);
        for (; e + 1 < e1; e += 2) {
            int sr0 = __ldg(&src[e]);
            int sr1 = __ldg(&src[e + 1]);
            float w0 = __ldg(&w[e]);
            float w1 = __ldg(&w[e + 1]);
            float4 u0 = in[(size_t)sr0 * DIMV + x];
            float4 u1 = in[(size_t)sr1 * DIMV + x];
            wsum += w0; wsum2 += w1;
            acc.x = fmaf(w0, u0.x, acc.x);   acc2.x = fmaf(w1, u1.x, acc2.x);
            acc.y = fmaf(w0, u0.y, acc.y);   acc2.y = fmaf(w1, u1.y, acc2.y);
            acc.z = fmaf(w0, u0.z, acc.z);   acc2.z = fmaf(w1, u1.z, acc2.z);
            acc.w = fmaf(w0, u0.w, acc.w);   acc2.w = fmaf(w1, u1.w, acc2.w);
        }
        if (e < e1) {
            int sr = __ldg(&src[e]);
            float ww = __ldg(&w[e]);
            float4 u = in[(size_t)sr * DIMV + x];
            wsum += ww;
            acc.x = fmaf(ww, u.x, acc.x);
            acc.y = fmaf(ww, u.y, acc.y);
            acc.z = fmaf(ww, u.z, acc.z);
            acc.w = fmaf(ww, u.w, acc.w);
        }
        acc.x += acc2.x; acc.y += acc2.y; acc.z += acc2.z; acc.w += acc2.w;
        wsum += wsum2;
        if (MODE == 1) {
            acc.x = fmaxf(acc.x + bb.x, 0.f);
            acc.y = fmaxf(acc.y + bb.y, 0.f);
            acc.z = fmaxf(acc.z + bb.z, 0.f);
            acc.w = fmaxf(acc.w + bb.w, 0.f);
            out[(size_t)n * DIMV + x] = acc;
            s1.x += acc.x; s1.y += acc.y; s1.z += acc.z; s1.w += acc.w;
            s2.x += acc.x * acc.x; s2.y += acc.y * acc.y;
            s2.z += acc.z * acc.z; s2.w += acc.w * acc.w;
        } else {
            acc.x = sc4.x * acc.x + sh4.x * wsum;
            acc.y = sc4.y * acc.y + sh4.y * wsum;
            acc.z = sc4.z * acc.z + sh4.z * wsum;
            acc.w = sc4.w * acc.w + sh4.w * wsum;
            __nv_bfloat16 h0, l0, h1, l1, h2, l2, h3, l3;
            splitf(acc.x, h0, l0); splitf(acc.y, h1, l1);
            splitf(acc.z, h2, l2); splitf(acc.w, h3, l3);
            uint2 hv, lv;
            hv.x = ((uint32_t)__bfloat16_as_ushort(h1) << 16) | __bfloat16_as_ushort(h0);
            hv.y = ((uint32_t)__bfloat16_as_ushort(h3) << 16) | __bfloat16_as_ushort(h2);
            lv.x = ((uint32_t)__bfloat16_as_ushort(l1) << 16) | __bfloat16_as_ushort(l0);
            lv.y = ((uint32_t)__bfloat16_as_ushort(l3) << 16) | __bfloat16_as_ushort(l2);
            *(uint2*)&outh[(size_t)n * DIM + x * 4] = hv;
            *(uint2*)&outl[(size_t)n * DIM + x * 4] = lv;
        }
    }
    if (MODE == 1) {
        int c = x * 4;
        atomicAdd(&colsum[c + 0], s1.x);
        atomicAdd(&colsum[c + 1], s1.y);
        atomicAdd(&colsum[c + 2], s1.z);
        atomicAdd(&colsum[c + 3], s1.w);
        atomicAdd(&colsq[c + 0], s2.x);
        atomicAdd(&colsq[c + 1], s2.y);
        atomicAdd(&colsq[c + 2], s2.z);
        atomicAdd(&colsq[c + 3], s2.w);
    }
}

__global__ void k_prop39(const float* __restrict__ in,
                         __nv_bfloat16* __restrict__ oh, __nv_bfloat16* __restrict__ ol,
                         const float* __restrict__ dis,
                         const int* __restrict__ off, const int* __restrict__ src,
                         const float* __restrict__ w) {
    int x = threadIdx.x;
    if (x >= K1PAD) return;
    int yy = threadIdx.y;
    __nv_bfloat16 z = __float2bfloat16(0.f);
    for (int n = blockIdx.x * 4 + yy; n < NN; n += gridDim.x * 4) {
        if (x >= NF) {
            oh[(size_t)n * K1PAD + x] = z;
            ol[(size_t)n * K1PAD + x] = z;
            continue;
        }
        float d = dis[n];
        float acc = d * d * in[(size_t)n * NF + x];
        int e1 = __ldg(&off[n + 1]);
        for (int e = __ldg(&off[n]); e < e1; e++)
            acc = fmaf(__ldg(&w[e]), in[(size_t)__ldg(&src[e]) * NF + x], acc);
        __nv_bfloat16 h, l;
        splitf(acc, h, l);
        oh[(size_t)n * K1PAD + x] = h;
        ol[(size_t)n * K1PAD + x] = l;
    }
}

// ================= bf16 3-product tensor-core GEMM (2-stage cp.async, R9) ======
__device__ __forceinline__ void ldsm4(uint32_t* r, const void* p) {
    uint32_t a = (uint32_t)__cvta_generic_to_shared(p);
    asm volatile("ldmatrix.sync.aligned.m8n8.x4.shared.b16 {%0,%1,%2,%3}, [%4];"
                 : "=r"(r[0]), "=r"(r[1]), "=r"(r[2]), "=r"(r[3]) : "r"(a));
}
__device__ __forceinline__ void ldsm4t(uint32_t* r, const void* p) {
    uint32_t a = (uint32_t)__cvta_generic_to_shared(p);
    asm volatile("ldmatrix.sync.aligned.m8n8.x4.trans.shared.b16 {%0,%1,%2,%3}, [%4];"
                 : "=r"(r[0]), "=r"(r[1]), "=r"(r[2]), "=r"(r[3]) : "r"(a));
}
__device__ __forceinline__ void mma16816(float* d, const uint32_t* a, const uint32_t* b) {
    asm volatile("mma.sync.aligned.m16n8k16.row.col.f32.bf16.bf16.f32 "
                 "{%0,%1,%2,%3}, {%4,%5,%6,%7}, {%8,%9}, {%0,%1,%2,%3};"
                 : "+f"(d[0]), "+f"(d[1]), "+f"(d[2]), "+f"(d[3])
                 : "r"(a[0]), "r"(a[1]), "r"(a[2]), "r"(a[3]),
                   "r"(b[0]), "r"(b[1]));
}
__device__ __forceinline__ void cpa16(uint32_t saddr, const void* g, int sz) {
    asm volatile("cp.async.cg.shared.global [%0], [%1], 16, %2;"
                 :: "r"(saddr), "l"(g), "r"(sz));
}
__device__ __forceinline__ void cpa_commit() {
    asm volatile("cp.async.commit_group;");
}
template <int N>
__device__ __forceinline__ void cpa_wait() {
    asm volatile("cp.async.wait_group %0;" :: "n"(N));
}

#define APAD 40   // A smem row stride: 80B/row (odd 16B multiple)
#define BPAD 136  // B smem row stride: 272B/row
#define ABUF (128 * APAD)
#define BBUF (32 * BPAD)
// dynamic smem: Ah[2], Al[2], Bh[2], Bl[2], s_sum[128], s_sq[128]
#define GEMM_SMEM (2 * (2 * ABUF + 2 * BBUF) * 2 + 256 * 4)

// mode: 0 = raw, 1 = +bias, 2 = +bias+relu, 3 = +bias+relu+stats
__global__ void __launch_bounds__(256)
k_mma_gemm(const __nv_bfloat16* __restrict__ Ah, const __nv_bfloat16* __restrict__ Al,
           const __nv_bfloat16* __restrict__ Bh, const __nv_bfloat16* __restrict__ Bl,
           const float* __restrict__ bias, float* __restrict__ C,
           int M, int N, int K, int mode,
           float* __restrict__ colsum, float* __restrict__ colsq) {
    extern __shared__ __align__(16) char dsm[];
    __nv_bfloat16* Ahs = (__nv_bfloat16*)dsm;
    __nv_bfloat16* Als = Ahs + 2 * ABUF;
    __nv_bfloat16* Bhs = Als + 2 * ABUF;
    __nv_bfloat16* Bls = Bhs + 2 * BBUF;
    float* s_sum = (float*)(Bls + 2 * BBUF);
    float* s_sq = s_sum + 128;

    const int tid = threadIdx.x;
    const int lane = tid & 31;
    const int warp = tid >> 5;
    const int wm = warp & 3;
    const int wn = warp >> 2;
    const int bm = blockIdx.y * 128;
    const int bn = blockIdx.x * 128;

    float acc[2][8][4];
#pragma unroll
    for (int i = 0; i < 2; i++)
#pragma unroll
        for (int j = 0; j < 8; j++)
#pragma unroll
            for (int c = 0; c < 4; c++) acc[i][j][c] = 0.f;

    const uint32_t sAh = (uint32_t)__cvta_generic_to_shared(Ahs);
    const uint32_t sAl = (uint32_t)__cvta_generic_to_shared(Als);
    const uint32_t sBh = (uint32_t)__cvta_generic_to_shared(Bhs);
    const uint32_t sBl = (uint32_t)__cvta_generic_to_shared(Bls);

    auto prefetch = [&](int k0, int buf) {
        uint32_t aOff = buf * ABUF * 2;
        uint32_t bOff = buf * BBUF * 2;
#pragma unroll
        for (int it = 0; it < 2; it++) {
            int idx = tid + it * 256;
            int r = idx >> 2, q = idx & 3;
            int gm = bm + r, gk = k0 + q * 8;
            int sz = (gm < M && gk < K) ? 16 : 0;
            int gmc = (gm < M) ? gm : 0;
            int gkc = (gk < K) ? gk : 0;
            uint32_t d = (uint32_t)(r * APAD + q * 8) * 2;
            cpa16(sAh + aOff + d, &Ah[(size_t)gmc * K + gkc], sz);
            cpa16(sAl + aOff + d, &Al[(size_t)gmc * K + gkc], sz);
        }
#pragma unroll
        for (int it = 0; it < 2; it++) {
            int idx = tid + it * 256;
            int r = idx >> 4, q = idx & 15;
            int gk = k0 + r, gn = bn + q * 8;
            int sz = (gk < K) ? 16 : 0;
            int gkc = (gk < K) ? gk : 0;
            uint32_t d = (uint32_t)(r * BPAD + q * 8) * 2;
            cpa16(sBh + bOff + d, &Bh[(size_t)gkc * N + gn], sz);
            cpa16(sBl + bOff + d, &Bl[(size_t)gkc * N + gn], sz);
        }
    };

    const int nk = (K + 31) >> 5;
    prefetch(0, 0);
    cpa_commit();

    for (int kt = 0; kt < nk; kt++) {
        const int cur = kt & 1;
        if (kt + 1 < nk) {
            prefetch((kt + 1) << 5, cur ^ 1);
            cpa_commit();
            cpa_wait<1>();
        } else {
            cpa_wait<0>();
        }
        __syncthreads();

        const __nv_bfloat16* cAh = Ahs + cur * ABUF;
        const __nv_bfloat16* cAl = Als + cur * ABUF;
        const __nv_bfloat16* cBh = Bhs + cur * BBUF;
        const __nv_bfloat16* cBl = Bls + cur * BBUF;

#pragma unroll
        for (int ks = 0; ks < 32; ks += 16) {
            uint32_t ah[2][4], al[2][4], bh[4][4], bl[4][4];
#pragma unroll
            for (int i = 0; i < 2; i++) {
                int rowa = wm * 32 + i * 16 + (lane & 15);
                int kc = ks + ((lane >> 4) << 3);
                ldsm4(ah[i], &cAh[rowa * APAD + kc]);
                ldsm4(al[i], &cAl[rowa * APAD + kc]);
            }
#pragma unroll
            for (int j2 = 0; j2 < 4; j2++) {
                int rowb = ks + (lane & 15);
                int nc = wn * 64 + j2 * 16 + ((lane >> 4) << 3);
                ldsm4t(bh[j2], &cBh[rowb * BPAD + nc]);
                ldsm4t(bl[j2], &cBl[rowb * BPAD + nc]);
            }
#pragma unroll
            for (int i = 0; i < 2; i++)
#pragma unroll
                for (int j = 0; j < 8; j++)
                    mma16816(acc[i][j], ah[i], &bh[j >> 1][(j & 1) * 2]);
#pragma unroll
            for (int i = 0; i < 2; i++)
#pragma unroll
                for (int j = 0; j < 8; j++)
                    mma16816(acc[i][j], ah[i], &bl[j >> 1][(j & 1) * 2]);
#pragma unroll
            for (int i = 0; i < 2; i++)
#pragma unroll
                for (int j = 0; j < 8; j++)
                    mma16816(acc[i][j], al[i], &bh[j >> 1][(j & 1) * 2]);
        }
        __syncthreads();
    }

    // ---- epilogue ----
    if (mode == 3) {
        if (tid < 128) { s_sum[tid] = 0.f; s_sq[tid] = 0.f; }
        __syncthreads();
    }
    float csum[8][2], csq[8][2];
#pragma unroll
    for (int j = 0; j < 8; j++) { csum[j][0] = csum[j][1] = 0.f; csq[j][0] = csq[j][1] = 0.f; }

#pragma unroll
    for (int i = 0; i < 2; i++) {
        int r0 = bm + wm * 32 + i * 16 + (lane >> 2);
#pragma unroll
        for (int j = 0; j < 8; j++) {
            int cc = bn + wn * 64 + j * 8 + (lane & 3) * 2;
            float b0 = 0.f, b1 = 0.f;
            if (mode >= 1) { b0 = bias[cc]; b1 = bias[cc + 1]; }
            float v0 = acc[i][j][0] + b0, v1 = acc[i][j][1] + b1;
            float v2 = acc[i][j][2] + b0, v3 = acc[i][j][3] + b1;
            if (mode >= 2) {
                v0 = fmaxf(v0, 0.f); v1 = fmaxf(v1, 0.f);
                v2 = fmaxf(v2, 0.f); v3 = fmaxf(v3, 0.f);
            }
            if (r0 < M) {
                *(float2*)&C[(size_t)r0 * N + cc] = make_float2(v0, v1);
                if (mode == 3) { csum[j][0] += v0; csum[j][1] += v1; csq[j][0] += v0 * v0; csq[j][1] += v1 * v1; }
            }
            if (r0 + 8 < M) {
                *(float2*)&C[(size_t)(r0 + 8) * N + cc] = make_float2(v2, v3);
                if (mode == 3) { csum[j][0] += v2; csum[j][1] += v3; csq[j][0] += v2 * v2; csq[j][1] += v3 * v3; }
            }
        }
    }
    if (mode == 3) {
#pragma unroll
        for (int j = 0; j < 8; j++) {
            int nl = wn * 64 + j * 8 + (lane & 3) * 2;
            atomicAdd(&s_sum[nl], csum[j][0]);
            atomicAdd(&s_sum[nl + 1], csum[j][1]);
            atomicAdd(&s_sq[nl], csq[j][0]);
            atomicAdd(&s_sq[nl + 1], csq[j][1]);
        }
        __syncthreads();
        if (tid < 128) {
            atomicAdd(&colsum[bn + tid], s_sum[tid]);
            atomicAdd(&colsq[bn + tid], s_sq[tid]);
        }
    }
}

// ---------------- fp32 SGEMM (small head GEMMs) --------------------
__global__ void __launch_bounds__(256, 2)
k_sgemm128(const float* __restrict__ A, const float* __restrict__ B,
           const float* __restrict__ bias, float* __restrict__ C,
           int M, int N, int K, int mode) {
    __shared__ float As[8][132];
    __shared__ float Bs[8][132];
    const int bm = blockIdx.y * 128;
    const int bn = blockIdx.x * 128;
    const int tid = threadIdx.x;
    const int tx = tid & 15, ty = tid >> 4;
    const bool vecK = (K & 3) == 0;
    const bool vecN = (N & 3) == 0;

    float acc[8][8];
#pragma unroll
    for (int i = 0; i < 8; i++)
#pragma unroll
        for (int j = 0; j < 8; j++) acc[i][j] = 0.f;

    const int arow = tid >> 1, ah = tid & 1;
    const int bk = tid >> 5, bn4 = (tid & 31) * 4;

    for (int k0 = 0; k0 < K; k0 += 8) {
        {
            int gm = bm + arow;
            float av[4];
            if (vecK && gm < M && k0 + ah * 4 + 3 < K) {
                float4 v = *(const float4*)&A[(size_t)gm * K + k0 + ah * 4];
                av[0] = v.x; av[1] = v.y; av[2] = v.z; av[3] = v.w;
            } else {
#pragma unroll
                for (int j = 0; j < 4; j++)
                    av[j] = (gm < M && k0 + ah * 4 + j < K)
                                ? A[(size_t)gm * K + k0 + ah * 4 + j] : 0.f;
            }
#pragma unroll
            for (int j = 0; j < 4; j++) As[ah * 4 + j][arow] = av[j];
        }
        {
            float4 v;
            if (vecN && k0 + bk < K && bn + bn4 + 3 < N) {
                v = *(const float4*)&B[(size_t)(k0 + bk) * N + bn + bn4];
            } else {
                float bv[4];
#pragma unroll
                for (int j = 0; j < 4; j++)
                    bv[j] = (k0 + bk < K && bn + bn4 + j < N)
                                ? B[(size_t)(k0 + bk) * N + bn + bn4 + j] : 0.f;
                v = make_float4(bv[0], bv[1], bv[2], bv[3]);
            }
            *(float4*)&Bs[bk][bn4] = v;
        }
        __syncthreads();
#pragma unroll
        for (int k = 0; k < 8; k++) {
            float4 a0 = *(const float4*)&As[k][ty * 4];
            float4 a1 = *(const float4*)&As[k][64 + ty * 4];
            float4 b0 = *(const float4*)&Bs[k][tx * 4];
            float4 b1 = *(const float4*)&Bs[k][64 + tx * 4];
            float a[8] = {a0.x, a0.y, a0.z, a0.w, a1.x, a1.y, a1.z, a1.w};
            float b[8] = {b0.x, b0.y, b0.z, b0.w, b1.x, b1.y, b1.z, b1.w};
#pragma unroll
            for (int i = 0; i < 8; i++)
#pragma unroll
                for (int j = 0; j < 8; j++) acc[i][j] = fmaf(a[i], b[j], acc[i][j]);
        }
        __syncthreads();
    }
#pragma unroll
    for (int i = 0; i < 8; i++) {
        int mr = (i < 4) ? (ty * 4 + i) : (64 + ty * 4 + i - 4);
        int m = bm + mr;
        if (m >= M) continue;
#pragma unroll
        for (int j = 0; j < 8; j++) {
            int nc = (j < 4) ? (tx * 4 + j) : (64 + tx * 4 + j - 4);
            int n = bn + nc;
            if (n >= N) continue;
            float v = acc[i][j];
            if (mode >= 1) v += bias[n];
            if (mode == 2) v = fmaxf(v, 0.f);
            C[(size_t)m * N + n] = v;
        }
    }
}

// ---------------- BN finalize (self-zeroing stats) ----------------
__global__ void k_mkscale(float* __restrict__ colsum, float* __restrict__ colsq,
                          const float* __restrict__ g, const float* __restrict__ be,
                          float* __restrict__ scale, float* __restrict__ shift,
                          float invn, int ncols) {
    int c = blockIdx.x * blockDim.x + threadIdx.x;
    if (c >= ncols) return;
    float mean = colsum[c] * invn;
    float var = colsq[c] * invn - mean * mean;
    float sc = g[c] * rsqrtf(var + BN_EPS);
    scale[c] = sc;
    shift[c] = be[c] - mean * sc;
    colsum[c] = 0.f;
    colsq[c] = 0.f;
}

// ---------------- fused pooling ----------------
__global__ void k_gateprep(const float* __restrict__ scale, const float* __restrict__ shift,
                           const float* __restrict__ gw, const float* __restrict__ gb,
                           float* __restrict__ gw2, float* __restrict__ gconst) {
    __shared__ float red[256];
    int tid = threadIdx.x;
    float part = 0.f;
    for (int c = tid; c < 1024; c += 256) {
        gw2[c] = scale[c] * gw[c];
        part += shift[c] * gw[c];
    }
    red[tid] = part;
    __syncthreads();
    for (int o = 128; o > 0; o >>= 1) {
        if (tid < o) red[tid] += red[tid + o];
        __syncthreads();
    }
    if (tid == 0) gconst[0] = red[0] + gb[0];
}
__global__ void k_bounds(const int* __restrict__ batch, int* gs, int* ge) {
    int i = blockIdx.x * blockDim.x + threadIdx.x;
    if (i >= NN) return;
    int b = batch[i];
    atomicMin(&gs[b], i);
    atomicMax(&ge[b], i + 1);
}

#define SGMAX 1024
__global__ void k_pool_gated(const float* __restrict__ x, const float* __restrict__ gw2,
                             const float* __restrict__ gconstp,
                             const float* __restrict__ scale, const float* __restrict__ shift,
                             const int* __restrict__ gs, const int* __restrict__ ge,
                             float* __restrict__ pooled) {
    int g = blockIdx.x;
    int s = gs[g], e = ge[g];
    int tid = threadIdx.x, lane = tid & 31, warp = tid >> 5;
    __shared__ float sgate[SGMAX];
    __shared__ float red[256];
    float gconst = gconstp[0];

    for (int i = s + warp; i < e; i += 8) {
        const float4* xr = (const float4*)(x + (size_t)i * 1024);
        const float4* w4 = (const float4*)gw2;
        float acc = 0.f;
#pragma unroll
        for (int k = 0; k < 8; k++) {
            float4 a = xr[lane + k * 32];
            float4 b = w4[lane + k * 32];
            acc += a.x * b.x + a.y * b.y + a.z * b.z + a.w * b.w;
        }
#pragma unroll
        for (int o = 16; o > 0; o >>= 1) acc += __shfl_down_sync(0xffffffffu, acc, o);
        if (lane == 0 && (i - s) < SGMAX) sgate[i - s] = acc + gconst;
    }
    __syncthreads();

    auto getg = [&](int i) -> float {
        if (i - s < SGMAX) return sgate[i - s];
        float acc = 0.f;
        const float* xr = x + (size_t)i * 1024;
        for (int c = 0; c < 1024; c++) acc += xr[c] * gw2[c];
        return acc + gconst;
    };

    float m = -INFINITY;
    for (int i = s + tid; i < e; i += 256) m = fmaxf(m, getg(i));
    red[tid] = m;
    __syncthreads();
    for (int o = 128; o > 0; o >>= 1) {
        if (tid < o) red[tid] = fmaxf(red[tid], red[tid + o]);
        __syncthreads();
    }
    float gm = red[0];
    __syncthreads();
    float ss = 0.f;
    for (int i = s + tid; i < e; i += 256) ss += expf(getg(i) - gm);
    red[tid] = ss;
    __syncthreads();
    for (int o = 128; o > 0; o >>= 1) {
        if (tid < o) red[tid] += red[tid + o];
        __syncthreads();
    }
    float inv = (e > s) ? 1.0f / red[0] : 0.f;

    int d = tid * 4;
    float4 acc = make_float4(0.f, 0.f, 0.f, 0.f);
    float ws = 0.f;
    for (int i = s; i < e; i++) {
        float w = expf(getg(i) - gm) * inv;
        ws += w;
        float4 v = *(const float4*)&x[(size_t)i * 1024 + d];
        acc.x += w * v.x; acc.y += w * v.y; acc.z += w * v.z; acc.w += w * v.w;
    }
    float4 o;
    o.x = scale[d + 0] * acc.x + shift[d + 0] * ws;
    o.y = scale[d + 1] * acc.y + shift[d + 1] * ws;
    o.z = scale[d + 2] * acc.z + shift[d + 2] * ws;
    o.w = scale[d + 3] * acc.w + shift[d + 3] * ws;
    *(float4*)&pooled[(size_t)g * 1024 + d] = o;
}

// ---------------- host orchestration ----------------
static inline int cdiv(long a, long b) { return (int)((a + b - 1) / b); }

static void gemm_tc(const __nv_bfloat16* Ah, const __nv_bfloat16* Al,
                    const __nv_bfloat16* Bh, const __nv_bfloat16* Bl,
                    const float* bias, float* C,
                    int M, int N, int K, int mode, float* colsum, float* colsq) {
    dim3 grid(N / 128, cdiv(M, 128));
    k_mma_gemm<<<grid, 256, GEMM_SMEM>>>(Ah, Al, Bh, Bl, bias, C, M, N, K, mode, colsum, colsq);
}
static void gemm32(const float* A, const float* B, const float* bias, float* C,
                   int M, int N, int K, int mode) {
    dim3 grid(cdiv(N, 128), cdiv(M, 128));
    k_sgemm128<<<grid, 256>>>(A, B, bias, C, M, N, K, mode);
}

extern "C" void kernel_launch(void* const* d_in, const int* in_sizes, int n_in,
                              void* d_out, int out_size) {
    (void)in_sizes; (void)n_in; (void)out_size;
    const float* x_in  = (const float*)d_in[0];
    const int*   ei    = (const int*)d_in[1];
    const int*   batch = (const int*)d_in[2];
    const float *W[5], *bb[5], *gg[5], *be[5];
    for (int l = 0; l < 5; l++) {
        W[l]  = (const float*)d_in[3 + 4 * l];
        bb[l] = (const float*)d_in[4 + 4 * l];
        gg[l] = (const float*)d_in[5 + 4 * l];
        be[l] = (const float*)d_in[6 + 4 * l];
    }
    const float* gate_W = (const float*)d_in[23];
    const float* gate_b = (const float*)d_in[24];
    const float* fc2_W  = (const float*)d_in[25];
    const float* fc2_b  = (const float*)d_in[26];
    const float* fc3_W  = (const float*)d_in[27];
    const float* fc3_b  = (const float*)d_in[28];
    const float* fc4_W  = (const float*)d_in[29];
    const float* fc4_b  = (const float*)d_in[30];
    float* out = (float*)d_out;

    float *dis, *norm, *bufA, *bufB, *bufC, *colsum, *colsq, *scale, *shift;
    float *pooled, *h2, *h3, *csr_w, *gw2, *gconst;
    __nv_bfloat16 *ah, *al, *wh, *wl;
    int *gs, *ge, *counts, *off, *cursor, *csr_src;
    cudaGetSymbolAddress((void**)&dis,     g_dis);
    cudaGetSymbolAddress((void**)&norm,    g_norm);
    cudaGetSymbolAddress((void**)&counts,  g_counts);
    cudaGetSymbolAddress((void**)&off,     g_off);
    cudaGetSymbolAddress((void**)&cursor,  g_cursor);
    cudaGetSymbolAddress((void**)&csr_src, g_src);
    cudaGetSymbolAddress((void**)&csr_w,   g_w);
    cudaGetSymbolAddress((void**)&bufA,    g_bufA);
    cudaGetSymbolAddress((void**)&bufB,    g_bufB);
    cudaGetSymbolAddress((void**)&bufC,    g_bufC);
    cudaGetSymbolAddress((void**)&ah,      g_ah);
    cudaGetSymbolAddress((void**)&al,      g_al);
    cudaGetSymbolAddress((void**)&wh,      g_wh);
    cudaGetSymbolAddress((void**)&wl,      g_wl);
    cudaGetSymbolAddress((void**)&colsum,  g_colsum);
    cudaGetSymbolAddress((void**)&colsq,   g_colsq);
    cudaGetSymbolAddress((void**)&scale,   g_scale);
    cudaGetSymbolAddress((void**)&shift,   g_shift);
    cudaGetSymbolAddress((void**)&gw2,     g_gw2);
    cudaGetSymbolAddress((void**)&gconst,  g_gconst);
    cudaGetSymbolAddress((void**)&gs,      g_gs);
    cudaGetSymbolAddress((void**)&ge,      g_ge);
    cudaGetSymbolAddress((void**)&pooled,  g_pooled);
    cudaGetSymbolAddress((void**)&h2,      g_h2);
    cudaGetSymbolAddress((void**)&h3,      g_h3);

    cudaFuncSetAttribute(k_mma_gemm, cudaFuncAttributeMaxDynamicSharedMemorySize, GEMM_SMEM);

    const int* row = ei;
    const int* col = ei + NE;

    const size_t wo1 = 0;
    const size_t wo2 = wo1 + (size_t)K1PAD * 1024;
    const size_t wo3 = wo2 + (size_t)1024 * 512;
    const size_t wo4 = wo3 + (size_t)512 * 256;
    const size_t wo5 = wo4 + (size_t)256 * 512;
    const size_t wo6 = wo5 + (size_t)512 * 1024;

    // ---- GCN norm + CSR build ----
    k_filli<<<256, 256>>>(counts, 0, NN);
    k_histc<<<cdiv(NE, 256), 256>>>(col, counts);
    k_disk<<<cdiv(NN, 256), 256>>>(counts, dis);
    k_edge_norm<<<cdiv(NE, 256), 256>>>(row, col, dis, norm);
    k_scan<<<1, 1024>>>(counts, off);
    k_copyi<<<cdiv(NN, 256), 256>>>(off, cursor, NN);
    k_scatter<<<cdiv(NE, 256), 256>>>(row, col, norm, cursor, csr_src, csr_w);

    // ---- weight pre-split ----
    k_split_mat<<<cdiv((long)K1PAD * 1024, 256), 256>>>(W[0], wh + wo1, wl + wo1, NF, K1PAD, 1024);
    k_split_mat<<<cdiv((long)1024 * 512, 256), 256>>>(W[1], wh + wo2, wl + wo2, 1024, 1024, 512);
    k_split_mat<<<cdiv((long)512 * 256, 256), 256>>>(W[2], wh + wo3, wl + wo3, 512, 512, 256);
    k_split_mat<<<cdiv((long)256 * 512, 256), 256>>>(W[3], wh + wo4, wl + wo4, 256, 256, 512);
    k_split_mat<<<cdiv((long)512 * 1024, 256), 256>>>(W[4], wh + wo5, wl + wo5, 512, 512, 1024);
    k_split_mat<<<cdiv((long)1024 * 128, 256), 256>>>(fc2_W, wh + wo6, wl + wo6, 1024, 1024, 128);

    const float invn = 1.0f / NN;

    // ---- Layer 1 ----
    k_prop39<<<2048, dim3(64, 4)>>>(x_in, ah, al, dis, off, csr_src, csr_w);
    gemm_tc(ah, al, wh + wo1, wl + wo1, bb[0], bufB, NN, 1024, K1PAD, 3, colsum, colsq);
    k_mkscale<<<4, 256>>>(colsum, colsq, gg[0], be[0], scale, shift, invn, 1024);
    k_bnsplit<<<cdiv((long)NN * 256, 256), 256>>>((const float4*)bufB, scale, shift, ah, al, 256, NN * 256);

    // ---- Layer 2 ----
    gemm_tc(ah, al, wh + wo2, wl + wo2, nullptr, bufA, NN, 512, 1024, 0, nullptr, nullptr);
    k_prop4<128, 2, 1><<<2048, dim3(128, 2)>>>((const float4*)bufA, (float4*)bufC, nullptr, nullptr,
                                               dis, off, csr_src, csr_w, bb[1], nullptr, nullptr,
                                               colsum, colsq);
    k_mkscale<<<2, 256>>>(colsum, colsq, gg[1], be[1], scale, shift, invn, 512);
    k_bnsplit<<<cdiv((long)NN * 128, 256), 256>>>((const float4*)bufC, scale, shift, ah, al, 128, NN * 128);

    // ---- Layer 3 ----
    gemm_tc(ah, al, wh + wo3, wl + wo3, nullptr, bufA, NN, 256, 512, 0, nullptr, nullptr);
    k_prop4<64, 4, 1><<<2048, dim3(64, 4)>>>((const float4*)bufA, (float4*)bufB, nullptr, nullptr,
                                             dis, off, csr_src, csr_w, bb[2], nullptr, nullptr,
                                             colsum, colsq);
    k_mkscale<<<1, 256>>>(colsum, colsq, gg[2], be[2], scale, shift, invn, 256);

    // ---- Layer 4 ----
    k_prop4<64, 4, 2><<<2048, dim3(64, 4)>>>((const float4*)bufB, nullptr, ah, al,
                                             dis, off, csr_src, csr_w, nullptr, scale, shift,
                                             nullptr, nullptr);
    gemm_tc(ah, al, wh + wo4, wl + wo4, bb[3], bufC, NN, 512, 256, 3, colsum, colsq);
    k_mkscale<<<2, 256>>>(colsum, colsq, gg[3], be[3], scale, shift, invn, 512);

    // ---- Layer 5 ----
    k_prop4<128, 2, 2><<<2048, dim3(128, 2)>>>((const float4*)bufC, nullptr, ah, al,
                                               dis, off, csr_src, csr_w, nullptr, scale, shift,
                                               nullptr, nullptr);
    gemm_tc(ah, al, wh + wo5, wl + wo5, bb[4], bufB, NN, 1024, 512, 3, colsum, colsq);
    k_mkscale<<<4, 256>>>(colsum, colsq, gg[4], be[4], scale, shift, invn, 1024);

    // ---- attentional pooling (BN5 folded in) ----
    k_gateprep<<<1, 256>>>(scale, shift, gate_W, gate_b, gw2, gconst);
    k_filli<<<32, 256>>>(gs, NN, NG);
    k_filli<<<32, 256>>>(ge, 0, NG);
    k_bounds<<<cdiv(NN, 256), 256>>>(batch, gs, ge);
    k_pool_gated<<<NG, 256>>>(bufB, gw2, gconst, scale, shift, gs, ge, pooled);

    // ---- MLP head ----
    k_split_mat<<<cdiv((long)NG * 1024, 256), 256>>>(pooled, ah, al, NG, NG, 1024);
    gemm_tc(ah, al, wh + wo6, wl + wo6, fc2_b, h2, NG, 128, 1024, 2, nullptr, nullptr);
    gemm32(h2, fc3_W, fc3_b, h3, NG, 16, 128, 2);
    gemm32(h3, fc4_W, fc4_b, out, NG, 1, 16, 1);
}

// round 12
// speedup vs baseline: 1.2922x; 1.0177x over previous
#include <cuda_runtime.h>
#include <cuda_bf16.h>
#include <math.h>
#include <stdint.h>

#define NN 100000
#define NE 400000
#define NG 4000
#define NF 39
#define K1PAD 40
#define DMAX 1024
#define BN_EPS 1e-5f
// W1(40x1024)+W2(1024x512)+W3(512x256)+W4(256x512)+W5(512x1024)+fc2(1024x128)
#define WTOT 1482752

// ---------------- static device scratch ----------------
__device__ float g_dis[NN];
__device__ float g_norm[NE];
__device__ int   g_counts[NN];
__device__ int   g_off[NN + 1];
__device__ int   g_cursor[NN];
__device__ int   g_src[NE];
__device__ float g_w[NE];
__device__ float g_bufA[(size_t)NN * DMAX];
__device__ float g_bufB[(size_t)NN * DMAX];
__device__ float g_bufC[(size_t)NN * DMAX];
__device__ __align__(16) __nv_bfloat16 g_ah[(size_t)NN * DMAX];
__device__ __align__(16) __nv_bfloat16 g_al[(size_t)NN * DMAX];
__device__ __align__(16) __nv_bfloat16 g_wh[WTOT];
__device__ __align__(16) __nv_bfloat16 g_wl[WTOT];
__device__ float g_colsum[DMAX];
__device__ float g_colsq[DMAX];
__device__ float g_scale[DMAX];
__device__ float g_shift[DMAX];
__device__ float g_gw2[DMAX];
__device__ float g_gconst[1];
__device__ int   g_gs[NG];
__device__ int   g_ge[NG];
__device__ float g_pooled[(size_t)NG * DMAX];
__device__ float g_h2[NG * 128];
__device__ float g_h3[NG * 16];

// ---------------- utility ----------------
__global__ void k_filli(int* p, int v, int n) {
    for (int i = blockIdx.x * blockDim.x + threadIdx.x; i < n; i += gridDim.x * blockDim.x)
        p[i] = v;
}
__global__ void k_copyi(const int* __restrict__ a, int* __restrict__ b, int n) {
    for (int i = blockIdx.x * blockDim.x + threadIdx.x; i < n; i += gridDim.x * blockDim.x)
        b[i] = a[i];
}

__device__ __forceinline__ void splitf(float v, __nv_bfloat16& h, __nv_bfloat16& l) {
    h = __float2bfloat16(v);
    l = __float2bfloat16(v - __bfloat162float(h));
}

// ---------------- CSR build ----------------
__global__ void k_histc(const int* __restrict__ col, int* counts) {
    int e = blockIdx.x * blockDim.x + threadIdx.x;
    if (e < NE) atomicAdd(&counts[col[e]], 1);
}
__global__ void k_disk(const int* __restrict__ counts, float* dis) {
    int i = blockIdx.x * blockDim.x + threadIdx.x;
    if (i < NN) dis[i] = rsqrtf((float)counts[i] + 1.0f);
}
__global__ void k_edge_norm(const int* __restrict__ row, const int* __restrict__ col,
                            const float* __restrict__ dis, float* __restrict__ norm) {
    int e = blockIdx.x * blockDim.x + threadIdx.x;
    if (e < NE) norm[e] = dis[row[e]] * dis[col[e]];
}
__global__ void k_scan(const int* __restrict__ counts, int* __restrict__ off) {
    __shared__ int sh[1024];
    __shared__ int carry_s;
    int t = threadIdx.x;
    if (t == 0) { carry_s = 0; off[0] = 0; }
    __syncthreads();
    for (int base = 0; base < NN; base += 1024) {
        int i = base + t;
        int v = (i < NN) ? counts[i] : 0;
        sh[t] = v;
        __syncthreads();
        for (int o = 1; o < 1024; o <<= 1) {
            int add = (t >= o) ? sh[t - o] : 0;
            __syncthreads();
            sh[t] += add;
            __syncthreads();
        }
        int carry = carry_s;
        if (i < NN) off[i + 1] = carry + sh[t];
        __syncthreads();
        if (t == 1023) carry_s = carry + sh[1023];
        __syncthreads();
    }
}
__global__ void k_scatter(const int* __restrict__ row, const int* __restrict__ col,
                          const float* __restrict__ norm, int* cursor,
                          int* __restrict__ csr_src, float* __restrict__ csr_w) {
    int e = blockIdx.x * blockDim.x + threadIdx.x;
    if (e >= NE) return;
    int c = col[e];
    int p = atomicAdd(&cursor[c], 1);
    csr_src[p] = row[e];
    csr_w[p] = norm[e];
}

// ---------------- split passes ----------------
__global__ void k_split_mat(const float* __restrict__ src, __nv_bfloat16* __restrict__ oh,
                            __nv_bfloat16* __restrict__ ol, int k, int kpad, int n) {
    int idx = blockIdx.x * blockDim.x + threadIdx.x;
    if (idx >= kpad * n) return;
    int r = idx / n, c = idx - r * n;
    float v = (r < k) ? src[(size_t)r * n + c] : 0.f;
    __nv_bfloat16 h, l;
    splitf(v, h, l);
    oh[idx] = h;
    ol[idx] = l;
}
__global__ void k_bnsplit(const float4* __restrict__ y, const float* __restrict__ scale,
                          const float* __restrict__ shift,
                          __nv_bfloat16* __restrict__ oh, __nv_bfloat16* __restrict__ ol,
                          int dimv, int total4) {
    int idx = blockIdx.x * blockDim.x + threadIdx.x;
    if (idx >= total4) return;
    int c = (idx % dimv) * 4;
    float4 v = y[idx];
    v.x = v.x * scale[c + 0] + shift[c + 0];
    v.y = v.y * scale[c + 1] + shift[c + 1];
    v.z = v.z * scale[c + 2] + shift[c + 2];
    v.w = v.w * scale[c + 3] + shift[c + 3];
    __nv_bfloat16 h0, l0, h1, l1, h2, l2, h3, l3;
    splitf(v.x, h0, l0); splitf(v.y, h1, l1); splitf(v.z, h2, l2); splitf(v.w, h3, l3);
    uint2 hv, lv;
    hv.x = ((uint32_t)__bfloat16_as_ushort(h1) << 16) | __bfloat16_as_ushort(h0);
    hv.y = ((uint32_t)__bfloat16_as_ushort(h3) << 16) | __bfloat16_as_ushort(h2);
    lv.x = ((uint32_t)__bfloat16_as_ushort(l1) << 16) | __bfloat16_as_ushort(l0);
    lv.y = ((uint32_t)__bfloat16_as_ushort(l3) << 16) | __bfloat16_as_ushort(l2);
    *(uint2*)&oh[(size_t)idx * 4] = hv;
    *(uint2*)&ol[(size_t)idx * 4] = lv;
}

// ---------------- CSR gather propagate (R9 form) ----------------
template <int DIMV, int NPB, int MODE>
__global__ void k_prop4(const float4* __restrict__ in, float4* __restrict__ out,
                        __nv_bfloat16* __restrict__ outh, __nv_bfloat16* __restrict__ outl,
                        const float* __restrict__ dis,
                        const int* __restrict__ off, const int* __restrict__ src,
                        const float* __restrict__ w,
                        const float* __restrict__ bias,
                        const float* __restrict__ insc, const float* __restrict__ insh,
                        float* __restrict__ colsum, float* __restrict__ colsq) {
    const int DIM = DIMV * 4;
    int x = threadIdx.x;
    int yy = threadIdx.y;
    float4 bb = make_float4(0.f, 0.f, 0.f, 0.f);
    float4 sc4 = make_float4(0.f, 0.f, 0.f, 0.f), sh4 = sc4;
    float4 s1 = make_float4(0.f, 0.f, 0.f, 0.f);
    float4 s2 = make_float4(0.f, 0.f, 0.f, 0.f);
    if (MODE == 1) bb = *(const float4*)&bias[x * 4];
    if (MODE == 2) {
        sc4 = *(const float4*)&insc[x * 4];
        sh4 = *(const float4*)&insh[x * 4];
    }
    for (int n = blockIdx.x * NPB + yy; n < NN; n += gridDim.x * NPB) {
        float d = dis[n];
        float sw = d * d;
        float4 v = in[(size_t)n * DIMV + x];
        float4 acc = make_float4(sw * v.x, sw * v.y, sw * v.z, sw * v.w);
        float wsum = sw;
        int e1 = __ldg(&off[n + 1]);
        for (int e = __ldg(&off[n]); e < e1; e++) {
            int sr = __ldg(&src[e]);
            float ww = __ldg(&w[e]);
            wsum += ww;
            float4 u = in[(size_t)sr * DIMV + x];
            acc.x = fmaf(ww, u.x, acc.x);
            acc.y = fmaf(ww, u.y, acc.y);
            acc.z = fmaf(ww, u.z, acc.z);
            acc.w = fmaf(ww, u.w, acc.w);
        }
        if (MODE == 1) {
            acc.x = fmaxf(acc.x + bb.x, 0.f);
            acc.y = fmaxf(acc.y + bb.y, 0.f);
            acc.z = fmaxf(acc.z + bb.z, 0.f);
            acc.w = fmaxf(acc.w + bb.w, 0.f);
            out[(size_t)n * DIMV + x] = acc;
            s1.x += acc.x; s1.y += acc.y; s1.z += acc.z; s1.w += acc.w;
            s2.x += acc.x * acc.x; s2.y += acc.y * acc.y;
            s2.z += acc.z * acc.z; s2.w += acc.w * acc.w;
        } else {
            acc.x = sc4.x * acc.x + sh4.x * wsum;
            acc.y = sc4.y * acc.y + sh4.y * wsum;
            acc.z = sc4.z * acc.z + sh4.z * wsum;
            acc.w = sc4.w * acc.w + sh4.w * wsum;
            __nv_bfloat16 h0, l0, h1, l1, h2, l2, h3, l3;
            splitf(acc.x, h0, l0); splitf(acc.y, h1, l1);
            splitf(acc.z, h2, l2); splitf(acc.w, h3, l3);
            uint2 hv, lv;
            hv.x = ((uint32_t)__bfloat16_as_ushort(h1) << 16) | __bfloat16_as_ushort(h0);
            hv.y = ((uint32_t)__bfloat16_as_ushort(h3) << 16) | __bfloat16_as_ushort(h2);
            lv.x = ((uint32_t)__bfloat16_as_ushort(l1) << 16) | __bfloat16_as_ushort(l0);
            lv.y = ((uint32_t)__bfloat16_as_ushort(l3) << 16) | __bfloat16_as_ushort(l2);
            *(uint2*)&outh[(size_t)n * DIM + x * 4] = hv;
            *(uint2*)&outl[(size_t)n * DIM + x * 4] = lv;
        }
    }
    if (MODE == 1) {
        int c = x * 4;
        atomicAdd(&colsum[c + 0], s1.x);
        atomicAdd(&colsum[c + 1], s1.y);
        atomicAdd(&colsum[c + 2], s1.z);
        atomicAdd(&colsum[c + 3], s1.w);
        atomicAdd(&colsq[c + 0], s2.x);
        atomicAdd(&colsq[c + 1], s2.y);
        atomicAdd(&colsq[c + 2], s2.z);
        atomicAdd(&colsq[c + 3], s2.w);
    }
}

__global__ void k_prop39(const float* __restrict__ in,
                         __nv_bfloat16* __restrict__ oh, __nv_bfloat16* __restrict__ ol,
                         const float* __restrict__ dis,
                         const int* __restrict__ off, const int* __restrict__ src,
                         const float* __restrict__ w) {
    int x = threadIdx.x;
    if (x >= K1PAD) return;
    int yy = threadIdx.y;
    __nv_bfloat16 z = __float2bfloat16(0.f);
    for (int n = blockIdx.x * 4 + yy; n < NN; n += gridDim.x * 4) {
        if (x >= NF) {
            oh[(size_t)n * K1PAD + x] = z;
            ol[(size_t)n * K1PAD + x] = z;
            continue;
        }
        float d = dis[n];
        float acc = d * d * in[(size_t)n * NF + x];
        int e1 = __ldg(&off[n + 1]);
        for (int e = __ldg(&off[n]); e < e1; e++)
            acc = fmaf(__ldg(&w[e]), in[(size_t)__ldg(&src[e]) * NF + x], acc);
        __nv_bfloat16 h, l;
        splitf(acc, h, l);
        oh[(size_t)n * K1PAD + x] = h;
        ol[(size_t)n * K1PAD + x] = l;
    }
}

// ======== bf16 3-product tensor-core GEMM (2-stage cp.async, 2 CTA/SM) =========
__device__ __forceinline__ void ldsm4(uint32_t* r, const void* p) {
    uint32_t a = (uint32_t)__cvta_generic_to_shared(p);
    asm volatile("ldmatrix.sync.aligned.m8n8.x4.shared.b16 {%0,%1,%2,%3}, [%4];"
                 : "=r"(r[0]), "=r"(r[1]), "=r"(r[2]), "=r"(r[3]) : "r"(a));
}
__device__ __forceinline__ void ldsm4t(uint32_t* r, const void* p) {
    uint32_t a = (uint32_t)__cvta_generic_to_shared(p);
    asm volatile("ldmatrix.sync.aligned.m8n8.x4.trans.shared.b16 {%0,%1,%2,%3}, [%4];"
                 : "=r"(r[0]), "=r"(r[1]), "=r"(r[2]), "=r"(r[3]) : "r"(a));
}
__device__ __forceinline__ void mma16816(float* d, const uint32_t* a, const uint32_t* b) {
    asm volatile("mma.sync.aligned.m16n8k16.row.col.f32.bf16.bf16.f32 "
                 "{%0,%1,%2,%3}, {%4,%5,%6,%7}, {%8,%9}, {%0,%1,%2,%3};"
                 : "+f"(d[0]), "+f"(d[1]), "+f"(d[2]), "+f"(d[3])
                 : "r"(a[0]), "r"(a[1]), "r"(a[2]), "r"(a[3]),
                   "r"(b[0]), "r"(b[1]));
}
__device__ __forceinline__ void cpa16(uint32_t saddr, const void* g, int sz) {
    asm volatile("cp.async.cg.shared.global [%0], [%1], 16, %2;"
                 :: "r"(saddr), "l"(g), "r"(sz));
}
__device__ __forceinline__ void cpa_commit() {
    asm volatile("cp.async.commit_group;");
}
template <int N>
__device__ __forceinline__ void cpa_wait() {
    asm volatile("cp.async.wait_group %0;" :: "n"(N));
}

#define APAD 40   // A smem row stride: 80B/row (odd 16B multiple)
#define BPAD 136  // B smem row stride: 272B/row
#define ABUF (128 * APAD)
#define BBUF (32 * BPAD)
// dynamic smem: Ah[2], Al[2], Bh[2], Bl[2], s_sum[128], s_sq[128]
#define GEMM_SMEM (2 * (2 * ABUF + 2 * BBUF) * 2 + 256 * 4)

// mode: 0 = raw, 1 = +bias, 2 = +bias+relu, 3 = +bias+relu+stats
__global__ void __launch_bounds__(256, 2)
k_mma_gemm(const __nv_bfloat16* __restrict__ Ah, const __nv_bfloat16* __restrict__ Al,
           const __nv_bfloat16* __restrict__ Bh, const __nv_bfloat16* __restrict__ Bl,
           const float* __restrict__ bias, float* __restrict__ C,
           int M, int N, int K, int mode,
           float* __restrict__ colsum, float* __restrict__ colsq) {
    extern __shared__ __align__(16) char dsm[];
    __nv_bfloat16* Ahs = (__nv_bfloat16*)dsm;
    __nv_bfloat16* Als = Ahs + 2 * ABUF;
    __nv_bfloat16* Bhs = Als + 2 * ABUF;
    __nv_bfloat16* Bls = Bhs + 2 * BBUF;
    float* s_sum = (float*)(Bls + 2 * BBUF);
    float* s_sq = s_sum + 128;

    const int tid = threadIdx.x;
    const int lane = tid & 31;
    const int warp = tid >> 5;
    const int wm = warp & 3;
    const int wn = warp >> 2;
    const int bm = blockIdx.y * 128;
    const int bn = blockIdx.x * 128;

    float acc[2][8][4];
#pragma unroll
    for (int i = 0; i < 2; i++)
#pragma unroll
        for (int j = 0; j < 8; j++)
#pragma unroll
            for (int c = 0; c < 4; c++) acc[i][j][c] = 0.f;

    const uint32_t sAh = (uint32_t)__cvta_generic_to_shared(Ahs);
    const uint32_t sAl = (uint32_t)__cvta_generic_to_shared(Als);
    const uint32_t sBh = (uint32_t)__cvta_generic_to_shared(Bhs);
    const uint32_t sBl = (uint32_t)__cvta_generic_to_shared(Bls);

    auto prefetch = [&](int k0, int buf) {
        uint32_t aOff = buf * ABUF * 2;
        uint32_t bOff = buf * BBUF * 2;
#pragma unroll
        for (int it = 0; it < 2; it++) {
            int idx = tid + it * 256;
            int r = idx >> 2, q = idx & 3;
            int gm = bm + r, gk = k0 + q * 8;
            int sz = (gm < M && gk < K) ? 16 : 0;
            int gmc = (gm < M) ? gm : 0;
            int gkc = (gk < K) ? gk : 0;
            uint32_t d = (uint32_t)(r * APAD + q * 8) * 2;
            cpa16(sAh + aOff + d, &Ah[(size_t)gmc * K + gkc], sz);
            cpa16(sAl + aOff + d, &Al[(size_t)gmc * K + gkc], sz);
        }
#pragma unroll
        for (int it = 0; it < 2; it++) {
            int idx = tid + it * 256;
            int r = idx >> 4, q = idx & 15;
            int gk = k0 + r, gn = bn + q * 8;
            int sz = (gk < K) ? 16 : 0;
            int gkc = (gk < K) ? gk : 0;
            uint32_t d = (uint32_t)(r * BPAD + q * 8) * 2;
            cpa16(sBh + bOff + d, &Bh[(size_t)gkc * N + gn], sz);
            cpa16(sBl + bOff + d, &Bl[(size_t)gkc * N + gn], sz);
        }
    };

    const int nk = (K + 31) >> 5;
    prefetch(0, 0);
    cpa_commit();

    for (int kt = 0; kt < nk; kt++) {
        const int cur = kt & 1;
        if (kt + 1 < nk) {
            prefetch((kt + 1) << 5, cur ^ 1);
            cpa_commit();
            cpa_wait<1>();
        } else {
            cpa_wait<0>();
        }
        __syncthreads();

        const __nv_bfloat16* cAh = Ahs + cur * ABUF;
        const __nv_bfloat16* cAl = Als + cur * ABUF;
        const __nv_bfloat16* cBh = Bhs + cur * BBUF;
        const __nv_bfloat16* cBl = Bls + cur * BBUF;

#pragma unroll
        for (int ks = 0; ks < 32; ks += 16) {
            uint32_t ah[2][4], al[2][4];
#pragma unroll
            for (int i = 0; i < 2; i++) {
                int rowa = wm * 32 + i * 16 + (lane & 15);
                int kc = ks + ((lane >> 4) << 3);
                ldsm4(ah[i], &cAh[rowa * APAD + kc]);
                ldsm4(al[i], &cAl[rowa * APAD + kc]);
            }
            // process the 128-col N tile in two 64-col halves to cap B-frag liveness
#pragma unroll
            for (int nh = 0; nh < 2; nh++) {
                uint32_t bh[2][4], bl[2][4];
#pragma unroll
                for (int j2 = 0; j2 < 2; j2++) {
                    int rowb = ks + (lane & 15);
                    int nc = wn * 64 + (nh * 2 + j2) * 16 + ((lane >> 4) << 3);
                    ldsm4t(bh[j2], &cBh[rowb * BPAD + nc]);
                    ldsm4t(bl[j2], &cBl[rowb * BPAD + nc]);
                }
#pragma unroll
                for (int i = 0; i < 2; i++)
#pragma unroll
                    for (int j = 0; j < 4; j++)
                        mma16816(acc[i][nh * 4 + j], ah[i], &bh[j >> 1][(j & 1) * 2]);
#pragma unroll
                for (int i = 0; i < 2; i++)
#pragma unroll
                    for (int j = 0; j < 4; j++)
                        mma16816(acc[i][nh * 4 + j], ah[i], &bl[j >> 1][(j & 1) * 2]);
#pragma unroll
                for (int i = 0; i < 2; i++)
#pragma unroll
                    for (int j = 0; j < 4; j++)
                        mma16816(acc[i][nh * 4 + j], al[i], &bh[j >> 1][(j & 1) * 2]);
            }
        }
        __syncthreads();
    }

    // ---- epilogue ----
    if (mode == 3) {
        if (tid < 128) { s_sum[tid] = 0.f; s_sq[tid] = 0.f; }
        __syncthreads();
    }
    float csum[8][2], csq[8][2];
#pragma unroll
    for (int j = 0; j < 8; j++) { csum[j][0] = csum[j][1] = 0.f; csq[j][0] = csq[j][1] = 0.f; }

#pragma unroll
    for (int i = 0; i < 2; i++) {
        int r0 = bm + wm * 32 + i * 16 + (lane >> 2);
#pragma unroll
        for (int j = 0; j < 8; j++) {
            // column mapping: acc[i][j] covers cols wn*64 + (j>>2)*32 + (j&3)*8? no:
            // j = nh*4 + jj with nh = j>>2, jj = j&3; nc group = (nh*2 + (jj>>1))*16 + (jj&1)*8
            int nh = j >> 2, jj = j & 3;
            int cc = bn + wn * 64 + (nh * 2 + (jj >> 1)) * 16 + (jj & 1) * 8 + (lane & 3) * 2;
            float b0 = 0.f, b1 = 0.f;
            if (mode >= 1) { b0 = bias[cc]; b1 = bias[cc + 1]; }
            float v0 = acc[i][j][0] + b0, v1 = acc[i][j][1] + b1;
            float v2 = acc[i][j][2] + b0, v3 = acc[i][j][3] + b1;
            if (mode >= 2) {
                v0 = fmaxf(v0, 0.f); v1 = fmaxf(v1, 0.f);
                v2 = fmaxf(v2, 0.f); v3 = fmaxf(v3, 0.f);
            }
            if (r0 < M) {
                *(float2*)&C[(size_t)r0 * N + cc] = make_float2(v0, v1);
                if (mode == 3) { csum[j][0] += v0; csum[j][1] += v1; csq[j][0] += v0 * v0; csq[j][1] += v1 * v1; }
            }
            if (r0 + 8 < M) {
                *(float2*)&C[(size_t)(r0 + 8) * N + cc] = make_float2(v2, v3);
                if (mode == 3) { csum[j][0] += v2; csum[j][1] += v3; csq[j][0] += v2 * v2; csq[j][1] += v3 * v3; }
            }
        }
    }
    if (mode == 3) {
#pragma unroll
        for (int j = 0; j < 8; j++) {
            int nh = j >> 2, jj = j & 3;
            int nl = wn * 64 + (nh * 2 + (jj >> 1)) * 16 + (jj & 1) * 8 + (lane & 3) * 2;
            atomicAdd(&s_sum[nl], csum[j][0]);
            atomicAdd(&s_sum[nl + 1], csum[j][1]);
            atomicAdd(&s_sq[nl], csq[j][0]);
            atomicAdd(&s_sq[nl + 1], csq[j][1]);
        }
        __syncthreads();
        if (tid < 128) {
            atomicAdd(&colsum[bn + tid], s_sum[tid]);
            atomicAdd(&colsq[bn + tid], s_sq[tid]);
        }
    }
}

// ---------------- fp32 SGEMM (small head GEMMs) --------------------
__global__ void __launch_bounds__(256, 2)
k_sgemm128(const float* __restrict__ A, const float* __restrict__ B,
           const float* __restrict__ bias, float* __restrict__ C,
           int M, int N, int K, int mode) {
    __shared__ float As[8][132];
    __shared__ float Bs[8][132];
    const int bm = blockIdx.y * 128;
    const int bn = blockIdx.x * 128;
    const int tid = threadIdx.x;
    const int tx = tid & 15, ty = tid >> 4;
    const bool vecK = (K & 3) == 0;
    const bool vecN = (N & 3) == 0;

    float acc[8][8];
#pragma unroll
    for (int i = 0; i < 8; i++)
#pragma unroll
        for (int j = 0; j < 8; j++) acc[i][j] = 0.f;

    const int arow = tid >> 1, ah = tid & 1;
    const int bk = tid >> 5, bn4 = (tid & 31) * 4;

    for (int k0 = 0; k0 < K; k0 += 8) {
        {
            int gm = bm + arow;
            float av[4];
            if (vecK && gm < M && k0 + ah * 4 + 3 < K) {
                float4 v = *(const float4*)&A[(size_t)gm * K + k0 + ah * 4];
                av[0] = v.x; av[1] = v.y; av[2] = v.z; av[3] = v.w;
            } else {
#pragma unroll
                for (int j = 0; j < 4; j++)
                    av[j] = (gm < M && k0 + ah * 4 + j < K)
                                ? A[(size_t)gm * K + k0 + ah * 4 + j] : 0.f;
            }
#pragma unroll
            for (int j = 0; j < 4; j++) As[ah * 4 + j][arow] = av[j];
        }
        {
            float4 v;
            if (vecN && k0 + bk < K && bn + bn4 + 3 < N) {
                v = *(const float4*)&B[(size_t)(k0 + bk) * N + bn + bn4];
            } else {
                float bv[4];
#pragma unroll
                for (int j = 0; j < 4; j++)
                    bv[j] = (k0 + bk < K && bn + bn4 + j < N)
                                ? B[(size_t)(k0 + bk) * N + bn + bn4 + j] : 0.f;
                v = make_float4(bv[0], bv[1], bv[2], bv[3]);
            }
            *(float4*)&Bs[bk][bn4] = v;
        }
        __syncthreads();
#pragma unroll
        for (int k = 0; k < 8; k++) {
            float4 a0 = *(const float4*)&As[k][ty * 4];
            float4 a1 = *(const float4*)&As[k][64 + ty * 4];
            float4 b0 = *(const float4*)&Bs[k][tx * 4];
            float4 b1 = *(const float4*)&Bs[k][64 + tx * 4];
            float a[8] = {a0.x, a0.y, a0.z, a0.w, a1.x, a1.y, a1.z, a1.w};
            float b[8] = {b0.x, b0.y, b0.z, b0.w, b1.x, b1.y, b1.z, b1.w};
#pragma unroll
            for (int i = 0; i < 8; i++)
#pragma unroll
                for (int j = 0; j < 8; j++) acc[i][j] = fmaf(a[i], b[j], acc[i][j]);
        }
        __syncthreads();
    }
#pragma unroll
    for (int i = 0; i < 8; i++) {
        int mr = (i < 4) ? (ty * 4 + i) : (64 + ty * 4 + i - 4);
        int m = bm + mr;
        if (m >= M) continue;
#pragma unroll
        for (int j = 0; j < 8; j++) {
            int nc = (j < 4) ? (tx * 4 + j) : (64 + tx * 4 + j - 4);
            int n = bn + nc;
            if (n >= N) continue;
            float v = acc[i][j];
            if (mode >= 1) v += bias[n];
            if (mode == 2) v = fmaxf(v, 0.f);
            C[(size_t)m * N + n] = v;
        }
    }
}

// ---------------- BN finalize (self-zeroing stats) ----------------
__global__ void k_mkscale(float* __restrict__ colsum, float* __restrict__ colsq,
                          const float* __restrict__ g, const float* __restrict__ be,
                          float* __restrict__ scale, float* __restrict__ shift,
                          float invn, int ncols) {
    int c = blockIdx.x * blockDim.x + threadIdx.x;
    if (c >= ncols) return;
    float mean = colsum[c] * invn;
    float var = colsq[c] * invn - mean * mean;
    float sc = g[c] * rsqrtf(var + BN_EPS);
    scale[c] = sc;
    shift[c] = be[c] - mean * sc;
    colsum[c] = 0.f;
    colsq[c] = 0.f;
}

// ---------------- fused pooling ----------------
__global__ void k_gateprep(const float* __restrict__ scale, const float* __restrict__ shift,
                           const float* __restrict__ gw, const float* __restrict__ gb,
                           float* __restrict__ gw2, float* __restrict__ gconst) {
    __shared__ float red[256];
    int tid = threadIdx.x;
    float part = 0.f;
    for (int c = tid; c < 1024; c += 256) {
        gw2[c] = scale[c] * gw[c];
        part += shift[c] * gw[c];
    }
    red[tid] = part;
    __syncthreads();
    for (int o = 128; o > 0; o >>= 1) {
        if (tid < o) red[tid] += red[tid + o];
        __syncthreads();
    }
    if (tid == 0) gconst[0] = red[0] + gb[0];
}
__global__ void k_bounds(const int* __restrict__ batch, int* gs, int* ge) {
    int i = blockIdx.x * blockDim.x + threadIdx.x;
    if (i >= NN) return;
    int b = batch[i];
    atomicMin(&gs[b], i);
    atomicMax(&ge[b], i + 1);
}

#define SGMAX 1024
__global__ void k_pool_gated(const float* __restrict__ x, const float* __restrict__ gw2,
                             const float* __restrict__ gconstp,
                             const float* __restrict__ scale, const float* __restrict__ shift,
                             const int* __restrict__ gs, const int* __restrict__ ge,
                             float* __restrict__ pooled) {
    int g = blockIdx.x;
    int s = gs[g], e = ge[g];
    int tid = threadIdx.x, lane = tid & 31, warp = tid >> 5;
    __shared__ float sgate[SGMAX];
    __shared__ float red[256];
    float gconst = gconstp[0];

    for (int i = s + warp; i < e; i += 8) {
        const float4* xr = (const float4*)(x + (size_t)i * 1024);
        const float4* w4 = (const float4*)gw2;
        float acc = 0.f;
#pragma unroll
        for (int k = 0; k < 8; k++) {
            float4 a = xr[lane + k * 32];
            float4 b = w4[lane + k * 32];
            acc += a.x * b.x + a.y * b.y + a.z * b.z + a.w * b.w;
        }
#pragma unroll
        for (int o = 16; o > 0; o >>= 1) acc += __shfl_down_sync(0xffffffffu, acc, o);
        if (lane == 0 && (i - s) < SGMAX) sgate[i - s] = acc + gconst;
    }
    __syncthreads();

    auto getg = [&](int i) -> float {
        if (i - s < SGMAX) return sgate[i - s];
        float acc = 0.f;
        const float* xr = x + (size_t)i * 1024;
        for (int c = 0; c < 1024; c++) acc += xr[c] * gw2[c];
        return acc + gconst;
    };

    float m = -INFINITY;
    for (int i = s + tid; i < e; i += 256) m = fmaxf(m, getg(i));
    red[tid] = m;
    __syncthreads();
    for (int o = 128; o > 0; o >>= 1) {
        if (tid < o) red[tid] = fmaxf(red[tid], red[tid + o]);
        __syncthreads();
    }
    float gm = red[0];
    __syncthreads();
    float ss = 0.f;
    for (int i = s + tid; i < e; i += 256) ss += expf(getg(i) - gm);
    red[tid] = ss;
    __syncthreads();
    for (int o = 128; o > 0; o >>= 1) {
        if (tid < o) red[tid] += red[tid + o];
        __syncthreads();
    }
    float inv = (e > s) ? 1.0f / red[0] : 0.f;

    int d = tid * 4;
    float4 acc = make_float4(0.f, 0.f, 0.f, 0.f);
    float ws = 0.f;
    for (int i = s; i < e; i++) {
        float w = expf(getg(i) - gm) * inv;
        ws += w;
        float4 v = *(const float4*)&x[(size_t)i * 1024 + d];
        acc.x += w * v.x; acc.y += w * v.y; acc.z += w * v.z; acc.w += w * v.w;
    }
    float4 o;
    o.x = scale[d + 0] * acc.x + shift[d + 0] * ws;
    o.y = scale[d + 1] * acc.y + shift[d + 1] * ws;
    o.z = scale[d + 2] * acc.z + shift[d + 2] * ws;
    o.w = scale[d + 3] * acc.w + shift[d + 3] * ws;
    *(float4*)&pooled[(size_t)g * 1024 + d] = o;
}

// ---------------- host orchestration ----------------
static inline int cdiv(long a, long b) { return (int)((a + b - 1) / b); }

static void gemm_tc(const __nv_bfloat16* Ah, const __nv_bfloat16* Al,
                    const __nv_bfloat16* Bh, const __nv_bfloat16* Bl,
                    const float* bias, float* C,
                    int M, int N, int K, int mode, float* colsum, float* colsq) {
    dim3 grid(N / 128, cdiv(M, 128));
    k_mma_gemm<<<grid, 256, GEMM_SMEM>>>(Ah, Al, Bh, Bl, bias, C, M, N, K, mode, colsum, colsq);
}
static void gemm32(const float* A, const float* B, const float* bias, float* C,
                   int M, int N, int K, int mode) {
    dim3 grid(cdiv(N, 128), cdiv(M, 128));
    k_sgemm128<<<grid, 256>>>(A, B, bias, C, M, N, K, mode);
}

extern "C" void kernel_launch(void* const* d_in, const int* in_sizes, int n_in,
                              void* d_out, int out_size) {
    (void)in_sizes; (void)n_in; (void)out_size;
    const float* x_in  = (const float*)d_in[0];
    const int*   ei    = (const int*)d_in[1];
    const int*   batch = (const int*)d_in[2];
    const float *W[5], *bb[5], *gg[5], *be[5];
    for (int l = 0; l < 5; l++) {
        W[l]  = (const float*)d_in[3 + 4 * l];
        bb[l] = (const float*)d_in[4 + 4 * l];
        gg[l] = (const float*)d_in[5 + 4 * l];
        be[l] = (const float*)d_in[6 + 4 * l];
    }
    const float* gate_W = (const float*)d_in[23];
    const float* gate_b = (const float*)d_in[24];
    const float* fc2_W  = (const float*)d_in[25];
    const float* fc2_b  = (const float*)d_in[26];
    const float* fc3_W  = (const float*)d_in[27];
    const float* fc3_b  = (const float*)d_in[28];
    const float* fc4_W  = (const float*)d_in[29];
    const float* fc4_b  = (const float*)d_in[30];
    float* out = (float*)d_out;

    float *dis, *norm, *bufA, *bufB, *bufC, *colsum, *colsq, *scale, *shift;
    float *pooled, *h2, *h3, *csr_w, *gw2, *gconst;
    __nv_bfloat16 *ah, *al, *wh, *wl;
    int *gs, *ge, *counts, *off, *cursor, *csr_src;
    cudaGetSymbolAddress((void**)&dis,     g_dis);
    cudaGetSymbolAddress((void**)&norm,    g_norm);
    cudaGetSymbolAddress((void**)&counts,  g_counts);
    cudaGetSymbolAddress((void**)&off,     g_off);
    cudaGetSymbolAddress((void**)&cursor,  g_cursor);
    cudaGetSymbolAddress((void**)&csr_src, g_src);
    cudaGetSymbolAddress((void**)&csr_w,   g_w);
    cudaGetSymbolAddress((void**)&bufA,    g_bufA);
    cudaGetSymbolAddress((void**)&bufB,    g_bufB);
    cudaGetSymbolAddress((void**)&bufC,    g_bufC);
    cudaGetSymbolAddress((void**)&ah,      g_ah);
    cudaGetSymbolAddress((void**)&al,      g_al);
    cudaGetSymbolAddress((void**)&wh,      g_wh);
    cudaGetSymbolAddress((void**)&wl,      g_wl);
    cudaGetSymbolAddress((void**)&colsum,  g_colsum);
    cudaGetSymbolAddress((void**)&colsq,   g_colsq);
    cudaGetSymbolAddress((void**)&scale,   g_scale);
    cudaGetSymbolAddress((void**)&shift,   g_shift);
    cudaGetSymbolAddress((void**)&gw2,     g_gw2);
    cudaGetSymbolAddress((void**)&gconst,  g_gconst);
    cudaGetSymbolAddress((void**)&gs,      g_gs);
    cudaGetSymbolAddress((void**)&ge,      g_ge);
    cudaGetSymbolAddress((void**)&pooled,  g_pooled);
    cudaGetSymbolAddress((void**)&h2,      g_h2);
    cudaGetSymbolAddress((void**)&h3,      g_h3);

    cudaFuncSetAttribute(k_mma_gemm, cudaFuncAttributeMaxDynamicSharedMemorySize, GEMM_SMEM);

    const int* row = ei;
    const int* col = ei + NE;

    const size_t wo1 = 0;
    const size_t wo2 = wo1 + (size_t)K1PAD * 1024;
    const size_t wo3 = wo2 + (size_t)1024 * 512;
    const size_t wo4 = wo3 + (size_t)512 * 256;
    const size_t wo5 = wo4 + (size_t)256 * 512;
    const size_t wo6 = wo5 + (size_t)512 * 1024;

    // ---- GCN norm + CSR build ----
    k_filli<<<256, 256>>>(counts, 0, NN);
    k_histc<<<cdiv(NE, 256), 256>>>(col, counts);
    k_disk<<<cdiv(NN, 256), 256>>>(counts, dis);
    k_edge_norm<<<cdiv(NE, 256), 256>>>(row, col, dis, norm);
    k_scan<<<1, 1024>>>(counts, off);
    k_copyi<<<cdiv(NN, 256), 256>>>(off, cursor, NN);
    k_scatter<<<cdiv(NE, 256), 256>>>(row, col, norm, cursor, csr_src, csr_w);

    // ---- weight pre-split ----
    k_split_mat<<<cdiv((long)K1PAD * 1024, 256), 256>>>(W[0], wh + wo1, wl + wo1, NF, K1PAD, 1024);
    k_split_mat<<<cdiv((long)1024 * 512, 256), 256>>>(W[1], wh + wo2, wl + wo2, 1024, 1024, 512);
    k_split_mat<<<cdiv((long)512 * 256, 256), 256>>>(W[2], wh + wo3, wl + wo3, 512, 512, 256);
    k_split_mat<<<cdiv((long)256 * 512, 256), 256>>>(W[3], wh + wo4, wl + wo4, 256, 256, 512);
    k_split_mat<<<cdiv((long)512 * 1024, 256), 256>>>(W[4], wh + wo5, wl + wo5, 512, 512, 1024);
    k_split_mat<<<cdiv((long)1024 * 128, 256), 256>>>(fc2_W, wh + wo6, wl + wo6, 1024, 1024, 128);

    const float invn = 1.0f / NN;

    // ---- Layer 1 ----
    k_prop39<<<2048, dim3(64, 4)>>>(x_in, ah, al, dis, off, csr_src, csr_w);
    gemm_tc(ah, al, wh + wo1, wl + wo1, bb[0], bufB, NN, 1024, K1PAD, 3, colsum, colsq);
    k_mkscale<<<4, 256>>>(colsum, colsq, gg[0], be[0], scale, shift, invn, 1024);
    k_bnsplit<<<cdiv((long)NN * 256, 256), 256>>>((const float4*)bufB, scale, shift, ah, al, 256, NN * 256);

    // ---- Layer 2 ----
    gemm_tc(ah, al, wh + wo2, wl + wo2, nullptr, bufA, NN, 512, 1024, 0, nullptr, nullptr);
    k_prop4<128, 2, 1><<<2048, dim3(128, 2)>>>((const float4*)bufA, (float4*)bufC, nullptr, nullptr,
                                               dis, off, csr_src, csr_w, bb[1], nullptr, nullptr,
                                               colsum, colsq);
    k_mkscale<<<2, 256>>>(colsum, colsq, gg[1], be[1], scale, shift, invn, 512);
    k_bnsplit<<<cdiv((long)NN * 128, 256), 256>>>((const float4*)bufC, scale, shift, ah, al, 128, NN * 128);

    // ---- Layer 3 ----
    gemm_tc(ah, al, wh + wo3, wl + wo3, nullptr, bufA, NN, 256, 512, 0, nullptr, nullptr);
    k_prop4<64, 4, 1><<<2048, dim3(64, 4)>>>((const float4*)bufA, (float4*)bufB, nullptr, nullptr,
                                             dis, off, csr_src, csr_w, bb[2], nullptr, nullptr,
                                             colsum, colsq);
    k_mkscale<<<1, 256>>>(colsum, colsq, gg[2], be[2], scale, shift, invn, 256);

    // ---- Layer 4 ----
    k_prop4<64, 4, 2><<<2048, dim3(64, 4)>>>((const float4*)bufB, nullptr, ah, al,
                                             dis, off, csr_src, csr_w, nullptr, scale, shift,
                                             nullptr, nullptr);
    gemm_tc(ah, al, wh + wo4, wl + wo4, bb[3], bufC, NN, 512, 256, 3, colsum, colsq);
    k_mkscale<<<2, 256>>>(colsum, colsq, gg[3], be[3], scale, shift, invn, 512);

    // ---- Layer 5 ----
    k_prop4<128, 2, 2><<<2048, dim3(128, 2)>>>((const float4*)bufC, nullptr, ah, al,
                                               dis, off, csr_src, csr_w, nullptr, scale, shift,
                                               nullptr, nullptr);
    gemm_tc(ah, al, wh + wo5, wl + wo5, bb[4], bufB, NN, 1024, 512, 3, colsum, colsq);
    k_mkscale<<<4, 256>>>(colsum, colsq, gg[4], be[4], scale, shift, invn, 1024);

    // ---- attentional pooling (BN5 folded in) ----
    k_gateprep<<<1, 256>>>(scale, shift, gate_W, gate_b, gw2, gconst);
    k_filli<<<32, 256>>>(gs, NN, NG);
    k_filli<<<32, 256>>>(ge, 0, NG);
    k_bounds<<<cdiv(NN, 256), 256>>>(batch, gs, ge);
    k_pool_gated<<<NG, 256>>>(bufB, gw2, gconst, scale, shift, gs, ge, pooled);

    // ---- MLP head ----
    k_split_mat<<<cdiv((long)NG * 1024, 256), 256>>>(pooled, ah, al, NG, NG, 1024);
    gemm_tc(ah, al, wh + wo6, wl + wo6, fc2_b, h2, NG, 128, 1024, 2, nullptr, nullptr);
    gemm32(h2, fc3_W, fc3_b, h3, NG, 16, 128, 2);
    gemm32(h3, fc4_W, fc4_b, out, NG, 1, 16, 1);
}

// round 13
// speedup vs baseline: 1.3103x; 1.0140x over previous
#include <cuda_runtime.h>
#include <cuda_bf16.h>
#include <math.h>
#include <stdint.h>

#define NN 100000
#define NE 400000
#define NG 4000
#define NF 39
#define K1PAD 40
#define DMAX 1024
#define BN_EPS 1e-5f
// W1(40x1024)+W2(1024x512)+W3(512x256)+W4(256x512)+W5(512x1024)+fc2(1024x128)
#define WTOT 1482752

// ---------------- static device scratch ----------------
__device__ float g_dis[NN];
__device__ float g_norm[NE];
__device__ int   g_counts[NN];
__device__ int   g_off[NN + 1];
__device__ int   g_cursor[NN];
__device__ int   g_src[NE];
__device__ float g_w[NE];
__device__ float g_bufA[(size_t)NN * DMAX];
__device__ float g_bufB[(size_t)NN * DMAX];
__device__ float g_bufC[(size_t)NN * DMAX];
__device__ __align__(16) __nv_bfloat16 g_ah[(size_t)NN * DMAX];
__device__ __align__(16) __nv_bfloat16 g_al[(size_t)NN * DMAX];
__device__ __align__(16) __nv_bfloat16 g_ah2[(size_t)NN * DMAX];
__device__ __align__(16) __nv_bfloat16 g_al2[(size_t)NN * DMAX];
__device__ __align__(16) __nv_bfloat16 g_wh[WTOT];
__device__ __align__(16) __nv_bfloat16 g_wl[WTOT];
__device__ __align__(16) __nv_bfloat16 g_wsh[1024 * 512];
__device__ __align__(16) __nv_bfloat16 g_wsl[1024 * 512];
__device__ float g_bc[1024];
__device__ float g_colsum[DMAX];
__device__ float g_colsq[DMAX];
__device__ float g_scale[DMAX];
__device__ float g_shift[DMAX];
__device__ float g_gw2[DMAX];
__device__ float g_gconst[1];
__device__ int   g_gs[NG];
__device__ int   g_ge[NG];
__device__ float g_pooled[(size_t)NG * DMAX];
__device__ float g_h2[NG * 128];
__device__ float g_h3[NG * 16];

// ---------------- utility ----------------
__global__ void k_filli(int* p, int v, int n) {
    for (int i = blockIdx.x * blockDim.x + threadIdx.x; i < n; i += gridDim.x * blockDim.x)
        p[i] = v;
}
__global__ void k_copyi(const int* __restrict__ a, int* __restrict__ b, int n) {
    for (int i = blockIdx.x * blockDim.x + threadIdx.x; i < n; i += gridDim.x * blockDim.x)
        b[i] = a[i];
}

__device__ __forceinline__ void splitf(float v, __nv_bfloat16& h, __nv_bfloat16& l) {
    h = __float2bfloat16(v);
    l = __float2bfloat16(v - __bfloat162float(h));
}

// ---------------- CSR build ----------------
__global__ void k_histc(const int* __restrict__ col, int* counts) {
    int e = blockIdx.x * blockDim.x + threadIdx.x;
    if (e < NE) atomicAdd(&counts[col[e]], 1);
}
__global__ void k_disk(const int* __restrict__ counts, float* dis) {
    int i = blockIdx.x * blockDim.x + threadIdx.x;
    if (i < NN) dis[i] = rsqrtf((float)counts[i] + 1.0f);
}
__global__ void k_edge_norm(const int* __restrict__ row, const int* __restrict__ col,
                            const float* __restrict__ dis, float* __restrict__ norm) {
    int e = blockIdx.x * blockDim.x + threadIdx.x;
    if (e < NE) norm[e] = dis[row[e]] * dis[col[e]];
}
__global__ void k_scan(const int* __restrict__ counts, int* __restrict__ off) {
    __shared__ int sh[1024];
    __shared__ int carry_s;
    int t = threadIdx.x;
    if (t == 0) { carry_s = 0; off[0] = 0; }
    __syncthreads();
    for (int base = 0; base < NN; base += 1024) {
        int i = base + t;
        int v = (i < NN) ? counts[i] : 0;
        sh[t] = v;
        __syncthreads();
        for (int o = 1; o < 1024; o <<= 1) {
            int add = (t >= o) ? sh[t - o] : 0;
            __syncthreads();
            sh[t] += add;
            __syncthreads();
        }
        int carry = carry_s;
        if (i < NN) off[i + 1] = carry + sh[t];
        __syncthreads();
        if (t == 1023) carry_s = carry + sh[1023];
        __syncthreads();
    }
}
__global__ void k_scatter(const int* __restrict__ row, const int* __restrict__ col,
                          const float* __restrict__ norm, int* cursor,
                          int* __restrict__ csr_src, float* __restrict__ csr_w) {
    int e = blockIdx.x * blockDim.x + threadIdx.x;
    if (e >= NE) return;
    int c = col[e];
    int p = atomicAdd(&cursor[c], 1);
    csr_src[p] = row[e];
    csr_w[p] = norm[e];
}

// ---------------- split / transform passes ----------------
__global__ void k_split_mat(const float* __restrict__ src, __nv_bfloat16* __restrict__ oh,
                            __nv_bfloat16* __restrict__ ol, int k, int kpad, int n) {
    int idx = blockIdx.x * blockDim.x + threadIdx.x;
    if (idx >= kpad * n) return;
    int r = idx / n, c = idx - r * n;
    float v = (r < k) ? src[(size_t)r * n + c] : 0.f;
    __nv_bfloat16 h, l;
    splitf(v, h, l);
    oh[idx] = h;
    ol[idx] = l;
}
// W'[k,n] = split(sc[k]*W[k,n]); bc[n] = sum_k sh[k]*W[k,n]
// grid.x = N/32, block (32,8)
__global__ void k_wtrans(const float* __restrict__ W, const float* __restrict__ sc,
                         const float* __restrict__ sh,
                         __nv_bfloat16* __restrict__ wh, __nv_bfloat16* __restrict__ wl,
                         float* __restrict__ bc, int K, int N) {
    int c = blockIdx.x * 32 + threadIdx.x;
    float acc = 0.f;
    for (int k = threadIdx.y; k < K; k += 8) {
        float v = W[(size_t)k * N + c];
        __nv_bfloat16 h, l;
        splitf(sc[k] * v, h, l);
        wh[(size_t)k * N + c] = h;
        wl[(size_t)k * N + c] = l;
        acc = fmaf(sh[k], v, acc);
    }
    __shared__ float red[8][33];
    red[threadIdx.y][threadIdx.x] = acc;
    __syncthreads();
    if (threadIdx.y == 0) {
        float t = 0.f;
#pragma unroll
        for (int y = 0; y < 8; y++) t += red[y][threadIdx.x];
        bc[c] = t;
    }
}

// ---------------- CSR gather propagate ----------------
// MODE 1: acc = relu(agg + wsum*bc + bias); fp32 out + stats
// MODE 2: acc = insc*agg + insh*wsum; split bf16 out (BN-fold, no stats)
// MODE 3: acc = relu(agg + wsum*bc + bias); split bf16 out + stats
template <int DIMV, int NPB, int MODE>
__global__ void k_prop4(const float4* __restrict__ in, float4* __restrict__ out,
                        __nv_bfloat16* __restrict__ outh, __nv_bfloat16* __restrict__ outl,
                        const float* __restrict__ dis,
                        const int* __restrict__ off, const int* __restrict__ src,
                        const float* __restrict__ w,
                        const float* __restrict__ bias, const float* __restrict__ bc,
                        const float* __restrict__ insc, const float* __restrict__ insh,
                        float* __restrict__ colsum, float* __restrict__ colsq) {
    const int DIM = DIMV * 4;
    int x = threadIdx.x;
    int yy = threadIdx.y;
    float4 bb = make_float4(0.f, 0.f, 0.f, 0.f);
    float4 bc4 = make_float4(0.f, 0.f, 0.f, 0.f);
    float4 sc4 = make_float4(0.f, 0.f, 0.f, 0.f), sh4 = sc4;
    float4 s1 = make_float4(0.f, 0.f, 0.f, 0.f);
    float4 s2 = make_float4(0.f, 0.f, 0.f, 0.f);
    if (MODE == 1 || MODE == 3) {
        bb = *(const float4*)&bias[x * 4];
        bc4 = *(const float4*)&bc[x * 4];
    }
    if (MODE == 2) {
        sc4 = *(const float4*)&insc[x * 4];
        sh4 = *(const float4*)&insh[x * 4];
    }
    for (int n = blockIdx.x * NPB + yy; n < NN; n += gridDim.x * NPB) {
        float d = dis[n];
        float sw = d * d;
        float4 v = in[(size_t)n * DIMV + x];
        float4 acc = make_float4(sw * v.x, sw * v.y, sw * v.z, sw * v.w);
        float wsum = sw;
        int e1 = __ldg(&off[n + 1]);
        for (int e = __ldg(&off[n]); e < e1; e++) {
            int sr = __ldg(&src[e]);
            float ww = __ldg(&w[e]);
            wsum += ww;
            float4 u = in[(size_t)sr * DIMV + x];
            acc.x = fmaf(ww, u.x, acc.x);
            acc.y = fmaf(ww, u.y, acc.y);
            acc.z = fmaf(ww, u.z, acc.z);
            acc.w = fmaf(ww, u.w, acc.w);
        }
        if (MODE == 1 || MODE == 3) {
            acc.x = fmaxf(acc.x + wsum * bc4.x + bb.x, 0.f);
            acc.y = fmaxf(acc.y + wsum * bc4.y + bb.y, 0.f);
            acc.z = fmaxf(acc.z + wsum * bc4.z + bb.z, 0.f);
            acc.w = fmaxf(acc.w + wsum * bc4.w + bb.w, 0.f);
            s1.x += acc.x; s1.y += acc.y; s1.z += acc.z; s1.w += acc.w;
            s2.x += acc.x * acc.x; s2.y += acc.y * acc.y;
            s2.z += acc.z * acc.z; s2.w += acc.w * acc.w;
            if (MODE == 1) {
                out[(size_t)n * DIMV + x] = acc;
            } else {
                __nv_bfloat16 h0, l0, h1, l1, h2, l2, h3, l3;
                splitf(acc.x, h0, l0); splitf(acc.y, h1, l1);
                splitf(acc.z, h2, l2); splitf(acc.w, h3, l3);
                uint2 hv, lv;
                hv.x = ((uint32_t)__bfloat16_as_ushort(h1) << 16) | __bfloat16_as_ushort(h0);
                hv.y = ((uint32_t)__bfloat16_as_ushort(h3) << 16) | __bfloat16_as_ushort(h2);
                lv.x = ((uint32_t)__bfloat16_as_ushort(l1) << 16) | __bfloat16_as_ushort(l0);
                lv.y = ((uint32_t)__bfloat16_as_ushort(l3) << 16) | __bfloat16_as_ushort(l2);
                *(uint2*)&outh[(size_t)n * DIM + x * 4] = hv;
                *(uint2*)&outl[(size_t)n * DIM + x * 4] = lv;
            }
        } else {  // MODE 2
            acc.x = sc4.x * acc.x + sh4.x * wsum;
            acc.y = sc4.y * acc.y + sh4.y * wsum;
            acc.z = sc4.z * acc.z + sh4.z * wsum;
            acc.w = sc4.w * acc.w + sh4.w * wsum;
            __nv_bfloat16 h0, l0, h1, l1, h2, l2, h3, l3;
            splitf(acc.x, h0, l0); splitf(acc.y, h1, l1);
            splitf(acc.z, h2, l2); splitf(acc.w, h3, l3);
            uint2 hv, lv;
            hv.x = ((uint32_t)__bfloat16_as_ushort(h1) << 16) | __bfloat16_as_ushort(h0);
            hv.y = ((uint32_t)__bfloat16_as_ushort(h3) << 16) | __bfloat16_as_ushort(h2);
            lv.x = ((uint32_t)__bfloat16_as_ushort(l1) << 16) | __bfloat16_as_ushort(l0);
            lv.y = ((uint32_t)__bfloat16_as_ushort(l3) << 16) | __bfloat16_as_ushort(l2);
            *(uint2*)&outh[(size_t)n * DIM + x * 4] = hv;
            *(uint2*)&outl[(size_t)n * DIM + x * 4] = lv;
        }
    }
    if (MODE == 1 || MODE == 3) {
        int c = x * 4;
        atomicAdd(&colsum[c + 0], s1.x);
        atomicAdd(&colsum[c + 1], s1.y);
        atomicAdd(&colsum[c + 2], s1.z);
        atomicAdd(&colsum[c + 3], s1.w);
        atomicAdd(&colsq[c + 0], s2.x);
        atomicAdd(&colsq[c + 1], s2.y);
        atomicAdd(&colsq[c + 2], s2.z);
        atomicAdd(&colsq[c + 3], s2.w);
    }
}

__global__ void k_prop39(const float* __restrict__ in,
                         __nv_bfloat16* __restrict__ oh, __nv_bfloat16* __restrict__ ol,
                         const float* __restrict__ dis,
                         const int* __restrict__ off, const int* __restrict__ src,
                         const float* __restrict__ w) {
    int x = threadIdx.x;
    if (x >= K1PAD) return;
    int yy = threadIdx.y;
    __nv_bfloat16 z = __float2bfloat16(0.f);
    for (int n = blockIdx.x * 4 + yy; n < NN; n += gridDim.x * 4) {
        if (x >= NF) {
            oh[(size_t)n * K1PAD + x] = z;
            ol[(size_t)n * K1PAD + x] = z;
            continue;
        }
        float d = dis[n];
        float acc = d * d * in[(size_t)n * NF + x];
        int e1 = __ldg(&off[n + 1]);
        for (int e = __ldg(&off[n]); e < e1; e++)
            acc = fmaf(__ldg(&w[e]), in[(size_t)__ldg(&src[e]) * NF + x], acc);
        __nv_bfloat16 h, l;
        splitf(acc, h, l);
        oh[(size_t)n * K1PAD + x] = h;
        ol[(size_t)n * K1PAD + x] = l;
    }
}

// ======== bf16 3-product tensor-core GEMM (2-stage cp.async, 2 CTA/SM) =========
__device__ __forceinline__ void ldsm4(uint32_t* r, const void* p) {
    uint32_t a = (uint32_t)__cvta_generic_to_shared(p);
    asm volatile("ldmatrix.sync.aligned.m8n8.x4.shared.b16 {%0,%1,%2,%3}, [%4];"
                 : "=r"(r[0]), "=r"(r[1]), "=r"(r[2]), "=r"(r[3]) : "r"(a));
}
__device__ __forceinline__ void ldsm4t(uint32_t* r, const void* p) {
    uint32_t a = (uint32_t)__cvta_generic_to_shared(p);
    asm volatile("ldmatrix.sync.aligned.m8n8.x4.trans.shared.b16 {%0,%1,%2,%3}, [%4];"
                 : "=r"(r[0]), "=r"(r[1]), "=r"(r[2]), "=r"(r[3]) : "r"(a));
}
__device__ __forceinline__ void mma16816(float* d, const uint32_t* a, const uint32_t* b) {
    asm volatile("mma.sync.aligned.m16n8k16.row.col.f32.bf16.bf16.f32 "
                 "{%0,%1,%2,%3}, {%4,%5,%6,%7}, {%8,%9}, {%0,%1,%2,%3};"
                 : "+f"(d[0]), "+f"(d[1]), "+f"(d[2]), "+f"(d[3])
                 : "r"(a[0]), "r"(a[1]), "r"(a[2]), "r"(a[3]),
                   "r"(b[0]), "r"(b[1]));
}
__device__ __forceinline__ void cpa16(uint32_t saddr, const void* g, int sz) {
    asm volatile("cp.async.cg.shared.global [%0], [%1], 16, %2;"
                 :: "r"(saddr), "l"(g), "r"(sz));
}
__device__ __forceinline__ void cpa_commit() {
    asm volatile("cp.async.commit_group;");
}
template <int N>
__device__ __forceinline__ void cpa_wait() {
    asm volatile("cp.async.wait_group %0;" :: "n"(N));
}

#define APAD 40
#define BPAD 136
#define ABUF (128 * APAD)
#define BBUF (32 * BPAD)
#define GEMM_SMEM (2 * (2 * ABUF + 2 * BBUF) * 2 + 256 * 4)

// mode: 0 raw fp32 | 1 +bias | 2 +bias+relu | 3 +bias+relu+stats fp32 | 4 +bias+relu+stats split-bf16
__global__ void __launch_bounds__(256, 2)
k_mma_gemm(const __nv_bfloat16* __restrict__ Ah, const __nv_bfloat16* __restrict__ Al,
           const __nv_bfloat16* __restrict__ Bh, const __nv_bfloat16* __restrict__ Bl,
           const float* __restrict__ bias, float* __restrict__ C,
           __nv_bfloat16* __restrict__ OH, __nv_bfloat16* __restrict__ OL,
           int M, int N, int K, int mode,
           float* __restrict__ colsum, float* __restrict__ colsq) {
    extern __shared__ __align__(16) char dsm[];
    __nv_bfloat16* Ahs = (__nv_bfloat16*)dsm;
    __nv_bfloat16* Als = Ahs + 2 * ABUF;
    __nv_bfloat16* Bhs = Als + 2 * ABUF;
    __nv_bfloat16* Bls = Bhs + 2 * BBUF;
    float* s_sum = (float*)(Bls + 2 * BBUF);
    float* s_sq = s_sum + 128;

    const int tid = threadIdx.x;
    const int lane = tid & 31;
    const int warp = tid >> 5;
    const int wm = warp & 3;
    const int wn = warp >> 2;
    const int bm = blockIdx.y * 128;
    const int bn = blockIdx.x * 128;

    float acc[2][8][4];
#pragma unroll
    for (int i = 0; i < 2; i++)
#pragma unroll
        for (int j = 0; j < 8; j++)
#pragma unroll
            for (int c = 0; c < 4; c++) acc[i][j][c] = 0.f;

    const uint32_t sAh = (uint32_t)__cvta_generic_to_shared(Ahs);
    const uint32_t sAl = (uint32_t)__cvta_generic_to_shared(Als);
    const uint32_t sBh = (uint32_t)__cvta_generic_to_shared(Bhs);
    const uint32_t sBl = (uint32_t)__cvta_generic_to_shared(Bls);

    auto prefetch = [&](int k0, int buf) {
        uint32_t aOff = buf * ABUF * 2;
        uint32_t bOff = buf * BBUF * 2;
#pragma unroll
        for (int it = 0; it < 2; it++) {
            int idx = tid + it * 256;
            int r = idx >> 2, q = idx & 3;
            int gm = bm + r, gk = k0 + q * 8;
            int sz = (gm < M && gk < K) ? 16 : 0;
            int gmc = (gm < M) ? gm : 0;
            int gkc = (gk < K) ? gk : 0;
            uint32_t d = (uint32_t)(r * APAD + q * 8) * 2;
            cpa16(sAh + aOff + d, &Ah[(size_t)gmc * K + gkc], sz);
            cpa16(sAl + aOff + d, &Al[(size_t)gmc * K + gkc], sz);
        }
#pragma unroll
        for (int it = 0; it < 2; it++) {
            int idx = tid + it * 256;
            int r = idx >> 4, q = idx & 15;
            int gk = k0 + r, gn = bn + q * 8;
            int sz = (gk < K) ? 16 : 0;
            int gkc = (gk < K) ? gk : 0;
            uint32_t d = (uint32_t)(r * BPAD + q * 8) * 2;
            cpa16(sBh + bOff + d, &Bh[(size_t)gkc * N + gn], sz);
            cpa16(sBl + bOff + d, &Bl[(size_t)gkc * N + gn], sz);
        }
    };

    const int nk = (K + 31) >> 5;
    prefetch(0, 0);
    cpa_commit();

    for (int kt = 0; kt < nk; kt++) {
        const int cur = kt & 1;
        if (kt + 1 < nk) {
            prefetch((kt + 1) << 5, cur ^ 1);
            cpa_commit();
            cpa_wait<1>();
        } else {
            cpa_wait<0>();
        }
        __syncthreads();

        const __nv_bfloat16* cAh = Ahs + cur * ABUF;
        const __nv_bfloat16* cAl = Als + cur * ABUF;
        const __nv_bfloat16* cBh = Bhs + cur * BBUF;
        const __nv_bfloat16* cBl = Bls + cur * BBUF;

#pragma unroll
        for (int ks = 0; ks < 32; ks += 16) {
            uint32_t ah[2][4], al[2][4];
#pragma unroll
            for (int i = 0; i < 2; i++) {
                int rowa = wm * 32 + i * 16 + (lane & 15);
                int kc = ks + ((lane >> 4) << 3);
                ldsm4(ah[i], &cAh[rowa * APAD + kc]);
                ldsm4(al[i], &cAl[rowa * APAD + kc]);
            }
#pragma unroll
            for (int nh = 0; nh < 2; nh++) {
                uint32_t bh[2][4], bl[2][4];
#pragma unroll
                for (int j2 = 0; j2 < 2; j2++) {
                    int rowb = ks + (lane & 15);
                    int nc = wn * 64 + (nh * 2 + j2) * 16 + ((lane >> 4) << 3);
                    ldsm4t(bh[j2], &cBh[rowb * BPAD + nc]);
                    ldsm4t(bl[j2], &cBl[rowb * BPAD + nc]);
                }
#pragma unroll
                for (int i = 0; i < 2; i++)
#pragma unroll
                    for (int j = 0; j < 4; j++)
                        mma16816(acc[i][nh * 4 + j], ah[i], &bh[j >> 1][(j & 1) * 2]);
#pragma unroll
                for (int i = 0; i < 2; i++)
#pragma unroll
                    for (int j = 0; j < 4; j++)
                        mma16816(acc[i][nh * 4 + j], ah[i], &bl[j >> 1][(j & 1) * 2]);
#pragma unroll
                for (int i = 0; i < 2; i++)
#pragma unroll
                    for (int j = 0; j < 4; j++)
                        mma16816(acc[i][nh * 4 + j], al[i], &bh[j >> 1][(j & 1) * 2]);
            }
        }
        __syncthreads();
    }

    // ---- epilogue ----
    if (mode >= 3) {
        if (tid < 128) { s_sum[tid] = 0.f; s_sq[tid] = 0.f; }
        __syncthreads();
    }
    float csum[8][2], csq[8][2];
#pragma unroll
    for (int j = 0; j < 8; j++) { csum[j][0] = csum[j][1] = 0.f; csq[j][0] = csq[j][1] = 0.f; }

#pragma unroll
    for (int i = 0; i < 2; i++) {
        int r0 = bm + wm * 32 + i * 16 + (lane >> 2);
#pragma unroll
        for (int j = 0; j < 8; j++) {
            int nh = j >> 2, jj = j & 3;
            int cc = bn + wn * 64 + (nh * 2 + (jj >> 1)) * 16 + (jj & 1) * 8 + (lane & 3) * 2;
            float b0 = 0.f, b1 = 0.f;
            if (mode >= 1) { b0 = bias[cc]; b1 = bias[cc + 1]; }
            float v0 = acc[i][j][0] + b0, v1 = acc[i][j][1] + b1;
            float v2 = acc[i][j][2] + b0, v3 = acc[i][j][3] + b1;
            if (mode >= 2) {
                v0 = fmaxf(v0, 0.f); v1 = fmaxf(v1, 0.f);
                v2 = fmaxf(v2, 0.f); v3 = fmaxf(v3, 0.f);
            }
            if (r0 < M) {
                if (mode == 4) {
                    __nv_bfloat16 h0, l0, h1, l1;
                    splitf(v0, h0, l0); splitf(v1, h1, l1);
                    *(uint32_t*)&OH[(size_t)r0 * N + cc] =
                        ((uint32_t)__bfloat16_as_ushort(h1) << 16) | __bfloat16_as_ushort(h0);
                    *(uint32_t*)&OL[(size_t)r0 * N + cc] =
                        ((uint32_t)__bfloat16_as_ushort(l1) << 16) | __bfloat16_as_ushort(l0);
                } else {
                    *(float2*)&C[(size_t)r0 * N + cc] = make_float2(v0, v1);
                }
                if (mode >= 3) { csum[j][0] += v0; csum[j][1] += v1; csq[j][0] += v0 * v0; csq[j][1] += v1 * v1; }
            }
            if (r0 + 8 < M) {
                if (mode == 4) {
                    __nv_bfloat16 h2, l2, h3, l3;
                    splitf(v2, h2, l2); splitf(v3, h3, l3);
                    *(uint32_t*)&OH[(size_t)(r0 + 8) * N + cc] =
                        ((uint32_t)__bfloat16_as_ushort(h3) << 16) | __bfloat16_as_ushort(h2);
                    *(uint32_t*)&OL[(size_t)(r0 + 8) * N + cc] =
                        ((uint32_t)__bfloat16_as_ushort(l3) << 16) | __bfloat16_as_ushort(l2);
                } else {
                    *(float2*)&C[(size_t)(r0 + 8) * N + cc] = make_float2(v2, v3);
                }
                if (mode >= 3) { csum[j][0] += v2; csum[j][1] += v3; csq[j][0] += v2 * v2; csq[j][1] += v3 * v3; }
            }
        }
    }
    if (mode >= 3) {
#pragma unroll
        for (int j = 0; j < 8; j++) {
            int nh = j >> 2, jj = j & 3;
            int nl = wn * 64 + (nh * 2 + (jj >> 1)) * 16 + (jj & 1) * 8 + (lane & 3) * 2;
            atomicAdd(&s_sum[nl], csum[j][0]);
            atomicAdd(&s_sum[nl + 1], csum[j][1]);
            atomicAdd(&s_sq[nl], csq[j][0]);
            atomicAdd(&s_sq[nl + 1], csq[j][1]);
        }
        __syncthreads();
        if (tid < 128) {
            atomicAdd(&colsum[bn + tid], s_sum[tid]);
            atomicAdd(&colsq[bn + tid], s_sq[tid]);
        }
    }
}

// ---------------- fp32 SGEMM (small head GEMMs) --------------------
__global__ void __launch_bounds__(256, 2)
k_sgemm128(const float* __restrict__ A, const float* __restrict__ B,
           const float* __restrict__ bias, float* __restrict__ C,
           int M, int N, int K, int mode) {
    __shared__ float As[8][132];
    __shared__ float Bs[8][132];
    const int bm = blockIdx.y * 128;
    const int bn = blockIdx.x * 128;
    const int tid = threadIdx.x;
    const int tx = tid & 15, ty = tid >> 4;
    const bool vecK = (K & 3) == 0;
    const bool vecN = (N & 3) == 0;

    float acc[8][8];
#pragma unroll
    for (int i = 0; i < 8; i++)
#pragma unroll
        for (int j = 0; j < 8; j++) acc[i][j] = 0.f;

    const int arow = tid >> 1, ah = tid & 1;
    const int bk = tid >> 5, bn4 = (tid & 31) * 4;

    for (int k0 = 0; k0 < K; k0 += 8) {
        {
            int gm = bm + arow;
            float av[4];
            if (vecK && gm < M && k0 + ah * 4 + 3 < K) {
                float4 v = *(const float4*)&A[(size_t)gm * K + k0 + ah * 4];
                av[0] = v.x; av[1] = v.y; av[2] = v.z; av[3] = v.w;
            } else {
#pragma unroll
                for (int j = 0; j < 4; j++)
                    av[j] = (gm < M && k0 + ah * 4 + j < K)
                                ? A[(size_t)gm * K + k0 + ah * 4 + j] : 0.f;
            }
#pragma unroll
            for (int j = 0; j < 4; j++) As[ah * 4 + j][arow] = av[j];
        }
        {
            float4 v;
            if (vecN && k0 + bk < K && bn + bn4 + 3 < N) {
                v = *(const float4*)&B[(size_t)(k0 + bk) * N + bn + bn4];
            } else {
                float bv[4];
#pragma unroll
                for (int j = 0; j < 4; j++)
                    bv[j] = (k0 + bk < K && bn + bn4 + j < N)
                                ? B[(size_t)(k0 + bk) * N + bn + bn4 + j] : 0.f;
                v = make_float4(bv[0], bv[1], bv[2], bv[3]);
            }
            *(float4*)&Bs[bk][bn4] = v;
        }
        __syncthreads();
#pragma unroll
        for (int k = 0; k < 8; k++) {
            float4 a0 = *(const float4*)&As[k][ty * 4];
            float4 a1 = *(const float4*)&As[k][64 + ty * 4];
            float4 b0 = *(const float4*)&Bs[k][tx * 4];
            float4 b1 = *(const float4*)&Bs[k][64 + tx * 4];
            float a[8] = {a0.x, a0.y, a0.z, a0.w, a1.x, a1.y, a1.z, a1.w};
            float b[8] = {b0.x, b0.y, b0.z, b0.w, b1.x, b1.y, b1.z, b1.w};
#pragma unroll
            for (int i = 0; i < 8; i++)
#pragma unroll
                for (int j = 0; j < 8; j++) acc[i][j] = fmaf(a[i], b[j], acc[i][j]);
        }
        __syncthreads();
    }
#pragma unroll
    for (int i = 0; i < 8; i++) {
        int mr = (i < 4) ? (ty * 4 + i) : (64 + ty * 4 + i - 4);
        int m = bm + mr;
        if (m >= M) continue;
#pragma unroll
        for (int j = 0; j < 8; j++) {
            int nc = (j < 4) ? (tx * 4 + j) : (64 + tx * 4 + j - 4);
            int n = bn + nc;
            if (n >= N) continue;
            float v = acc[i][j];
            if (mode >= 1) v += bias[n];
            if (mode == 2) v = fmaxf(v, 0.f);
            C[(size_t)m * N + n] = v;
        }
    }
}

// ---------------- BN finalize (self-zeroing stats) ----------------
__global__ void k_mkscale(float* __restrict__ colsum, float* __restrict__ colsq,
                          const float* __restrict__ g, const float* __restrict__ be,
                          float* __restrict__ scale, float* __restrict__ shift,
                          float invn, int ncols) {
    int c = blockIdx.x * blockDim.x + threadIdx.x;
    if (c >= ncols) return;
    float mean = colsum[c] * invn;
    float var = colsq[c] * invn - mean * mean;
    float sc = g[c] * rsqrtf(var + BN_EPS);
    scale[c] = sc;
    shift[c] = be[c] - mean * sc;
    colsum[c] = 0.f;
    colsq[c] = 0.f;
}

// ---------------- fused pooling ----------------
__global__ void k_gateprep(const float* __restrict__ scale, const float* __restrict__ shift,
                           const float* __restrict__ gw, const float* __restrict__ gb,
                           float* __restrict__ gw2, float* __restrict__ gconst) {
    __shared__ float red[256];
    int tid = threadIdx.x;
    float part = 0.f;
    for (int c = tid; c < 1024; c += 256) {
        gw2[c] = scale[c] * gw[c];
        part += shift[c] * gw[c];
    }
    red[tid] = part;
    __syncthreads();
    for (int o = 128; o > 0; o >>= 1) {
        if (tid < o) red[tid] += red[tid + o];
        __syncthreads();
    }
    if (tid == 0) gconst[0] = red[0] + gb[0];
}
__global__ void k_bounds(const int* __restrict__ batch, int* gs, int* ge) {
    int i = blockIdx.x * blockDim.x + threadIdx.x;
    if (i >= NN) return;
    int b = batch[i];
    atomicMin(&gs[b], i);
    atomicMax(&ge[b], i + 1);
}

#define SGMAX 1024
__global__ void k_pool_gated(const float* __restrict__ x, const float* __restrict__ gw2,
                             const float* __restrict__ gconstp,
                             const float* __restrict__ scale, const float* __restrict__ shift,
                             const int* __restrict__ gs, const int* __restrict__ ge,
                             float* __restrict__ pooled) {
    int g = blockIdx.x;
    int s = gs[g], e = ge[g];
    int tid = threadIdx.x, lane = tid & 31, warp = tid >> 5;
    __shared__ float sgate[SGMAX];
    __shared__ float red[256];
    float gconst = gconstp[0];

    for (int i = s + warp; i < e; i += 8) {
        const float4* xr = (const float4*)(x + (size_t)i * 1024);
        const float4* w4 = (const float4*)gw2;
        float acc = 0.f;
#pragma unroll
        for (int k = 0; k < 8; k++) {
            float4 a = xr[lane + k * 32];
            float4 b = w4[lane + k * 32];
            acc += a.x * b.x + a.y * b.y + a.z * b.z + a.w * b.w;
        }
#pragma unroll
        for (int o = 16; o > 0; o >>= 1) acc += __shfl_down_sync(0xffffffffu, acc, o);
        if (lane == 0 && (i - s) < SGMAX) sgate[i - s] = acc + gconst;
    }
    __syncthreads();

    auto getg = [&](int i) -> float {
        if (i - s < SGMAX) return sgate[i - s];
        float acc = 0.f;
        const float* xr = x + (size_t)i * 1024;
        for (int c = 0; c < 1024; c++) acc += xr[c] * gw2[c];
        return acc + gconst;
    };

    float m = -INFINITY;
    for (int i = s + tid; i < e; i += 256) m = fmaxf(m, getg(i));
    red[tid] = m;
    __syncthreads();
    for (int o = 128; o > 0; o >>= 1) {
        if (tid < o) red[tid] = fmaxf(red[tid], red[tid + o]);
        __syncthreads();
    }
    float gm = red[0];
    __syncthreads();
    float ss = 0.f;
    for (int i = s + tid; i < e; i += 256) ss += expf(getg(i) - gm);
    red[tid] = ss;
    __syncthreads();
    for (int o = 128; o > 0; o >>= 1) {
        if (tid < o) red[tid] += red[tid + o];
        __syncthreads();
    }
    float inv = (e > s) ? 1.0f / red[0] : 0.f;

    int d = tid * 4;
    float4 acc = make_float4(0.f, 0.f, 0.f, 0.f);
    float ws = 0.f;
    for (int i = s; i < e; i++) {
        float w = expf(getg(i) - gm) * inv;
        ws += w;
        float4 v = *(const float4*)&x[(size_t)i * 1024 + d];
        acc.x += w * v.x; acc.y += w * v.y; acc.z += w * v.z; acc.w += w * v.w;
    }
    float4 o;
    o.x = scale[d + 0] * acc.x + shift[d + 0] * ws;
    o.y = scale[d + 1] * acc.y + shift[d + 1] * ws;
    o.z = scale[d + 2] * acc.z + shift[d + 2] * ws;
    o.w = scale[d + 3] * acc.w + shift[d + 3] * ws;
    *(float4*)&pooled[(size_t)g * 1024 + d] = o;
}

// ---------------- host orchestration ----------------
static inline int cdiv(long a, long b) { return (int)((a + b - 1) / b); }

static void gemm_tc(const __nv_bfloat16* Ah, const __nv_bfloat16* Al,
                    const __nv_bfloat16* Bh, const __nv_bfloat16* Bl,
                    const float* bias, float* C,
                    __nv_bfloat16* OH, __nv_bfloat16* OL,
                    int M, int N, int K, int mode, float* colsum, float* colsq) {
    dim3 grid(N / 128, cdiv(M, 128));
    k_mma_gemm<<<grid, 256, GEMM_SMEM>>>(Ah, Al, Bh, Bl, bias, C, OH, OL, M, N, K, mode,
                                         colsum, colsq);
}
static void gemm32(const float* A, const float* B, const float* bias, float* C,
                   int M, int N, int K, int mode) {
    dim3 grid(cdiv(N, 128), cdiv(M, 128));
    k_sgemm128<<<grid, 256>>>(A, B, bias, C, M, N, K, mode);
}

extern "C" void kernel_launch(void* const* d_in, const int* in_sizes, int n_in,
                              void* d_out, int out_size) {
    (void)in_sizes; (void)n_in; (void)out_size;
    const float* x_in  = (const float*)d_in[0];
    const int*   ei    = (const int*)d_in[1];
    const int*   batch = (const int*)d_in[2];
    const float *W[5], *bb[5], *gg[5], *be[5];
    for (int l = 0; l < 5; l++) {
        W[l]  = (const float*)d_in[3 + 4 * l];
        bb[l] = (const float*)d_in[4 + 4 * l];
        gg[l] = (const float*)d_in[5 + 4 * l];
        be[l] = (const float*)d_in[6 + 4 * l];
    }
    const float* gate_W = (const float*)d_in[23];
    const float* gate_b = (const float*)d_in[24];
    const float* fc2_W  = (const float*)d_in[25];
    const float* fc2_b  = (const float*)d_in[26];
    const float* fc3_W  = (const float*)d_in[27];
    const float* fc3_b  = (const float*)d_in[28];
    const float* fc4_W  = (const float*)d_in[29];
    const float* fc4_b  = (const float*)d_in[30];
    float* out = (float*)d_out;

    float *dis, *norm, *bufA, *bufB, *bufC, *colsum, *colsq, *scale, *shift;
    float *pooled, *h2, *h3, *csr_w, *gw2, *gconst, *bc;
    __nv_bfloat16 *ah, *al, *ah2, *al2, *wh, *wl, *wsh, *wsl;
    int *gs, *ge, *counts, *off, *cursor, *csr_src;
    cudaGetSymbolAddress((void**)&dis,     g_dis);
    cudaGetSymbolAddress((void**)&norm,    g_norm);
    cudaGetSymbolAddress((void**)&counts,  g_counts);
    cudaGetSymbolAddress((void**)&off,     g_off);
    cudaGetSymbolAddress((void**)&cursor,  g_cursor);
    cudaGetSymbolAddress((void**)&csr_src, g_src);
    cudaGetSymbolAddress((void**)&csr_w,   g_w);
    cudaGetSymbolAddress((void**)&bufA,    g_bufA);
    cudaGetSymbolAddress((void**)&bufB,    g_bufB);
    cudaGetSymbolAddress((void**)&bufC,    g_bufC);
    cudaGetSymbolAddress((void**)&ah,      g_ah);
    cudaGetSymbolAddress((void**)&al,      g_al);
    cudaGetSymbolAddress((void**)&ah2,     g_ah2);
    cudaGetSymbolAddress((void**)&al2,     g_al2);
    cudaGetSymbolAddress((void**)&wh,      g_wh);
    cudaGetSymbolAddress((void**)&wl,      g_wl);
    cudaGetSymbolAddress((void**)&wsh,     g_wsh);
    cudaGetSymbolAddress((void**)&wsl,     g_wsl);
    cudaGetSymbolAddress((void**)&bc,      g_bc);
    cudaGetSymbolAddress((void**)&colsum,  g_colsum);
    cudaGetSymbolAddress((void**)&colsq,   g_colsq);
    cudaGetSymbolAddress((void**)&scale,   g_scale);
    cudaGetSymbolAddress((void**)&shift,   g_shift);
    cudaGetSymbolAddress((void**)&gw2,     g_gw2);
    cudaGetSymbolAddress((void**)&gconst,  g_gconst);
    cudaGetSymbolAddress((void**)&gs,      g_gs);
    cudaGetSymbolAddress((void**)&ge,      g_ge);
    cudaGetSymbolAddress((void**)&pooled,  g_pooled);
    cudaGetSymbolAddress((void**)&h2,      g_h2);
    cudaGetSymbolAddress((void**)&h3,      g_h3);

    cudaFuncSetAttribute(k_mma_gemm, cudaFuncAttributeMaxDynamicSharedMemorySize, GEMM_SMEM);

    const int* row = ei;
    const int* col = ei + NE;

    const size_t wo1 = 0;
    const size_t wo4 = wo1 + (size_t)K1PAD * 1024;
    const size_t wo5 = wo4 + (size_t)256 * 512;
    const size_t wo6 = wo5 + (size_t)512 * 1024;

    // ---- GCN norm + CSR build ----
    k_filli<<<256, 256>>>(counts, 0, NN);
    k_histc<<<cdiv(NE, 256), 256>>>(col, counts);
    k_disk<<<cdiv(NN, 256), 256>>>(counts, dis);
    k_edge_norm<<<cdiv(NE, 256), 256>>>(row, col, dis, norm);
    k_scan<<<1, 1024>>>(counts, off);
    k_copyi<<<cdiv(NN, 256), 256>>>(off, cursor, NN);
    k_scatter<<<cdiv(NE, 256), 256>>>(row, col, norm, cursor, csr_src, csr_w);

    // ---- static weight pre-split (W1, W4, W5, fc2; W2/W3 are BN-transformed per call) ----
    k_split_mat<<<cdiv((long)K1PAD * 1024, 256), 256>>>(W[0], wh + wo1, wl + wo1, NF, K1PAD, 1024);
    k_split_mat<<<cdiv((long)256 * 512, 256), 256>>>(W[3], wh + wo4, wl + wo4, 256, 256, 512);
    k_split_mat<<<cdiv((long)512 * 1024, 256), 256>>>(W[4], wh + wo5, wl + wo5, 512, 512, 1024);
    k_split_mat<<<cdiv((long)1024 * 128, 256), 256>>>(fc2_W, wh + wo6, wl + wo6, 1024, 1024, 128);

    const float invn = 1.0f / NN;

    // ---- Layer 1: prop39 -> GEMM1 (mode 4: bias+relu+stats, split-bf16 out) ----
    k_prop39<<<2048, dim3(64, 4)>>>(x_in, ah, al, dis, off, csr_src, csr_w);
    gemm_tc(ah, al, wh + wo1, wl + wo1, bb[0], nullptr, ah2, al2,
            NN, 1024, K1PAD, 4, colsum, colsq);
    k_mkscale<<<4, 256>>>(colsum, colsq, gg[0], be[0], scale, shift, invn, 1024);

    // ---- Layer 2: fold BN1 into W2; GEMM2 raw; prop MODE3 (split out + stats) ----
    k_wtrans<<<16, dim3(32, 8)>>>(W[1], scale, shift, wsh, wsl, bc, 1024, 512);
    gemm_tc(ah2, al2, wsh, wsl, nullptr, bufA, nullptr, nullptr,
            NN, 512, 1024, 0, nullptr, nullptr);
    k_prop4<128, 2, 3><<<2048, dim3(128, 2)>>>((const float4*)bufA, nullptr, ah, al,
                                               dis, off, csr_src, csr_w, bb[1], bc,
                                               nullptr, nullptr, colsum, colsq);
    k_mkscale<<<2, 256>>>(colsum, colsq, gg[1], be[1], scale, shift, invn, 512);

    // ---- Layer 3: fold BN2 into W3; GEMM3 raw; prop MODE1 (fp32 y3 + stats) ----
    k_wtrans<<<8, dim3(32, 8)>>>(W[2], scale, shift, wsh, wsl, bc, 512, 256);
    gemm_tc(ah, al, wsh, wsl, nullptr, bufA, nullptr, nullptr,
            NN, 256, 512, 0, nullptr, nullptr);
    k_prop4<64, 4, 1><<<2048, dim3(64, 4)>>>((const float4*)bufA, (float4*)bufB, nullptr, nullptr,
                                             dis, off, csr_src, csr_w, bb[2], bc,
                                             nullptr, nullptr, colsum, colsq);
    k_mkscale<<<1, 256>>>(colsum, colsq, gg[2], be[2], scale, shift, invn, 256);

    // ---- Layer 4: prop MODE2 (BN3 fold, split out) -> GEMM4 (mode 3) ----
    k_prop4<64, 4, 2><<<2048, dim3(64, 4)>>>((const float4*)bufB, nullptr, ah, al,
                                             dis, off, csr_src, csr_w, nullptr, nullptr,
                                             scale, shift, nullptr, nullptr);
    gemm_tc(ah, al, wh + wo4, wl + wo4, bb[3], bufC, nullptr, nullptr,
            NN, 512, 256, 3, colsum, colsq);
    k_mkscale<<<2, 256>>>(colsum, colsq, gg[3], be[3], scale, shift, invn, 512);

    // ---- Layer 5: prop MODE2 (BN4 fold) -> GEMM5 (mode 3) ----
    k_prop4<128, 2, 2><<<2048, dim3(128, 2)>>>((const float4*)bufC, nullptr, ah, al,
                                               dis, off, csr_src, csr_w, nullptr, nullptr,
                                               scale, shift, nullptr, nullptr);
    gemm_tc(ah, al, wh + wo5, wl + wo5, bb[4], bufB, nullptr, nullptr,
            NN, 1024, 512, 3, colsum, colsq);
    k_mkscale<<<4, 256>>>(colsum, colsq, gg[4], be[4], scale, shift, invn, 1024);

    // ---- attentional pooling (BN5 folded in) ----
    k_gateprep<<<1, 256>>>(scale, shift, gate_W, gate_b, gw2, gconst);
    k_filli<<<32, 256>>>(gs, NN, NG);
    k_filli<<<32, 256>>>(ge, 0, NG);
    k_bounds<<<cdiv(NN, 256), 256>>>(batch, gs, ge);
    k_pool_gated<<<NG, 256>>>(bufB, gw2, gconst, scale, shift, gs, ge, pooled);

    // ---- MLP head ----
    k_split_mat<<<cdiv((long)NG * 1024, 256), 256>>>(pooled, ah, al, NG, NG, 1024);
    gemm_tc(ah, al, wh + wo6, wl + wo6, fc2_b, h2, nullptr, nullptr,
            NG, 128, 1024, 2, nullptr, nullptr);
    gemm32(h2, fc3_W, fc3_b, h3, NG, 16, 128, 2);
    gemm32(h3, fc4_W, fc4_b, out, NG, 1, 16, 1);
}

// round 14
// speedup vs baseline: 1.3117x; 1.0011x over previous
#include <cuda_runtime.h>
#include <cuda_bf16.h>
#include <math.h>
#include <stdint.h>

#define NN 100000
#define NE 400000
#define NG 4000
#define NF 39
#define K1PAD 40
#define DMAX 1024
#define BN_EPS 1e-5f
// W1(40x1024)+W2(1024x512)+W3(512x256)+W4(256x512)+W5(512x1024)+fc2(1024x128)
#define WTOT 1482752

// ---------------- static device scratch ----------------
__device__ float g_dis[NN];
__device__ float g_norm[NE];
__device__ int   g_counts[NN];
__device__ int   g_off[NN + 1];
__device__ int   g_cursor[NN];
__device__ int   g_src[NE];
__device__ float g_w[NE];
__device__ float g_bufA[(size_t)NN * DMAX];
__device__ float g_bufB[(size_t)NN * DMAX];
__device__ float g_bufC[(size_t)NN * DMAX];
__device__ __align__(16) __nv_bfloat16 g_ah[(size_t)NN * DMAX];
__device__ __align__(16) __nv_bfloat16 g_al[(size_t)NN * DMAX];
__device__ __align__(16) __nv_bfloat16 g_ah2[(size_t)NN * DMAX];
__device__ __align__(16) __nv_bfloat16 g_al2[(size_t)NN * DMAX];
__device__ __align__(16) __nv_bfloat16 g_wh[WTOT];
__device__ __align__(16) __nv_bfloat16 g_wl[WTOT];
__device__ __align__(16) __nv_bfloat16 g_wsh[1024 * 512];
__device__ __align__(16) __nv_bfloat16 g_wsl[1024 * 512];
__device__ float g_bc[1024];
__device__ float g_colsum[DMAX];
__device__ float g_colsq[DMAX];
__device__ float g_scale[DMAX];
__device__ float g_shift[DMAX];
__device__ float g_gw2[DMAX];
__device__ float g_gconst[1];
__device__ int   g_gs[NG];
__device__ int   g_ge[NG];
__device__ float g_pooled[(size_t)NG * DMAX];
__device__ float g_h2[NG * 128];
__device__ float g_h3[NG * 16];

// ---------------- utility ----------------
__global__ void k_filli(int* p, int v, int n) {
    for (int i = blockIdx.x * blockDim.x + threadIdx.x; i < n; i += gridDim.x * blockDim.x)
        p[i] = v;
}
__global__ void k_copyi(const int* __restrict__ a, int* __restrict__ b, int n) {
    for (int i = blockIdx.x * blockDim.x + threadIdx.x; i < n; i += gridDim.x * blockDim.x)
        b[i] = a[i];
}

__device__ __forceinline__ void splitf(float v, __nv_bfloat16& h, __nv_bfloat16& l) {
    h = __float2bfloat16(v);
    l = __float2bfloat16(v - __bfloat162float(h));
}

// ---------------- CSR build ----------------
__global__ void k_histc(const int* __restrict__ col, int* counts) {
    int e = blockIdx.x * blockDim.x + threadIdx.x;
    if (e < NE) atomicAdd(&counts[col[e]], 1);
}
__global__ void k_disk(const int* __restrict__ counts, float* dis) {
    int i = blockIdx.x * blockDim.x + threadIdx.x;
    if (i < NN) dis[i] = rsqrtf((float)counts[i] + 1.0f);
}
__global__ void k_edge_norm(const int* __restrict__ row, const int* __restrict__ col,
                            const float* __restrict__ dis, float* __restrict__ norm) {
    int e = blockIdx.x * blockDim.x + threadIdx.x;
    if (e < NE) norm[e] = dis[row[e]] * dis[col[e]];
}
__global__ void k_scan(const int* __restrict__ counts, int* __restrict__ off) {
    __shared__ int sh[1024];
    __shared__ int carry_s;
    int t = threadIdx.x;
    if (t == 0) { carry_s = 0; off[0] = 0; }
    __syncthreads();
    for (int base = 0; base < NN; base += 1024) {
        int i = base + t;
        int v = (i < NN) ? counts[i] : 0;
        sh[t] = v;
        __syncthreads();
        for (int o = 1; o < 1024; o <<= 1) {
            int add = (t >= o) ? sh[t - o] : 0;
            __syncthreads();
            sh[t] += add;
            __syncthreads();
        }
        int carry = carry_s;
        if (i < NN) off[i + 1] = carry + sh[t];
        __syncthreads();
        if (t == 1023) carry_s = carry + sh[1023];
        __syncthreads();
    }
}
__global__ void k_scatter(const int* __restrict__ row, const int* __restrict__ col,
                          const float* __restrict__ norm, int* cursor,
                          int* __restrict__ csr_src, float* __restrict__ csr_w) {
    int e = blockIdx.x * blockDim.x + threadIdx.x;
    if (e >= NE) return;
    int c = col[e];
    int p = atomicAdd(&cursor[c], 1);
    csr_src[p] = row[e];
    csr_w[p] = norm[e];
}

// ---------------- split / transform passes ----------------
__global__ void k_split_mat(const float* __restrict__ src, __nv_bfloat16* __restrict__ oh,
                            __nv_bfloat16* __restrict__ ol, int k, int kpad, int n) {
    int idx = blockIdx.x * blockDim.x + threadIdx.x;
    if (idx >= kpad * n) return;
    int r = idx / n, c = idx - r * n;
    float v = (r < k) ? src[(size_t)r * n + c] : 0.f;
    __nv_bfloat16 h, l;
    splitf(v, h, l);
    oh[idx] = h;
    ol[idx] = l;
}
// W'[k,n] = split(sc[k]*W[k,n]); bc[n] = sum_k sh[k]*W[k,n]
// grid.x = N/32, block (32,8)
__global__ void k_wtrans(const float* __restrict__ W, const float* __restrict__ sc,
                         const float* __restrict__ sh,
                         __nv_bfloat16* __restrict__ wh, __nv_bfloat16* __restrict__ wl,
                         float* __restrict__ bc, int K, int N) {
    int c = blockIdx.x * 32 + threadIdx.x;
    float acc = 0.f;
    for (int k = threadIdx.y; k < K; k += 8) {
        float v = W[(size_t)k * N + c];
        __nv_bfloat16 h, l;
        splitf(sc[k] * v, h, l);
        wh[(size_t)k * N + c] = h;
        wl[(size_t)k * N + c] = l;
        acc = fmaf(sh[k], v, acc);
    }
    __shared__ float red[8][33];
    red[threadIdx.y][threadIdx.x] = acc;
    __syncthreads();
    if (threadIdx.y == 0) {
        float t = 0.f;
#pragma unroll
        for (int y = 0; y < 8; y++) t += red[y][threadIdx.x];
        bc[c] = t;
    }
}

// ---------------- CSR gather propagate ----------------
// MODE 1: acc = relu(agg + wsum*bc + bias); fp32 out + stats
// MODE 2: acc = insc*agg + insh*wsum; split bf16 out (BN-fold, no stats)
// MODE 3: acc = relu(agg + wsum*bc + bias); split bf16 out + stats
template <int DIMV, int NPB, int MODE>
__global__ void k_prop4(const float4* __restrict__ in, float4* __restrict__ out,
                        __nv_bfloat16* __restrict__ outh, __nv_bfloat16* __restrict__ outl,
                        const float* __restrict__ dis,
                        const int* __restrict__ off, const int* __restrict__ src,
                        const float* __restrict__ w,
                        const float* __restrict__ bias, const float* __restrict__ bc,
                        const float* __restrict__ insc, const float* __restrict__ insh,
                        float* __restrict__ colsum, float* __restrict__ colsq) {
    const int DIM = DIMV * 4;
    int x = threadIdx.x;
    int yy = threadIdx.y;
    float4 bb = make_float4(0.f, 0.f, 0.f, 0.f);
    float4 bc4 = make_float4(0.f, 0.f, 0.f, 0.f);
    float4 sc4 = make_float4(0.f, 0.f, 0.f, 0.f), sh4 = sc4;
    float4 s1 = make_float4(0.f, 0.f, 0.f, 0.f);
    float4 s2 = make_float4(0.f, 0.f, 0.f, 0.f);
    if (MODE == 1 || MODE == 3) {
        bb = *(const float4*)&bias[x * 4];
        bc4 = *(const float4*)&bc[x * 4];
    }
    if (MODE == 2) {
        sc4 = *(const float4*)&insc[x * 4];
        sh4 = *(const float4*)&insh[x * 4];
    }
    for (int n = blockIdx.x * NPB + yy; n < NN; n += gridDim.x * NPB) {
        float d = dis[n];
        float sw = d * d;
        float4 v = in[(size_t)n * DIMV + x];
        float4 acc = make_float4(sw * v.x, sw * v.y, sw * v.z, sw * v.w);
        float wsum = sw;
        int e1 = __ldg(&off[n + 1]);
        for (int e = __ldg(&off[n]); e < e1; e++) {
            int sr = __ldg(&src[e]);
            float ww = __ldg(&w[e]);
            wsum += ww;
            float4 u = in[(size_t)sr * DIMV + x];
            acc.x = fmaf(ww, u.x, acc.x);
            acc.y = fmaf(ww, u.y, acc.y);
            acc.z = fmaf(ww, u.z, acc.z);
            acc.w = fmaf(ww, u.w, acc.w);
        }
        if (MODE == 1 || MODE == 3) {
            acc.x = fmaxf(acc.x + wsum * bc4.x + bb.x, 0.f);
            acc.y = fmaxf(acc.y + wsum * bc4.y + bb.y, 0.f);
            acc.z = fmaxf(acc.z + wsum * bc4.z + bb.z, 0.f);
            acc.w = fmaxf(acc.w + wsum * bc4.w + bb.w, 0.f);
            s1.x += acc.x; s1.y += acc.y; s1.z += acc.z; s1.w += acc.w;
            s2.x += acc.x * acc.x; s2.y += acc.y * acc.y;
            s2.z += acc.z * acc.z; s2.w += acc.w * acc.w;
            if (MODE == 1) {
                out[(size_t)n * DIMV + x] = acc;
            } else {
                __nv_bfloat16 h0, l0, h1, l1, h2, l2, h3, l3;
                splitf(acc.x, h0, l0); splitf(acc.y, h1, l1);
                splitf(acc.z, h2, l2); splitf(acc.w, h3, l3);
                uint2 hv, lv;
                hv.x = ((uint32_t)__bfloat16_as_ushort(h1) << 16) | __bfloat16_as_ushort(h0);
                hv.y = ((uint32_t)__bfloat16_as_ushort(h3) << 16) | __bfloat16_as_ushort(h2);
                lv.x = ((uint32_t)__bfloat16_as_ushort(l1) << 16) | __bfloat16_as_ushort(l0);
                lv.y = ((uint32_t)__bfloat16_as_ushort(l3) << 16) | __bfloat16_as_ushort(l2);
                *(uint2*)&outh[(size_t)n * DIM + x * 4] = hv;
                *(uint2*)&outl[(size_t)n * DIM + x * 4] = lv;
            }
        } else {  // MODE 2
            acc.x = sc4.x * acc.x + sh4.x * wsum;
            acc.y = sc4.y * acc.y + sh4.y * wsum;
            acc.z = sc4.z * acc.z + sh4.z * wsum;
            acc.w = sc4.w * acc.w + sh4.w * wsum;
            __nv_bfloat16 h0, l0, h1, l1, h2, l2, h3, l3;
            splitf(acc.x, h0, l0); splitf(acc.y, h1, l1);
            splitf(acc.z, h2, l2); splitf(acc.w, h3, l3);
            uint2 hv, lv;
            hv.x = ((uint32_t)__bfloat16_as_ushort(h1) << 16) | __bfloat16_as_ushort(h0);
            hv.y = ((uint32_t)__bfloat16_as_ushort(h3) << 16) | __bfloat16_as_ushort(h2);
            lv.x = ((uint32_t)__bfloat16_as_ushort(l1) << 16) | __bfloat16_as_ushort(l0);
            lv.y = ((uint32_t)__bfloat16_as_ushort(l3) << 16) | __bfloat16_as_ushort(l2);
            *(uint2*)&outh[(size_t)n * DIM + x * 4] = hv;
            *(uint2*)&outl[(size_t)n * DIM + x * 4] = lv;
        }
    }
    if (MODE == 1 || MODE == 3) {
        int c = x * 4;
        atomicAdd(&colsum[c + 0], s1.x);
        atomicAdd(&colsum[c + 1], s1.y);
        atomicAdd(&colsum[c + 2], s1.z);
        atomicAdd(&colsum[c + 3], s1.w);
        atomicAdd(&colsq[c + 0], s2.x);
        atomicAdd(&colsq[c + 1], s2.y);
        atomicAdd(&colsq[c + 2], s2.z);
        atomicAdd(&colsq[c + 3], s2.w);
    }
}

__global__ void k_prop39(const float* __restrict__ in,
                         __nv_bfloat16* __restrict__ oh, __nv_bfloat16* __restrict__ ol,
                         const float* __restrict__ dis,
                         const int* __restrict__ off, const int* __restrict__ src,
                         const float* __restrict__ w) {
    int x = threadIdx.x;
    if (x >= K1PAD) return;
    int yy = threadIdx.y;
    __nv_bfloat16 z = __float2bfloat16(0.f);
    for (int n = blockIdx.x * 4 + yy; n < NN; n += gridDim.x * 4) {
        if (x >= NF) {
            oh[(size_t)n * K1PAD + x] = z;
            ol[(size_t)n * K1PAD + x] = z;
            continue;
        }
        float d = dis[n];
        float acc = d * d * in[(size_t)n * NF + x];
        int e1 = __ldg(&off[n + 1]);
        for (int e = __ldg(&off[n]); e < e1; e++)
            acc = fmaf(__ldg(&w[e]), in[(size_t)__ldg(&src[e]) * NF + x], acc);
        __nv_bfloat16 h, l;
        splitf(acc, h, l);
        oh[(size_t)n * K1PAD + x] = h;
        ol[(size_t)n * K1PAD + x] = l;
    }
}

// ======== bf16 3-product tensor-core GEMM (2-stage cp.async, 2 CTA/SM) =========
__device__ __forceinline__ void ldsm4(uint32_t* r, const void* p) {
    uint32_t a = (uint32_t)__cvta_generic_to_shared(p);
    asm volatile("ldmatrix.sync.aligned.m8n8.x4.shared.b16 {%0,%1,%2,%3}, [%4];"
                 : "=r"(r[0]), "=r"(r[1]), "=r"(r[2]), "=r"(r[3]) : "r"(a));
}
__device__ __forceinline__ void ldsm4t(uint32_t* r, const void* p) {
    uint32_t a = (uint32_t)__cvta_generic_to_shared(p);
    asm volatile("ldmatrix.sync.aligned.m8n8.x4.trans.shared.b16 {%0,%1,%2,%3}, [%4];"
                 : "=r"(r[0]), "=r"(r[1]), "=r"(r[2]), "=r"(r[3]) : "r"(a));
}
__device__ __forceinline__ void mma16816(float* d, const uint32_t* a, const uint32_t* b) {
    asm volatile("mma.sync.aligned.m16n8k16.row.col.f32.bf16.bf16.f32 "
                 "{%0,%1,%2,%3}, {%4,%5,%6,%7}, {%8,%9}, {%0,%1,%2,%3};"
                 : "+f"(d[0]), "+f"(d[1]), "+f"(d[2]), "+f"(d[3])
                 : "r"(a[0]), "r"(a[1]), "r"(a[2]), "r"(a[3]),
                   "r"(b[0]), "r"(b[1]));
}
__device__ __forceinline__ void cpa16(uint32_t saddr, const void* g, int sz) {
    asm volatile("cp.async.cg.shared.global [%0], [%1], 16, %2;"
                 :: "r"(saddr), "l"(g), "r"(sz));
}
__device__ __forceinline__ void cpa_commit() {
    asm volatile("cp.async.commit_group;");
}
template <int N>
__device__ __forceinline__ void cpa_wait() {
    asm volatile("cp.async.wait_group %0;" :: "n"(N));
}

#define APAD 40
#define BPAD 136
#define ABUF (128 * APAD)
#define BBUF (32 * BPAD)
#define GEMM_SMEM (2 * (2 * ABUF + 2 * BBUF) * 2 + 256 * 4)

// mode: 0 raw fp32 | 1 +bias | 2 +bias+relu | 3 +bias+relu+stats fp32 | 4 +bias+relu+stats split-bf16
__global__ void __launch_bounds__(256, 2)
k_mma_gemm(const __nv_bfloat16* __restrict__ Ah, const __nv_bfloat16* __restrict__ Al,
           const __nv_bfloat16* __restrict__ Bh, const __nv_bfloat16* __restrict__ Bl,
           const float* __restrict__ bias, float* __restrict__ C,
           __nv_bfloat16* __restrict__ OH, __nv_bfloat16* __restrict__ OL,
           int M, int N, int K, int mode,
           float* __restrict__ colsum, float* __restrict__ colsq) {
    extern __shared__ __align__(16) char dsm[];
    __nv_bfloat16* Ahs = (__nv_bfloat16*)dsm;
    __nv_bfloat16* Als = Ahs + 2 * ABUF;
    __nv_bfloat16* Bhs = Als + 2 * ABUF;
    __nv_bfloat16* Bls = Bhs + 2 * BBUF;
    float* s_sum = (float*)(Bls + 2 * BBUF);
    float* s_sq = s_sum + 128;

    const int tid = threadIdx.x;
    const int lane = tid & 31;
    const int warp = tid >> 5;
    const int wm = warp & 3;
    const int wn = warp >> 2;
    const int bm = blockIdx.y * 128;
    const int bn = blockIdx.x * 128;

    float acc[2][8][4];
#pragma unroll
    for (int i = 0; i < 2; i++)
#pragma unroll
        for (int j = 0; j < 8; j++)
#pragma unroll
            for (int c = 0; c < 4; c++) acc[i][j][c] = 0.f;

    const uint32_t sAh = (uint32_t)__cvta_generic_to_shared(Ahs);
    const uint32_t sAl = (uint32_t)__cvta_generic_to_shared(Als);
    const uint32_t sBh = (uint32_t)__cvta_generic_to_shared(Bhs);
    const uint32_t sBl = (uint32_t)__cvta_generic_to_shared(Bls);

    auto prefetch = [&](int k0, int buf) {
        uint32_t aOff = buf * ABUF * 2;
        uint32_t bOff = buf * BBUF * 2;
#pragma unroll
        for (int it = 0; it < 2; it++) {
            int idx = tid + it * 256;
            int r = idx >> 2, q = idx & 3;
            int gm = bm + r, gk = k0 + q * 8;
            int sz = (gm < M && gk < K) ? 16 : 0;
            int gmc = (gm < M) ? gm : 0;
            int gkc = (gk < K) ? gk : 0;
            uint32_t d = (uint32_t)(r * APAD + q * 8) * 2;
            cpa16(sAh + aOff + d, &Ah[(size_t)gmc * K + gkc], sz);
            cpa16(sAl + aOff + d, &Al[(size_t)gmc * K + gkc], sz);
        }
#pragma unroll
        for (int it = 0; it < 2; it++) {
            int idx = tid + it * 256;
            int r = idx >> 4, q = idx & 15;
            int gk = k0 + r, gn = bn + q * 8;
            int sz = (gk < K) ? 16 : 0;
            int gkc = (gk < K) ? gk : 0;
            uint32_t d = (uint32_t)(r * BPAD + q * 8) * 2;
            cpa16(sBh + bOff + d, &Bh[(size_t)gkc * N + gn], sz);
            cpa16(sBl + bOff + d, &Bl[(size_t)gkc * N + gn], sz);
        }
    };

    const int nk = (K + 31) >> 5;
    prefetch(0, 0);
    cpa_commit();

    for (int kt = 0; kt < nk; kt++) {
        const int cur = kt & 1;
        if (kt + 1 < nk) {
            prefetch((kt + 1) << 5, cur ^ 1);
            cpa_commit();
            cpa_wait<1>();
        } else {
            cpa_wait<0>();
        }
        __syncthreads();

        const __nv_bfloat16* cAh = Ahs + cur * ABUF;
        const __nv_bfloat16* cAl = Als + cur * ABUF;
        const __nv_bfloat16* cBh = Bhs + cur * BBUF;
        const __nv_bfloat16* cBl = Bls + cur * BBUF;

#pragma unroll
        for (int ks = 0; ks < 32; ks += 16) {
            uint32_t ah[2][4], al[2][4];
#pragma unroll
            for (int i = 0; i < 2; i++) {
                int rowa = wm * 32 + i * 16 + (lane & 15);
                int kc = ks + ((lane >> 4) << 3);
                ldsm4(ah[i], &cAh[rowa * APAD + kc]);
                ldsm4(al[i], &cAl[rowa * APAD + kc]);
            }
#pragma unroll
            for (int nh = 0; nh < 2; nh++) {
                uint32_t bh[2][4], bl[2][4];
#pragma unroll
                for (int j2 = 0; j2 < 2; j2++) {
                    int rowb = ks + (lane & 15);
                    int nc = wn * 64 + (nh * 2 + j2) * 16 + ((lane >> 4) << 3);
                    ldsm4t(bh[j2], &cBh[rowb * BPAD + nc]);
                    ldsm4t(bl[j2], &cBl[rowb * BPAD + nc]);
                }
#pragma unroll
                for (int i = 0; i < 2; i++)
#pragma unroll
                    for (int j = 0; j < 4; j++)
                        mma16816(acc[i][nh * 4 + j], ah[i], &bh[j >> 1][(j & 1) * 2]);
#pragma unroll
                for (int i = 0; i < 2; i++)
#pragma unroll
                    for (int j = 0; j < 4; j++)
                        mma16816(acc[i][nh * 4 + j], ah[i], &bl[j >> 1][(j & 1) * 2]);
#pragma unroll
                for (int i = 0; i < 2; i++)
#pragma unroll
                    for (int j = 0; j < 4; j++)
                        mma16816(acc[i][nh * 4 + j], al[i], &bh[j >> 1][(j & 1) * 2]);
            }
        }
        __syncthreads();
    }

    // ---- epilogue ----
    if (mode >= 3) {
        if (tid < 128) { s_sum[tid] = 0.f; s_sq[tid] = 0.f; }
        __syncthreads();
    }
    float csum[8][2], csq[8][2];
#pragma unroll
    for (int j = 0; j < 8; j++) { csum[j][0] = csum[j][1] = 0.f; csq[j][0] = csq[j][1] = 0.f; }

#pragma unroll
    for (int i = 0; i < 2; i++) {
        int r0 = bm + wm * 32 + i * 16 + (lane >> 2);
#pragma unroll
        for (int j = 0; j < 8; j++) {
            int nh = j >> 2, jj = j & 3;
            int cc = bn + wn * 64 + (nh * 2 + (jj >> 1)) * 16 + (jj & 1) * 8 + (lane & 3) * 2;
            float b0 = 0.f, b1 = 0.f;
            if (mode >= 1) { b0 = bias[cc]; b1 = bias[cc + 1]; }
            float v0 = acc[i][j][0] + b0, v1 = acc[i][j][1] + b1;
            float v2 = acc[i][j][2] + b0, v3 = acc[i][j][3] + b1;
            if (mode >= 2) {
                v0 = fmaxf(v0, 0.f); v1 = fmaxf(v1, 0.f);
                v2 = fmaxf(v2, 0.f); v3 = fmaxf(v3, 0.f);
            }
            if (r0 < M) {
                if (mode == 4) {
                    __nv_bfloat16 h0, l0, h1, l1;
                    splitf(v0, h0, l0); splitf(v1, h1, l1);
                    *(uint32_t*)&OH[(size_t)r0 * N + cc] =
                        ((uint32_t)__bfloat16_as_ushort(h1) << 16) | __bfloat16_as_ushort(h0);
                    *(uint32_t*)&OL[(size_t)r0 * N + cc] =
                        ((uint32_t)__bfloat16_as_ushort(l1) << 16) | __bfloat16_as_ushort(l0);
                } else {
                    *(float2*)&C[(size_t)r0 * N + cc] = make_float2(v0, v1);
                }
                if (mode >= 3) { csum[j][0] += v0; csum[j][1] += v1; csq[j][0] += v0 * v0; csq[j][1] += v1 * v1; }
            }
            if (r0 + 8 < M) {
                if (mode == 4) {
                    __nv_bfloat16 h2, l2, h3, l3;
                    splitf(v2, h2, l2); splitf(v3, h3, l3);
                    *(uint32_t*)&OH[(size_t)(r0 + 8) * N + cc] =
                        ((uint32_t)__bfloat16_as_ushort(h3) << 16) | __bfloat16_as_ushort(h2);
                    *(uint32_t*)&OL[(size_t)(r0 + 8) * N + cc] =
                        ((uint32_t)__bfloat16_as_ushort(l3) << 16) | __bfloat16_as_ushort(l2);
                } else {
                    *(float2*)&C[(size_t)(r0 + 8) * N + cc] = make_float2(v2, v3);
                }
                if (mode >= 3) { csum[j][0] += v2; csum[j][1] += v3; csq[j][0] += v2 * v2; csq[j][1] += v3 * v3; }
            }
        }
    }
    if (mode >= 3) {
#pragma unroll
        for (int j = 0; j < 8; j++) {
            int nh = j >> 2, jj = j & 3;
            int nl = wn * 64 + (nh * 2 + (jj >> 1)) * 16 + (jj & 1) * 8 + (lane & 3) * 2;
            atomicAdd(&s_sum[nl], csum[j][0]);
            atomicAdd(&s_sum[nl + 1], csum[j][1]);
            atomicAdd(&s_sq[nl], csq[j][0]);
            atomicAdd(&s_sq[nl + 1], csq[j][1]);
        }
        __syncthreads();
        if (tid < 128) {
            atomicAdd(&colsum[bn + tid], s_sum[tid]);
            atomicAdd(&colsq[bn + tid], s_sq[tid]);
        }
    }
}

// ---------------- fp32 SGEMM (small head GEMMs) --------------------
__global__ void __launch_bounds__(256, 2)
k_sgemm128(const float* __restrict__ A, const float* __restrict__ B,
           const float* __restrict__ bias, float* __restrict__ C,
           int M, int N, int K, int mode) {
    __shared__ float As[8][132];
    __shared__ float Bs[8][132];
    const int bm = blockIdx.y * 128;
    const int bn = blockIdx.x * 128;
    const int tid = threadIdx.x;
    const int tx = tid & 15, ty = tid >> 4;
    const bool vecK = (K & 3) == 0;
    const bool vecN = (N & 3) == 0;

    float acc[8][8];
#pragma unroll
    for (int i = 0; i < 8; i++)
#pragma unroll
        for (int j = 0; j < 8; j++) acc[i][j] = 0.f;

    const int arow = tid >> 1, ah = tid & 1;
    const int bk = tid >> 5, bn4 = (tid & 31) * 4;

    for (int k0 = 0; k0 < K; k0 += 8) {
        {
            int gm = bm + arow;
            float av[4];
            if (vecK && gm < M && k0 + ah * 4 + 3 < K) {
                float4 v = *(const float4*)&A[(size_t)gm * K + k0 + ah * 4];
                av[0] = v.x; av[1] = v.y; av[2] = v.z; av[3] = v.w;
            } else {
#pragma unroll
                for (int j = 0; j < 4; j++)
                    av[j] = (gm < M && k0 + ah * 4 + j < K)
                                ? A[(size_t)gm * K + k0 + ah * 4 + j] : 0.f;
            }
#pragma unroll
            for (int j = 0; j < 4; j++) As[ah * 4 + j][arow] = av[j];
        }
        {
            float4 v;
            if (vecN && k0 + bk < K && bn + bn4 + 3 < N) {
                v = *(const float4*)&B[(size_t)(k0 + bk) * N + bn + bn4];
            } else {
                float bv[4];
#pragma unroll
                for (int j = 0; j < 4; j++)
                    bv[j] = (k0 + bk < K && bn + bn4 + j < N)
                                ? B[(size_t)(k0 + bk) * N + bn + bn4 + j] : 0.f;
                v = make_float4(bv[0], bv[1], bv[2], bv[3]);
            }
            *(float4*)&Bs[bk][bn4] = v;
        }
        __syncthreads();
#pragma unroll
        for (int k = 0; k < 8; k++) {
            float4 a0 = *(const float4*)&As[k][ty * 4];
            float4 a1 = *(const float4*)&As[k][64 + ty * 4];
            float4 b0 = *(const float4*)&Bs[k][tx * 4];
            float4 b1 = *(const float4*)&Bs[k][64 + tx * 4];
            float a[8] = {a0.x, a0.y, a0.z, a0.w, a1.x, a1.y, a1.z, a1.w};
            float b[8] = {b0.x, b0.y, b0.z, b0.w, b1.x, b1.y, b1.z, b1.w};
#pragma unroll
            for (int i = 0; i < 8; i++)
#pragma unroll
                for (int j = 0; j < 8; j++) acc[i][j] = fmaf(a[i], b[j], acc[i][j]);
        }
        __syncthreads();
    }
#pragma unroll
    for (int i = 0; i < 8; i++) {
        int mr = (i < 4) ? (ty * 4 + i) : (64 + ty * 4 + i - 4);
        int m = bm + mr;
        if (m >= M) continue;
#pragma unroll
        for (int j = 0; j < 8; j++) {
            int nc = (j < 4) ? (tx * 4 + j) : (64 + tx * 4 + j - 4);
            int n = bn + nc;
            if (n >= N) continue;
            float v = acc[i][j];
            if (mode >= 1) v += bias[n];
            if (mode == 2) v = fmaxf(v, 0.f);
            C[(size_t)m * N + n] = v;
        }
    }
}

// ---------------- BN finalize (self-zeroing stats) ----------------
__global__ void k_mkscale(float* __restrict__ colsum, float* __restrict__ colsq,
                          const float* __restrict__ g, const float* __restrict__ be,
                          float* __restrict__ scale, float* __restrict__ shift,
                          float invn, int ncols) {
    int c = blockIdx.x * blockDim.x + threadIdx.x;
    if (c >= ncols) return;
    float mean = colsum[c] * invn;
    float var = colsq[c] * invn - mean * mean;
    float sc = g[c] * rsqrtf(var + BN_EPS);
    scale[c] = sc;
    shift[c] = be[c] - mean * sc;
    colsum[c] = 0.f;
    colsq[c] = 0.f;
}

// ---------------- fused pooling ----------------
__global__ void k_gateprep(const float* __restrict__ scale, const float* __restrict__ shift,
                           const float* __restrict__ gw, const float* __restrict__ gb,
                           float* __restrict__ gw2, float* __restrict__ gconst) {
    __shared__ float red[256];
    int tid = threadIdx.x;
    float part = 0.f;
    for (int c = tid; c < 1024; c += 256) {
        gw2[c] = scale[c] * gw[c];
        part += shift[c] * gw[c];
    }
    red[tid] = part;
    __syncthreads();
    for (int o = 128; o > 0; o >>= 1) {
        if (tid < o) red[tid] += red[tid + o];
        __syncthreads();
    }
    if (tid == 0) gconst[0] = red[0] + gb[0];
}
__global__ void k_bounds(const int* __restrict__ batch, int* gs, int* ge) {
    int i = blockIdx.x * blockDim.x + threadIdx.x;
    if (i >= NN) return;
    int b = batch[i];
    atomicMin(&gs[b], i);
    atomicMax(&ge[b], i + 1);
}

#define SGMAX 1024
__global__ void k_pool_gated(const float* __restrict__ x, const float* __restrict__ gw2,
                             const float* __restrict__ gconstp,
                             const float* __restrict__ scale, const float* __restrict__ shift,
                             const int* __restrict__ gs, const int* __restrict__ ge,
                             float* __restrict__ pooled) {
    int g = blockIdx.x;
    int s = gs[g], e = ge[g];
    int tid = threadIdx.x, lane = tid & 31, warp = tid >> 5;
    __shared__ float sgate[SGMAX];
    __shared__ float red[256];
    float gconst = gconstp[0];

    for (int i = s + warp; i < e; i += 8) {
        const float4* xr = (const float4*)(x + (size_t)i * 1024);
        const float4* w4 = (const float4*)gw2;
        float acc = 0.f;
#pragma unroll
        for (int k = 0; k < 8; k++) {
            float4 a = xr[lane + k * 32];
            float4 b = w4[lane + k * 32];
            acc += a.x * b.x + a.y * b.y + a.z * b.z + a.w * b.w;
        }
#pragma unroll
        for (int o = 16; o > 0; o >>= 1) acc += __shfl_down_sync(0xffffffffu, acc, o);
        if (lane == 0 && (i - s) < SGMAX) sgate[i - s] = acc + gconst;
    }
    __syncthreads();

    auto getg = [&](int i) -> float {
        if (i - s < SGMAX) return sgate[i - s];
        float acc = 0.f;
        const float* xr = x + (size_t)i * 1024;
        for (int c = 0; c < 1024; c++) acc += xr[c] * gw2[c];
        return acc + gconst;
    };

    float m = -INFINITY;
    for (int i = s + tid; i < e; i += 256) m = fmaxf(m, getg(i));
    red[tid] = m;
    __syncthreads();
    for (int o = 128; o > 0; o >>= 1) {
        if (tid < o) red[tid] = fmaxf(red[tid], red[tid + o]);
        __syncthreads();
    }
    float gm = red[0];
    __syncthreads();
    float ss = 0.f;
    for (int i = s + tid; i < e; i += 256) ss += expf(getg(i) - gm);
    red[tid] = ss;
    __syncthreads();
    for (int o = 128; o > 0; o >>= 1) {
        if (tid < o) red[tid] += red[tid + o];
        __syncthreads();
    }
    float inv = (e > s) ? 1.0f / red[0] : 0.f;

    int d = tid * 4;
    float4 acc = make_float4(0.f, 0.f, 0.f, 0.f);
    float ws = 0.f;
    for (int i = s; i < e; i++) {
        float w = expf(getg(i) - gm) * inv;
        ws += w;
        float4 v = *(const float4*)&x[(size_t)i * 1024 + d];
        acc.x += w * v.x; acc.y += w * v.y; acc.z += w * v.z; acc.w += w * v.w;
    }
    float4 o;
    o.x = scale[d + 0] * acc.x + shift[d + 0] * ws;
    o.y = scale[d + 1] * acc.y + shift[d + 1] * ws;
    o.z = scale[d + 2] * acc.z + shift[d + 2] * ws;
    o.w = scale[d + 3] * acc.w + shift[d + 3] * ws;
    *(float4*)&pooled[(size_t)g * 1024 + d] = o;
}

// ---------------- host orchestration ----------------
static inline int cdiv(long a, long b) { return (int)((a + b - 1) / b); }

static void gemm_tc(const __nv_bfloat16* Ah, const __nv_bfloat16* Al,
                    const __nv_bfloat16* Bh, const __nv_bfloat16* Bl,
                    const float* bias, float* C,
                    __nv_bfloat16* OH, __nv_bfloat16* OL,
                    int M, int N, int K, int mode, float* colsum, float* colsq) {
    dim3 grid(N / 128, cdiv(M, 128));
    k_mma_gemm<<<grid, 256, GEMM_SMEM>>>(Ah, Al, Bh, Bl, bias, C, OH, OL, M, N, K, mode,
                                         colsum, colsq);
}
static void gemm32(const float* A, const float* B, const float* bias, float* C,
                   int M, int N, int K, int mode) {
    dim3 grid(cdiv(N, 128), cdiv(M, 128));
    k_sgemm128<<<grid, 256>>>(A, B, bias, C, M, N, K, mode);
}

extern "C" void kernel_launch(void* const* d_in, const int* in_sizes, int n_in,
                              void* d_out, int out_size) {
    (void)in_sizes; (void)n_in; (void)out_size;
    const float* x_in  = (const float*)d_in[0];
    const int*   ei    = (const int*)d_in[1];
    const int*   batch = (const int*)d_in[2];
    const float *W[5], *bb[5], *gg[5], *be[5];
    for (int l = 0; l < 5; l++) {
        W[l]  = (const float*)d_in[3 + 4 * l];
        bb[l] = (const float*)d_in[4 + 4 * l];
        gg[l] = (const float*)d_in[5 + 4 * l];
        be[l] = (const float*)d_in[6 + 4 * l];
    }
    const float* gate_W = (const float*)d_in[23];
    const float* gate_b = (const float*)d_in[24];
    const float* fc2_W  = (const float*)d_in[25];
    const float* fc2_b  = (const float*)d_in[26];
    const float* fc3_W  = (const float*)d_in[27];
    const float* fc3_b  = (const float*)d_in[28];
    const float* fc4_W  = (const float*)d_in[29];
    const float* fc4_b  = (const float*)d_in[30];
    float* out = (float*)d_out;

    float *dis, *norm, *bufA, *bufB, *bufC, *colsum, *colsq, *scale, *shift;
    float *pooled, *h2, *h3, *csr_w, *gw2, *gconst, *bc;
    __nv_bfloat16 *ah, *al, *ah2, *al2, *wh, *wl, *wsh, *wsl;
    int *gs, *ge, *counts, *off, *cursor, *csr_src;
    cudaGetSymbolAddress((void**)&dis,     g_dis);
    cudaGetSymbolAddress((void**)&norm,    g_norm);
    cudaGetSymbolAddress((void**)&counts,  g_counts);
    cudaGetSymbolAddress((void**)&off,     g_off);
    cudaGetSymbolAddress((void**)&cursor,  g_cursor);
    cudaGetSymbolAddress((void**)&csr_src, g_src);
    cudaGetSymbolAddress((void**)&csr_w,   g_w);
    cudaGetSymbolAddress((void**)&bufA,    g_bufA);
    cudaGetSymbolAddress((void**)&bufB,    g_bufB);
    cudaGetSymbolAddress((void**)&bufC,    g_bufC);
    cudaGetSymbolAddress((void**)&ah,      g_ah);
    cudaGetSymbolAddress((void**)&al,      g_al);
    cudaGetSymbolAddress((void**)&ah2,     g_ah2);
    cudaGetSymbolAddress((void**)&al2,     g_al2);
    cudaGetSymbolAddress((void**)&wh,      g_wh);
    cudaGetSymbolAddress((void**)&wl,      g_wl);
    cudaGetSymbolAddress((void**)&wsh,     g_wsh);
    cudaGetSymbolAddress((void**)&wsl,     g_wsl);
    cudaGetSymbolAddress((void**)&bc,      g_bc);
    cudaGetSymbolAddress((void**)&colsum,  g_colsum);
    cudaGetSymbolAddress((void**)&colsq,   g_colsq);
    cudaGetSymbolAddress((void**)&scale,   g_scale);
    cudaGetSymbolAddress((void**)&shift,   g_shift);
    cudaGetSymbolAddress((void**)&gw2,     g_gw2);
    cudaGetSymbolAddress((void**)&gconst,  g_gconst);
    cudaGetSymbolAddress((void**)&gs,      g_gs);
    cudaGetSymbolAddress((void**)&ge,      g_ge);
    cudaGetSymbolAddress((void**)&pooled,  g_pooled);
    cudaGetSymbolAddress((void**)&h2,      g_h2);
    cudaGetSymbolAddress((void**)&h3,      g_h3);

    cudaFuncSetAttribute(k_mma_gemm, cudaFuncAttributeMaxDynamicSharedMemorySize, GEMM_SMEM);

    const int* row = ei;
    const int* col = ei + NE;

    const size_t wo1 = 0;
    const size_t wo4 = wo1 + (size_t)K1PAD * 1024;
    const size_t wo5 = wo4 + (size_t)256 * 512;
    const size_t wo6 = wo5 + (size_t)512 * 1024;

    // ---- GCN norm + CSR build ----
    k_filli<<<256, 256>>>(counts, 0, NN);
    k_histc<<<cdiv(NE, 256), 256>>>(col, counts);
    k_disk<<<cdiv(NN, 256), 256>>>(counts, dis);
    k_edge_norm<<<cdiv(NE, 256), 256>>>(row, col, dis, norm);
    k_scan<<<1, 1024>>>(counts, off);
    k_copyi<<<cdiv(NN, 256), 256>>>(off, cursor, NN);
    k_scatter<<<cdiv(NE, 256), 256>>>(row, col, norm, cursor, csr_src, csr_w);

    // ---- static weight pre-split (W1, W4, W5, fc2; W2/W3 are BN-transformed per call) ----
    k_split_mat<<<cdiv((long)K1PAD * 1024, 256), 256>>>(W[0], wh + wo1, wl + wo1, NF, K1PAD, 1024);
    k_split_mat<<<cdiv((long)256 * 512, 256), 256>>>(W[3], wh + wo4, wl + wo4, 256, 256, 512);
    k_split_mat<<<cdiv((long)512 * 1024, 256), 256>>>(W[4], wh + wo5, wl + wo5, 512, 512, 1024);
    k_split_mat<<<cdiv((long)1024 * 128, 256), 256>>>(fc2_W, wh + wo6, wl + wo6, 1024, 1024, 128);

    const float invn = 1.0f / NN;

    // ---- Layer 1: prop39 -> GEMM1 (mode 4: bias+relu+stats, split-bf16 out) ----
    k_prop39<<<2048, dim3(64, 4)>>>(x_in, ah, al, dis, off, csr_src, csr_w);
    gemm_tc(ah, al, wh + wo1, wl + wo1, bb[0], nullptr, ah2, al2,
            NN, 1024, K1PAD, 4, colsum, colsq);
    k_mkscale<<<4, 256>>>(colsum, colsq, gg[0], be[0], scale, shift, invn, 1024);

    // ---- Layer 2: fold BN1 into W2; GEMM2 raw; prop MODE3 (split out + stats) ----
    k_wtrans<<<16, dim3(32, 8)>>>(W[1], scale, shift, wsh, wsl, bc, 1024, 512);
    gemm_tc(ah2, al2, wsh, wsl, nullptr, bufA, nullptr, nullptr,
            NN, 512, 1024, 0, nullptr, nullptr);
    k_prop4<128, 2, 3><<<2048, dim3(128, 2)>>>((const float4*)bufA, nullptr, ah, al,
                                               dis, off, csr_src, csr_w, bb[1], bc,
                                               nullptr, nullptr, colsum, colsq);
    k_mkscale<<<2, 256>>>(colsum, colsq, gg[1], be[1], scale, shift, invn, 512);

    // ---- Layer 3: fold BN2 into W3; GEMM3 raw; prop MODE1 (fp32 y3 + stats) ----
    k_wtrans<<<8, dim3(32, 8)>>>(W[2], scale, shift, wsh, wsl, bc, 512, 256);
    gemm_tc(ah, al, wsh, wsl, nullptr, bufA, nullptr, nullptr,
            NN, 256, 512, 0, nullptr, nullptr);
    k_prop4<64, 4, 1><<<2048, dim3(64, 4)>>>((const float4*)bufA, (float4*)bufB, nullptr, nullptr,
                                             dis, off, csr_src, csr_w, bb[2], bc,
                                             nullptr, nullptr, colsum, colsq);
    k_mkscale<<<1, 256>>>(colsum, colsq, gg[2], be[2], scale, shift, invn, 256);

    // ---- Layer 4: prop MODE2 (BN3 fold, split out) -> GEMM4 (mode 3) ----
    k_prop4<64, 4, 2><<<2048, dim3(64, 4)>>>((const float4*)bufB, nullptr, ah, al,
                                             dis, off, csr_src, csr_w, nullptr, nullptr,
                                             scale, shift, nullptr, nullptr);
    gemm_tc(ah, al, wh + wo4, wl + wo4, bb[3], bufC, nullptr, nullptr,
            NN, 512, 256, 3, colsum, colsq);
    k_mkscale<<<2, 256>>>(colsum, colsq, gg[3], be[3], scale, shift, invn, 512);

    // ---- Layer 5: prop MODE2 (BN4 fold) -> GEMM5 (mode 3) ----
    k_prop4<128, 2, 2><<<2048, dim3(128, 2)>>>((const float4*)bufC, nullptr, ah, al,
                                               dis, off, csr_src, csr_w, nullptr, nullptr,
                                               scale, shift, nullptr, nullptr);
    gemm_tc(ah, al, wh + wo5, wl + wo5, bb[4], bufB, nullptr, nullptr,
            NN, 1024, 512, 3, colsum, colsq);
    k_mkscale<<<4, 256>>>(colsum, colsq, gg[4], be[4], scale, shift, invn, 1024);

    // ---- attentional pooling (BN5 folded in) ----
    k_gateprep<<<1, 256>>>(scale, shift, gate_W, gate_b, gw2, gconst);
    k_filli<<<32, 256>>>(gs, NN, NG);
    k_filli<<<32, 256>>>(ge, 0, NG);
    k_bounds<<<cdiv(NN, 256), 256>>>(batch, gs, ge);
    k_pool_gated<<<NG, 256>>>(bufB, gw2, gconst, scale, shift, gs, ge, pooled);

    // ---- MLP head ----
    k_split_mat<<<cdiv((long)NG * 1024, 256), 256>>>(pooled, ah, al, NG, NG, 1024);
    gemm_tc(ah, al, wh + wo6, wl + wo6, fc2_b, h2, nullptr, nullptr,
            NG, 128, 1024, 2, nullptr, nullptr);
    gemm32(h2, fc3_W, fc3_b, h3, NG, 16, 128, 2);
    gemm32(h3, fc4_W, fc4_b, out, NG, 1, 16, 1);
}